// round 2
// baseline (speedup 1.0000x reference)
#include <cuda_runtime.h>
#include <math.h>

// ---------------- problem constants ----------------
#define TK   4096          // tokens = B*S
#define HN   1024          // hidden
#define NHD  4             // heads
#define HDD  256           // head dim
#define BB   4             // batch
#define SS   1024          // seq len
#define FFD  4096          // ffn dim
#define NE   8             // experts
#define EHD  2048          // expert hidden
#define VS   32000         // vocab
#define NL   2             // layers

// ---------------- scratch (device globals; no allocs allowed) -------------
__device__ float g_x  [(size_t)TK*HN];          // activations
__device__ float g_t1 [(size_t)TK*HN];          // attn-out / ffn-out / moe accum
__device__ float g_big[(size_t)TK*FFD];         // qkv / ffn hidden / moe hidden
__device__ float g_sc [(size_t)BB*NHD*SS*SS];   // attention scores
__device__ int   g_cnt[NE];
__device__ int   g_tok[NE*TK];

// ---------------- embedding gather ----------------
__global__ void embed_k(const int* __restrict__ ids, const float* __restrict__ emb,
                        float* __restrict__ out) {
    int t = blockIdx.x;
    const float4* src = (const float4*)(emb + (size_t)ids[t]*HN);
    float4* dst = (float4*)(out + (size_t)t*HN);
    for (int i = threadIdx.x; i < HN/4; i += blockDim.x) dst[i] = src[i];
}

// ---------------- generic tiled GEMM ----------------
// C[M,N] = act(alpha * A@B + bias)   (or += when SCATTER)
// BT: B stored [N,K] row-major (i.e. multiply by B^T). Otherwise [K,N].
// GATHER: A row r comes from A + ridx[r]*lda. SCATTER: C row r goes to C + ridx[r]*ldc (+=).
// Batched (attention): z = blockIdx.z decomposed as (zb, zh) = (z/nh, z%nh) when nh>0.
// Dynamic M: if cptr != null, M = *cptr (read on device; graph-capture safe).
template<int ACT, bool BT, bool GATHER, bool SCATTER>
__global__ void gemm_k(const float* __restrict__ A, const float* __restrict__ Bm,
                       const float* __restrict__ bias, float* __restrict__ C,
                       int M, int N, int Kd, int lda, int ldb, int ldc,
                       long long sAb, long long sAh, long long sBb, long long sBh,
                       long long sCb, long long sCh, int nh,
                       float alpha,
                       const int* __restrict__ ridx, const int* __restrict__ cptr)
{
    if (nh > 0) {
        int z  = blockIdx.z;
        int zb = z / nh, zh = z % nh;
        A  += (long long)zb*sAb + (long long)zh*sAh;
        Bm += (long long)zb*sBb + (long long)zh*sBh;
        C  += (long long)zb*sCb + (long long)zh*sCh;
    }
    if (cptr) M = *cptr;
    int m0 = blockIdx.y*64, n0 = blockIdx.x*64;
    if (m0 >= M) return;

    __shared__ float As[16][68];
    __shared__ float Bs[16][68];
    int tid = threadIdx.x;                 // 256 threads
    int ar = tid >> 2,  ak = (tid & 3)*4;  // A/B(T) tile load coords
    int bk = tid >> 4,  bn = (tid & 15)*4; // B(N) tile load coords
    int ty = tid >> 4,  tx = tid & 15;     // compute coords: 4x4 micro tile

    float acc[4][4];
#pragma unroll
    for (int i = 0; i < 4; i++)
#pragma unroll
        for (int j = 0; j < 4; j++) acc[i][j] = 0.f;

    const float* arow = nullptr;
    {
        int gm = m0 + ar;
        if (gm < M) {
            long long r = GATHER ? (long long)ridx[gm] : (long long)gm;
            arow = A + r*(long long)lda;
        }
    }

    for (int k0 = 0; k0 < Kd; k0 += 16) {
        float4 va = make_float4(0.f,0.f,0.f,0.f);
        if (arow) va = *(const float4*)(arow + k0 + ak);
        As[ak+0][ar] = va.x; As[ak+1][ar] = va.y; As[ak+2][ar] = va.z; As[ak+3][ar] = va.w;

        if (!BT) {
            float4 vb = *(const float4*)(Bm + (long long)(k0+bk)*ldb + n0 + bn);
            *(float4*)&Bs[bk][bn] = vb;
        } else {
            float4 vb = *(const float4*)(Bm + (long long)(n0+ar)*ldb + k0 + ak);
            Bs[ak+0][ar] = vb.x; Bs[ak+1][ar] = vb.y; Bs[ak+2][ar] = vb.z; Bs[ak+3][ar] = vb.w;
        }
        __syncthreads();

#pragma unroll
        for (int k = 0; k < 16; k++) {
            float4 a4 = *(float4*)&As[k][ty*4];
            float4 b4 = *(float4*)&Bs[k][tx*4];
            acc[0][0] += a4.x*b4.x; acc[0][1] += a4.x*b4.y; acc[0][2] += a4.x*b4.z; acc[0][3] += a4.x*b4.w;
            acc[1][0] += a4.y*b4.x; acc[1][1] += a4.y*b4.y; acc[1][2] += a4.y*b4.z; acc[1][3] += a4.y*b4.w;
            acc[2][0] += a4.z*b4.x; acc[2][1] += a4.z*b4.y; acc[2][2] += a4.z*b4.z; acc[2][3] += a4.z*b4.w;
            acc[3][0] += a4.w*b4.x; acc[3][1] += a4.w*b4.y; acc[3][2] += a4.w*b4.z; acc[3][3] += a4.w*b4.w;
        }
        __syncthreads();
    }

#pragma unroll
    for (int i = 0; i < 4; i++) {
        int gm = m0 + ty*4 + i;
        if (gm >= M) break;
        float* crow;
        if (SCATTER) crow = C + (long long)ridx[gm]*ldc;
        else         crow = C + (long long)gm*ldc;
#pragma unroll
        for (int j = 0; j < 4; j++) {
            int gn = n0 + tx*4 + j;
            float v = acc[i][j]*alpha;
            if (bias) v += bias[gn];
            if (ACT == 1) v = 0.5f*v*(1.0f + erff(v*0.7071067811865475f));   // exact GELU
            else if (ACT == 2) v = v > 0.f ? v : 0.f;                        // ReLU
            if (SCATTER) crow[gn] += v;
            else         crow[gn]  = v;
        }
    }
}

// ---------------- softmax over rows of length SS ----------------
__global__ void softmax_k(float* __restrict__ p) {
    long long row = blockIdx.x;
    float* r = p + row*SS;
    int tid = threadIdx.x;
    __shared__ float red[256];

    float mx = -1e30f;
    for (int i = tid; i < SS; i += 256) mx = fmaxf(mx, r[i]);
    red[tid] = mx; __syncthreads();
    for (int s = 128; s > 0; s >>= 1) { if (tid < s) red[tid] = fmaxf(red[tid], red[tid+s]); __syncthreads(); }
    mx = red[0]; __syncthreads();

    float sum = 0.f;
    for (int i = tid; i < SS; i += 256) { float e = expf(r[i]-mx); r[i] = e; sum += e; }
    red[tid] = sum; __syncthreads();
    for (int s = 128; s > 0; s >>= 1) { if (tid < s) red[tid] += red[tid+s]; __syncthreads(); }
    float inv = 1.f/red[0];
    for (int i = tid; i < SS; i += 256) r[i] *= inv;
}

// ---------------- residual + LayerNorm ----------------
__global__ void ln_k(const float* __restrict__ resid, const float* __restrict__ delta,
                     const float* __restrict__ g, const float* __restrict__ b,
                     float* __restrict__ out) {
    long long t = blockIdx.x;
    int tid = threadIdx.x;
    __shared__ float buf[HN];
    __shared__ float red[256];

    float s = 0.f;
    for (int i = tid; i < HN; i += 256) {
        float v = resid[t*HN+i] + delta[t*HN+i];
        buf[i] = v; s += v;
    }
    red[tid] = s; __syncthreads();
    for (int st = 128; st > 0; st >>= 1) { if (tid < st) red[tid] += red[tid+st]; __syncthreads(); }
    float m = red[0]*(1.0f/HN); __syncthreads();

    float s2 = 0.f;
    for (int i = tid; i < HN; i += 256) { float d = buf[i]-m; s2 += d*d; }
    red[tid] = s2; __syncthreads();
    for (int st = 128; st > 0; st >>= 1) { if (tid < st) red[tid] += red[tid+st]; __syncthreads(); }
    float inv = rsqrtf(red[0]*(1.0f/HN) + 1e-5f);

    for (int i = tid; i < HN; i += 256)
        out[t*HN+i] = (buf[i]-m)*inv*g[i] + b[i];
}

// ---------------- gate: logits + top-2 routing ----------------
__global__ void gate_k(const float* __restrict__ x, const float* __restrict__ gw,
                       const float* __restrict__ gb, int* __restrict__ cnt,
                       int* __restrict__ toks) {
    int t = blockIdx.x;
    int tid = threadIdx.x;
    __shared__ float xs[HN];
    __shared__ float red[256];

    for (int i = tid; i < HN; i += 256) xs[i] = x[(long long)t*HN+i];
    __syncthreads();

    int e = tid & 7, g = tid >> 3;   // 8 experts x 32 partial threads
    float p = 0.f;
    for (int j = g; j < HN; j += 32) p += xs[j]*gw[j*NE+e];
    red[tid] = p; __syncthreads();

    if (tid < 8) {
        float s = 0.f;
        for (int j = 0; j < 32; j++) s += red[j*8 + tid];
        red[tid] = s + gb[tid];
    }
    __syncthreads();
    if (tid == 0) {
        float l[NE];
        for (int i = 0; i < NE; i++) l[i] = red[i];
        int i1 = 0;
        for (int i = 1; i < NE; i++) if (l[i] > l[i1]) i1 = i;   // strict >: lowest idx on tie
        int i2 = (i1 == 0) ? 1 : 0;
        for (int i = 0; i < NE; i++) if (i != i1 && l[i] > l[i2]) i2 = i;
        int p1 = atomicAdd(&cnt[i1], 1); toks[i1*TK+p1] = t;
        int p2 = atomicAdd(&cnt[i2], 1); toks[i2*TK+p2] = t;
    }
}

// ---------------- utility kernels ----------------
__global__ void zero_f(float* p, long long n) {
    long long i = (long long)blockIdx.x*blockDim.x + threadIdx.x;
    if (i < n) p[i] = 0.f;
}
__global__ void zero_i(int* p, int n) {
    int i = blockIdx.x*blockDim.x + threadIdx.x;
    if (i < n) p[i] = 0;
}
__global__ void copy_f(float* __restrict__ dst, const float* __restrict__ src, long long n) {
    long long i = (long long)blockIdx.x*blockDim.x + threadIdx.x;
    if (i < n) dst[i] = src[i];
}

// ---------------- launch ----------------
extern "C" void kernel_launch(void* const* d_in, const int* in_sizes, int n_in,
                              void* d_out, int out_size)
{
    const int*   ids   = (const int*)d_in[0];
    const float* emb   = (const float*)d_in[1];
    const float* qkvw  = (const float*)d_in[2];
    const float* qkvb  = (const float*)d_in[3];
    const float* outw  = (const float*)d_in[4];
    const float* outb  = (const float*)d_in[5];
    const float* ln1g  = (const float*)d_in[6];
    const float* ln1b  = (const float*)d_in[7];
    const float* ffw1  = (const float*)d_in[8];
    const float* ffb1  = (const float*)d_in[9];
    const float* ffw2  = (const float*)d_in[10];
    const float* ffb2  = (const float*)d_in[11];
    const float* ln2g  = (const float*)d_in[12];
    const float* ln2b  = (const float*)d_in[13];
    const float* gw    = (const float*)d_in[14];
    const float* gb    = (const float*)d_in[15];
    const float* ew1   = (const float*)d_in[16];
    const float* eb1   = (const float*)d_in[17];
    const float* ew2   = (const float*)d_in[18];
    const float* eb2   = (const float*)d_in[19];
    const float* lmw   = (const float*)d_in[20];
    const float* lmb   = (const float*)d_in[21];
    float* out = (float*)d_out;

    float *x, *t1, *big, *sc; int *cnt, *tok;
    cudaGetSymbolAddress((void**)&x,   g_x);
    cudaGetSymbolAddress((void**)&t1,  g_t1);
    cudaGetSymbolAddress((void**)&big, g_big);
    cudaGetSymbolAddress((void**)&sc,  g_sc);
    cudaGetSymbolAddress((void**)&cnt, g_cnt);
    cudaGetSymbolAddress((void**)&tok, g_tok);

    const long long Z0 = 0;

    // embedding
    embed_k<<<TK, 256>>>(ids, emb, x);

    for (int l = 0; l < NL; l++) {
        const float* Wqkv = qkvw + (long long)l*3*HN*HN;
        const float* Bqkv = qkvb + (long long)l*3*HN;

        // qkv = x @ Wqkv^T + b  -> big [T, 3H]
        gemm_k<0,true,false,false><<<dim3(48,64,1),256>>>(
            x, Wqkv, Bqkv, big, TK, 3*HN, HN, HN, HN, 3*HN,
            Z0,Z0,Z0,Z0,Z0,Z0, 0, 1.f, nullptr, nullptr);

        // scores = q @ k^T / 16  (batched over B*NH)
        gemm_k<0,true,false,false><<<dim3(16,16,BB*NHD),256>>>(
            big, big + HN, nullptr, sc, SS, SS, HDD, 3*HN, 3*HN, SS,
            (long long)SS*3*HN, (long long)HDD,
            (long long)SS*3*HN, (long long)HDD,
            (long long)NHD*SS*SS, (long long)SS*SS, NHD,
            0.0625f, nullptr, nullptr);

        softmax_k<<<BB*NHD*SS, 256>>>(sc);

        // ao = attn @ v  -> t1 [T, H] (head-interleaved layout)
        gemm_k<0,false,false,false><<<dim3(4,16,BB*NHD),256>>>(
            sc, big + 2*HN, nullptr, t1, SS, HDD, SS, SS, 3*HN, HN,
            (long long)NHD*SS*SS, (long long)SS*SS,
            (long long)SS*3*HN, (long long)HDD,
            (long long)SS*HN, (long long)HDD, NHD,
            1.f, nullptr, nullptr);

        // proj = ao @ Wout^T + b -> big [T, H]
        gemm_k<0,true,false,false><<<dim3(16,64,1),256>>>(
            t1, outw + (long long)l*HN*HN, outb + (long long)l*HN, big,
            TK, HN, HN, HN, HN, HN, Z0,Z0,Z0,Z0,Z0,Z0, 0, 1.f, nullptr, nullptr);

        // x = LN(x + proj)
        ln_k<<<TK,256>>>(x, big, ln1g + (long long)l*HN, ln1b + (long long)l*HN, x);

        // ffn
        gemm_k<1,false,false,false><<<dim3(64,64,1),256>>>(
            x, ffw1 + (long long)l*HN*FFD, ffb1 + (long long)l*FFD, big,
            TK, FFD, HN, HN, FFD, FFD, Z0,Z0,Z0,Z0,Z0,Z0, 0, 1.f, nullptr, nullptr);
        gemm_k<0,false,false,false><<<dim3(16,64,1),256>>>(
            big, ffw2 + (long long)l*FFD*HN, ffb2 + (long long)l*HN, t1,
            TK, HN, FFD, FFD, HN, HN, Z0,Z0,Z0,Z0,Z0,Z0, 0, 1.f, nullptr, nullptr);

        // x = LN(x + ff)
        ln_k<<<TK,256>>>(x, t1, ln2g + (long long)l*HN, ln2b + (long long)l*HN, x);

        // MoE routing
        zero_i<<<1, NE>>>(cnt, NE);
        gate_k<<<TK,256>>>(x, gw + (long long)l*HN*NE, gb + (long long)l*NE, cnt, tok);
        zero_f<<<(TK*HN)/256, 256>>>(t1, (long long)TK*HN);

        for (int e = 0; e < NE; e++) {
            const float* W1 = ew1 + ((long long)l*NE+e)*HN*EHD;
            const float* B1 = eb1 + ((long long)l*NE+e)*EHD;
            const float* W2 = ew2 + ((long long)l*NE+e)*EHD*HN;
            const float* B2 = eb2 + ((long long)l*NE+e)*HN;
            // hidden = relu(gathered_x @ W1 + b1) -> big [cnt_e, EH]
            gemm_k<2,false,true,false><<<dim3(EHD/64,TK/64,1),256>>>(
                x, W1, B1, big, TK, EHD, HN, HN, EHD, EHD,
                Z0,Z0,Z0,Z0,Z0,Z0, 0, 1.f, tok + e*TK, cnt + e);
            // t1[token] += hidden @ W2 + b2
            gemm_k<0,false,false,true><<<dim3(HN/64,TK/64,1),256>>>(
                big, W2, B2, t1, TK, HN, EHD, EHD, HN, HN,
                Z0,Z0,Z0,Z0,Z0,Z0, 0, 1.f, tok + e*TK, cnt + e);
        }
        copy_f<<<(TK*HN)/256, 256>>>(x, t1, (long long)TK*HN);
    }

    // lm head: out = x @ lmw + lmb   [T, V]
    gemm_k<0,false,false,false><<<dim3(VS/64,TK/64,1),256>>>(
        x, lmw, lmb, out, TK, VS, HN, HN, VS, VS,
        Z0,Z0,Z0,Z0,Z0,Z0, 0, 1.f, nullptr, nullptr);
}

// round 6
// speedup vs baseline: 2.5467x; 2.5467x over previous
#include <cuda_runtime.h>
#include <cuda_bf16.h>
#include <math.h>

// ---------------- problem constants ----------------
#define TK   4096
#define HN   1024
#define NHD  4
#define HDD  256
#define BB   4
#define SS   1024
#define FFD  4096
#define NE   8
#define EHD  2048
#define VS   32000
#define NL   2

// ---------------- split-weight offsets (elements) ----------------
#define OFF_QKV 0LL
#define OFF_OUT  (OFF_QKV + (long long)NL*3*HN*HN)
#define OFF_FF1  (OFF_OUT + (long long)NL*HN*HN)
#define OFF_FF2  (OFF_FF1 + (long long)NL*HN*FFD)
#define OFF_E1   (OFF_FF2 + (long long)NL*FFD*HN)
#define OFF_E2   (OFF_E1  + (long long)NL*NE*HN*EHD)
#define OFF_LM   (OFF_E2  + (long long)NL*NE*EHD*HN)
#define TOTW     (OFF_LM  + (long long)HN*VS)

// ---------------- scratch ----------------
__device__ float g_x  [(size_t)TK*HN];
__device__ float g_t1 [(size_t)TK*HN];
__device__ float g_big[(size_t)TK*FFD];
__device__ float g_sc [(size_t)BB*NHD*SS*SS];
__device__ float g_eh [(size_t)NE*TK*EHD];      // per-expert compact hidden (race fix)
__device__ int   g_cnt[NE];
__device__ int   g_tok[NE*TK];
__device__ __nv_bfloat16 g_wh[TOTW];
__device__ __nv_bfloat16 g_wl[TOTW];
__device__ __nv_bfloat16 g_vth[(size_t)BB*NHD*HDD*SS];
__device__ __nv_bfloat16 g_vtl[(size_t)BB*NHD*HDD*SS];

// ================= helpers =================
__device__ __forceinline__ unsigned smem_u32(const void* p){
    unsigned a;
    asm("{ .reg .u64 t; cvta.to.shared.u64 t, %1; cvt.u32.u64 %0, t; }" : "=r"(a) : "l"(p));
    return a;
}
__device__ __forceinline__ void split4(float4 v, uint2& h, uint2& l) {
    __nv_bfloat16 h0 = __float2bfloat16(v.x), h1 = __float2bfloat16(v.y);
    __nv_bfloat16 h2 = __float2bfloat16(v.z), h3 = __float2bfloat16(v.w);
    __nv_bfloat16 l0 = __float2bfloat16(v.x - __bfloat162float(h0));
    __nv_bfloat16 l1 = __float2bfloat16(v.y - __bfloat162float(h1));
    __nv_bfloat16 l2 = __float2bfloat16(v.z - __bfloat162float(h2));
    __nv_bfloat16 l3 = __float2bfloat16(v.w - __bfloat162float(h3));
    h.x = (unsigned)__bfloat16_as_ushort(h0) | ((unsigned)__bfloat16_as_ushort(h1) << 16);
    h.y = (unsigned)__bfloat16_as_ushort(h2) | ((unsigned)__bfloat16_as_ushort(h3) << 16);
    l.x = (unsigned)__bfloat16_as_ushort(l0) | ((unsigned)__bfloat16_as_ushort(l1) << 16);
    l.y = (unsigned)__bfloat16_as_ushort(l2) | ((unsigned)__bfloat16_as_ushort(l3) << 16);
}

#define LDSM_X4(r0, r1, r2, r3, a) \
    asm volatile("ldmatrix.sync.aligned.m8n8.x4.shared.b16 {%0,%1,%2,%3}, [%4];" \
                 : "=r"(r0), "=r"(r1), "=r"(r2), "=r"(r3) : "r"(a))
#define LDSM_X2(r0, r1, a) \
    asm volatile("ldmatrix.sync.aligned.m8n8.x2.shared.b16 {%0,%1}, [%2];" \
                 : "=r"(r0), "=r"(r1) : "r"(a))
#define MMA16816(d, a, b) \
    asm volatile("mma.sync.aligned.m16n8k16.row.col.f32.bf16.bf16.f32 " \
                 "{%0,%1,%2,%3}, {%4,%5,%6,%7}, {%8,%9}, {%0,%1,%2,%3};" \
                 : "+f"((d)[0]), "+f"((d)[1]), "+f"((d)[2]), "+f"((d)[3]) \
                 : "r"((a)[0]), "r"((a)[1]), "r"((a)[2]), "r"((a)[3]), \
                   "r"((b)[0]), "r"((b)[1]))

// ================= bf16x3 MMA GEMM =================
// C[M,N] = act(alpha*(A@B^T) + bias); B^T given as [N,K] (fp32 or pre-split bf16 hi/lo)
#define BM 128
#define BN 128
#define KC 32
// smem: 80B row stride (20 banks) -> ldmatrix 8-row fetch is bank-conflict-free
#define ROWB 80
#define SA_H 0
#define SA_L 10240
#define SB_H 20480
#define SB_L 30720

template<int ACT, int BPRE, bool GATHER, bool SCATTER>
__global__ void __launch_bounds__(256, 1)
tc_k(const float* __restrict__ A, const float* __restrict__ Bf,
     const __nv_bfloat16* __restrict__ Bh, const __nv_bfloat16* __restrict__ Bl,
     const float* __restrict__ bias, float* __restrict__ C,
     int M, int N, int Kd, int lda, int ldb, int ldc,
     long long sAb, long long sAh, long long sBb, long long sBh,
     long long sCb, long long sCh, long long sBias, int nh, float alpha,
     const int* __restrict__ ridx, const int* __restrict__ cptr)
{
    if (nh > 0) {
        int z = blockIdx.z, zb = z / nh, zh = z % nh;
        A += zb*sAb + zh*sAh;
        if (BPRE) { Bh += zb*sBb + zh*sBh; Bl += zb*sBb + zh*sBh; }
        else      { Bf += zb*sBb + zh*sBh; }
        C += zb*sCb + zh*sCh;
        if (bias) bias += zb*sBias;
        if (GATHER || SCATTER) ridx += (long long)zb*TK;
        if (cptr) cptr += zb;
    }
    if (cptr) M = *cptr;
    int m0 = blockIdx.y*BM, n0 = blockIdx.x*BN;
    if (m0 >= M) return;

    __shared__ __align__(16) char sm[40960];
    unsigned sb = smem_u32(sm);
    int tid = threadIdx.x, lane = tid & 31, wid = tid >> 5;
    int wm = wid & 1, wn = wid >> 1;          // 2 x 4 warp grid; warp tile 64x32

    float acc[4][4][4];
#pragma unroll
    for (int i = 0; i < 4; i++)
#pragma unroll
        for (int j = 0; j < 4; j++)
#pragma unroll
            for (int e = 0; e < 4; e++) acc[i][j][e] = 0.f;

    // per-thread load coords
    int a_c4 = tid & 7;            // A/Bf: 8 float4 per 32-float row
    int a_rb = tid >> 3;           // + j*32
    int b_c8 = tid & 3;            // Bh/Bl: 4 uint4 per 32-bf16 row
    int b_rb = tid >> 2;           // + j*64

    float4 pa[4];
    float4 pbf[4];
    uint4  pbh[2], pbl[2];

    int NC = Kd / KC;

    // ---- load chunk 0 ----
    {
        int k0 = 0;
#pragma unroll
        for (int j = 0; j < 4; j++) {
            int gm = m0 + j*32 + a_rb;
            pa[j] = make_float4(0.f,0.f,0.f,0.f);
            if (gm < M) {
                long long row = GATHER ? (long long)ridx[gm] : (long long)gm;
                pa[j] = *(const float4*)(A + row*lda + k0 + a_c4*4);
            }
        }
        if (BPRE) {
#pragma unroll
            for (int j = 0; j < 2; j++) {
                long long bo = (long long)(n0 + j*64 + b_rb)*ldb + k0 + b_c8*8;
                pbh[j] = *(const uint4*)(Bh + bo);
                pbl[j] = *(const uint4*)(Bl + bo);
            }
        } else {
#pragma unroll
            for (int j = 0; j < 4; j++)
                pbf[j] = *(const float4*)(Bf + (long long)(n0 + j*32 + a_rb)*ldb + k0 + a_c4*4);
        }
    }
    // commit chunk 0 to smem
#pragma unroll
    for (int j = 0; j < 4; j++) {
        uint2 h, l; split4(pa[j], h, l);
        unsigned off = (unsigned)(j*32 + a_rb)*ROWB + a_c4*8;
        *(uint2*)(sm + SA_H + off) = h;
        *(uint2*)(sm + SA_L + off) = l;
    }
    if (BPRE) {
#pragma unroll
        for (int j = 0; j < 2; j++) {
            unsigned off = (unsigned)(j*64 + b_rb)*ROWB + b_c8*16;
            *(uint4*)(sm + SB_H + off) = pbh[j];
            *(uint4*)(sm + SB_L + off) = pbl[j];
        }
    } else {
#pragma unroll
        for (int j = 0; j < 4; j++) {
            uint2 h, l; split4(pbf[j], h, l);
            unsigned off = (unsigned)(j*32 + a_rb)*ROWB + a_c4*8;
            *(uint2*)(sm + SB_H + off) = h;
            *(uint2*)(sm + SB_L + off) = l;
        }
    }
    __syncthreads();

    for (int i = 0; i < NC; i++) {
        // ---- prefetch chunk i+1 into registers ----
        if (i + 1 < NC) {
            int k0 = (i+1)*KC;
#pragma unroll
            for (int j = 0; j < 4; j++) {
                int gm = m0 + j*32 + a_rb;
                pa[j] = make_float4(0.f,0.f,0.f,0.f);
                if (gm < M) {
                    long long row = GATHER ? (long long)ridx[gm] : (long long)gm;
                    pa[j] = *(const float4*)(A + row*lda + k0 + a_c4*4);
                }
            }
            if (BPRE) {
#pragma unroll
                for (int j = 0; j < 2; j++) {
                    long long bo = (long long)(n0 + j*64 + b_rb)*ldb + k0 + b_c8*8;
                    pbh[j] = *(const uint4*)(Bh + bo);
                    pbl[j] = *(const uint4*)(Bl + bo);
                }
            } else {
#pragma unroll
                for (int j = 0; j < 4; j++)
                    pbf[j] = *(const float4*)(Bf + (long long)(n0 + j*32 + a_rb)*ldb + k0 + a_c4*4);
            }
        }

        // ---- MMA on chunk i (from smem) ----
        unsigned abase = sb + (unsigned)(wm*64)*ROWB;
        unsigned bbase = sb + SB_H + (unsigned)(wn*32)*ROWB;
        unsigned aoff = (unsigned)(lane & 15)*ROWB + (unsigned)(lane >> 4)*16;
        unsigned boff = (unsigned)(lane & 7)*ROWB + (unsigned)((lane >> 3) & 1)*16;
#pragma unroll
        for (int ks = 0; ks < 2; ks++) {
            unsigned ah[4][4], al[4][4], bh[4][2], bl[4][2];
#pragma unroll
            for (int mt = 0; mt < 4; mt++) {
                unsigned ad = abase + (unsigned)(mt*16)*ROWB + aoff + ks*32;
                LDSM_X4(ah[mt][0], ah[mt][1], ah[mt][2], ah[mt][3], ad + SA_H);
                LDSM_X4(al[mt][0], al[mt][1], al[mt][2], al[mt][3], ad + SA_L);
            }
#pragma unroll
            for (int nt = 0; nt < 4; nt++) {
                unsigned bd = bbase + (unsigned)(nt*8)*ROWB + boff + ks*32;
                LDSM_X2(bh[nt][0], bh[nt][1], bd);
                LDSM_X2(bl[nt][0], bl[nt][1], bd + (SB_L - SB_H));
            }
#pragma unroll
            for (int mt = 0; mt < 4; mt++)
#pragma unroll
                for (int nt = 0; nt < 4; nt++) {
                    MMA16816(acc[mt][nt], ah[mt], bh[nt]);
                    MMA16816(acc[mt][nt], ah[mt], bl[nt]);
                    MMA16816(acc[mt][nt], al[mt], bh[nt]);
                }
        }
        __syncthreads();

        // ---- commit prefetched chunk to smem ----
        if (i + 1 < NC) {
#pragma unroll
            for (int j = 0; j < 4; j++) {
                uint2 h, l; split4(pa[j], h, l);
                unsigned off = (unsigned)(j*32 + a_rb)*ROWB + a_c4*8;
                *(uint2*)(sm + SA_H + off) = h;
                *(uint2*)(sm + SA_L + off) = l;
            }
            if (BPRE) {
#pragma unroll
                for (int j = 0; j < 2; j++) {
                    unsigned off = (unsigned)(j*64 + b_rb)*ROWB + b_c8*16;
                    *(uint4*)(sm + SB_H + off) = pbh[j];
                    *(uint4*)(sm + SB_L + off) = pbl[j];
                }
            } else {
#pragma unroll
                for (int j = 0; j < 4; j++) {
                    uint2 h, l; split4(pbf[j], h, l);
                    unsigned off = (unsigned)(j*32 + a_rb)*ROWB + a_c4*8;
                    *(uint2*)(sm + SB_H + off) = h;
                    *(uint2*)(sm + SB_L + off) = l;
                }
            }
            __syncthreads();
        }
    }

    // ---- epilogue: straight from registers ----
#pragma unroll
    for (int mt = 0; mt < 4; mt++) {
#pragma unroll
        for (int half = 0; half < 2; half++) {
            int gm = m0 + wm*64 + mt*16 + (lane >> 2) + half*8;
            if (gm >= M) continue;
            float* crow;
            if (SCATTER) crow = C + (long long)ridx[gm]*ldc;
            else         crow = C + (long long)gm*ldc;
#pragma unroll
            for (int nt = 0; nt < 4; nt++) {
                int gn = n0 + wn*32 + nt*8 + (lane & 3)*2;
                float v0 = acc[mt][nt][half*2 + 0] * alpha;
                float v1 = acc[mt][nt][half*2 + 1] * alpha;
                if (bias) { v0 += bias[gn]; v1 += bias[gn+1]; }
                if (ACT == 1) {
                    v0 = 0.5f*v0*(1.0f + erff(v0*0.7071067811865475f));
                    v1 = 0.5f*v1*(1.0f + erff(v1*0.7071067811865475f));
                } else if (ACT == 2) {
                    v0 = v0 > 0.f ? v0 : 0.f;
                    v1 = v1 > 0.f ? v1 : 0.f;
                }
                if (SCATTER) {
                    // top-2 routing: two experts may own the same token in one
                    // batched launch -> must be atomic
                    atomicAdd(crow + gn,     v0);
                    atomicAdd(crow + gn + 1, v1);
                } else {
                    *(float2*)(crow + gn) = make_float2(v0, v1);
                }
            }
        }
    }
}

// ================= weight prep =================
__global__ void split_k(const float* __restrict__ W, __nv_bfloat16* __restrict__ hi,
                        __nv_bfloat16* __restrict__ lo, long long n) {
    long long i = (long long)blockIdx.x*256 + threadIdx.x;
    if (i >= n) return;
    float v = W[i];
    __nv_bfloat16 h = __float2bfloat16(v);
    hi[i] = h;
    lo[i] = __float2bfloat16(v - __bfloat162float(h));
}
// out[N,K] = split(W[K,N])  (W row stride ldw), batched via z=(zb,zh)
__global__ void transsplit_k(const float* __restrict__ W, int ldw,
                             __nv_bfloat16* __restrict__ hi, __nv_bfloat16* __restrict__ lo,
                             int Kd, int Nd, long long sWb, long long sWh,
                             long long sOb, long long sOh, int nhz) {
    int z = blockIdx.z, zb = z / nhz, zh = z % nhz;
    W += zb*sWb + zh*sWh; hi += zb*sOb + zh*sOh; lo += zb*sOb + zh*sOh;
    __shared__ float ts[32][33];
    int n0 = blockIdx.x*32, k0 = blockIdx.y*32;
    int tx = threadIdx.x & 31, ty = threadIdx.x >> 5;
    for (int r = ty; r < 32; r += 8)
        ts[r][tx] = W[(long long)(k0 + r)*ldw + n0 + tx];
    __syncthreads();
    for (int r = ty; r < 32; r += 8) {
        float v = ts[tx][r];
        __nv_bfloat16 h = __float2bfloat16(v);
        long long o = (long long)(n0 + r)*Kd + k0 + tx;
        hi[o] = h;
        lo[o] = __float2bfloat16(v - __bfloat162float(h));
    }
}

// ================= misc kernels =================
__global__ void embed_k(const int* __restrict__ ids, const float* __restrict__ emb,
                        float* __restrict__ out) {
    int t = blockIdx.x;
    const float4* src = (const float4*)(emb + (size_t)ids[t]*HN);
    float4* dst = (float4*)(out + (size_t)t*HN);
    for (int i = threadIdx.x; i < HN/4; i += blockDim.x) dst[i] = src[i];
}
__global__ void softmax_k(float* __restrict__ p) {
    long long row = blockIdx.x;
    float* r = p + row*SS;
    int tid = threadIdx.x;
    __shared__ float red[256];
    float mx = -1e30f;
    for (int i = tid; i < SS; i += 256) mx = fmaxf(mx, r[i]);
    red[tid] = mx; __syncthreads();
    for (int s = 128; s > 0; s >>= 1) { if (tid < s) red[tid] = fmaxf(red[tid], red[tid+s]); __syncthreads(); }
    mx = red[0]; __syncthreads();
    float sum = 0.f;
    for (int i = tid; i < SS; i += 256) { float e = expf(r[i]-mx); r[i] = e; sum += e; }
    red[tid] = sum; __syncthreads();
    for (int s = 128; s > 0; s >>= 1) { if (tid < s) red[tid] += red[tid+s]; __syncthreads(); }
    float inv = 1.f/red[0];
    for (int i = tid; i < SS; i += 256) r[i] *= inv;
}
__global__ void ln_k(const float* __restrict__ resid, const float* __restrict__ delta,
                     const float* __restrict__ g, const float* __restrict__ b,
                     float* __restrict__ out) {
    long long t = blockIdx.x;
    int tid = threadIdx.x;
    __shared__ float buf[HN];
    __shared__ float red[256];
    float s = 0.f;
    for (int i = tid; i < HN; i += 256) { float v = resid[t*HN+i] + delta[t*HN+i]; buf[i] = v; s += v; }
    red[tid] = s; __syncthreads();
    for (int st = 128; st > 0; st >>= 1) { if (tid < st) red[tid] += red[tid+st]; __syncthreads(); }
    float m = red[0]*(1.0f/HN); __syncthreads();
    float s2 = 0.f;
    for (int i = tid; i < HN; i += 256) { float d = buf[i]-m; s2 += d*d; }
    red[tid] = s2; __syncthreads();
    for (int st = 128; st > 0; st >>= 1) { if (tid < st) red[tid] += red[tid+st]; __syncthreads(); }
    float inv = rsqrtf(red[0]*(1.0f/HN) + 1e-5f);
    for (int i = tid; i < HN; i += 256) out[t*HN+i] = (buf[i]-m)*inv*g[i] + b[i];
}
__global__ void gate_k(const float* __restrict__ x, const float* __restrict__ gw,
                       const float* __restrict__ gb, int* __restrict__ cnt,
                       int* __restrict__ toks) {
    int t = blockIdx.x;
    int tid = threadIdx.x;
    __shared__ float xs[HN];
    __shared__ float red[256];
    for (int i = tid; i < HN; i += 256) xs[i] = x[(long long)t*HN+i];
    __syncthreads();
    int e = tid & 7, g = tid >> 3;
    float p = 0.f;
    for (int j = g; j < HN; j += 32) p += xs[j]*gw[j*NE+e];
    red[tid] = p; __syncthreads();
    if (tid < 8) {
        float s = 0.f;
        for (int j = 0; j < 32; j++) s += red[j*8 + tid];
        red[tid] = s + gb[tid];
    }
    __syncthreads();
    if (tid == 0) {
        float l[NE];
        for (int i = 0; i < NE; i++) l[i] = red[i];
        int i1 = 0;
        for (int i = 1; i < NE; i++) if (l[i] > l[i1]) i1 = i;
        int i2 = (i1 == 0) ? 1 : 0;
        for (int i = 0; i < NE; i++) if (i != i1 && l[i] > l[i2]) i2 = i;
        int p1 = atomicAdd(&cnt[i1], 1); toks[i1*TK+p1] = t;
        int p2 = atomicAdd(&cnt[i2], 1); toks[i2*TK+p2] = t;
    }
}
__global__ void zero_f(float* p, long long n) {
    long long i = (long long)blockIdx.x*blockDim.x + threadIdx.x;
    if (i < n) p[i] = 0.f;
}
__global__ void zero_i(int* p, int n) {
    int i = blockIdx.x*blockDim.x + threadIdx.x;
    if (i < n) p[i] = 0;
}
__global__ void copy_f(float* __restrict__ dst, const float* __restrict__ src, long long n) {
    long long i = (long long)blockIdx.x*blockDim.x + threadIdx.x;
    if (i < n) dst[i] = src[i];
}

// ================= launch =================
extern "C" void kernel_launch(void* const* d_in, const int* in_sizes, int n_in,
                              void* d_out, int out_size)
{
    const int*   ids   = (const int*)d_in[0];
    const float* emb   = (const float*)d_in[1];
    const float* qkvw  = (const float*)d_in[2];
    const float* qkvb  = (const float*)d_in[3];
    const float* outw  = (const float*)d_in[4];
    const float* outb  = (const float*)d_in[5];
    const float* ln1g  = (const float*)d_in[6];
    const float* ln1b  = (const float*)d_in[7];
    const float* ffw1  = (const float*)d_in[8];
    const float* ffb1  = (const float*)d_in[9];
    const float* ffw2  = (const float*)d_in[10];
    const float* ffb2  = (const float*)d_in[11];
    const float* ln2g  = (const float*)d_in[12];
    const float* ln2b  = (const float*)d_in[13];
    const float* gw    = (const float*)d_in[14];
    const float* gb    = (const float*)d_in[15];
    const float* ew1   = (const float*)d_in[16];
    const float* eb1   = (const float*)d_in[17];
    const float* ew2   = (const float*)d_in[18];
    const float* eb2   = (const float*)d_in[19];
    const float* lmw   = (const float*)d_in[20];
    const float* lmb   = (const float*)d_in[21];
    float* out = (float*)d_out;

    float *x, *t1, *big, *sc, *eh; int *cnt, *tok;
    __nv_bfloat16 *wh, *wl, *vth, *vtl;
    cudaGetSymbolAddress((void**)&x,   g_x);
    cudaGetSymbolAddress((void**)&t1,  g_t1);
    cudaGetSymbolAddress((void**)&big, g_big);
    cudaGetSymbolAddress((void**)&sc,  g_sc);
    cudaGetSymbolAddress((void**)&eh,  g_eh);
    cudaGetSymbolAddress((void**)&cnt, g_cnt);
    cudaGetSymbolAddress((void**)&tok, g_tok);
    cudaGetSymbolAddress((void**)&wh,  g_wh);
    cudaGetSymbolAddress((void**)&wl,  g_wl);
    cudaGetSymbolAddress((void**)&vth, g_vth);
    cudaGetSymbolAddress((void**)&vtl, g_vtl);

    const long long Z0 = 0;

    // ---- weight pre-split ----
    split_k<<<(unsigned)(((long long)NL*3*HN*HN + 255)/256), 256>>>(qkvw, wh + OFF_QKV, wl + OFF_QKV, (long long)NL*3*HN*HN);
    split_k<<<(unsigned)(((long long)NL*HN*HN + 255)/256), 256>>>(outw, wh + OFF_OUT, wl + OFF_OUT, (long long)NL*HN*HN);
    transsplit_k<<<dim3(FFD/32, HN/32, NL), 256>>>(ffw1, FFD, wh + OFF_FF1, wl + OFF_FF1,
        HN, FFD, (long long)HN*FFD, Z0, (long long)HN*FFD, Z0, 1);
    transsplit_k<<<dim3(HN/32, FFD/32, NL), 256>>>(ffw2, HN, wh + OFF_FF2, wl + OFF_FF2,
        FFD, HN, (long long)FFD*HN, Z0, (long long)FFD*HN, Z0, 1);
    transsplit_k<<<dim3(EHD/32, HN/32, NL*NE), 256>>>(ew1, EHD, wh + OFF_E1, wl + OFF_E1,
        HN, EHD, (long long)HN*EHD, Z0, (long long)HN*EHD, Z0, 1);
    transsplit_k<<<dim3(HN/32, EHD/32, NL*NE), 256>>>(ew2, HN, wh + OFF_E2, wl + OFF_E2,
        EHD, HN, (long long)EHD*HN, Z0, (long long)EHD*HN, Z0, 1);
    transsplit_k<<<dim3(VS/32, HN/32, 1), 256>>>(lmw, VS, wh + OFF_LM, wl + OFF_LM,
        HN, VS, Z0, Z0, Z0, Z0, 1);

    embed_k<<<TK, 256>>>(ids, emb, x);

    for (int l = 0; l < NL; l++) {
        // qkv = x @ Wqkv^T + b  -> big [T,3H]
        tc_k<0,1,false,false><<<dim3(3*HN/BN, TK/BM, 1), 256>>>(
            x, nullptr, wh + OFF_QKV + (long long)l*3*HN*HN, wl + OFF_QKV + (long long)l*3*HN*HN,
            qkvb + (long long)l*3*HN, big, TK, 3*HN, HN, HN, HN, 3*HN,
            Z0,Z0,Z0,Z0,Z0,Z0,Z0, 0, 1.f, nullptr, nullptr);

        // V^T split per (b,h): Vt [b,h][HD][S]
        transsplit_k<<<dim3(HDD/32, SS/32, BB*NHD), 256>>>(
            big + 2*HN, 3*HN, vth, vtl, SS, HDD,
            (long long)SS*3*HN, (long long)HDD,
            (long long)NHD*HDD*SS, (long long)HDD*SS, NHD);

        // scores = Q @ K^T / 16
        tc_k<0,0,false,false><<<dim3(SS/BN, SS/BM, BB*NHD), 256>>>(
            big, big + HN, nullptr, nullptr, nullptr, sc,
            SS, SS, HDD, 3*HN, 3*HN, SS,
            (long long)SS*3*HN, (long long)HDD,
            (long long)SS*3*HN, (long long)HDD,
            (long long)NHD*SS*SS, (long long)SS*SS, Z0, NHD,
            0.0625f, nullptr, nullptr);

        softmax_k<<<BB*NHD*SS, 256>>>(sc);

        // ao = attn @ V  -> t1 [T,H]
        tc_k<0,1,false,false><<<dim3(HDD/BN, SS/BM, BB*NHD), 256>>>(
            sc, nullptr, vth, vtl, nullptr, t1,
            SS, HDD, SS, SS, SS, HN,
            (long long)NHD*SS*SS, (long long)SS*SS,
            (long long)NHD*HDD*SS, (long long)HDD*SS,
            (long long)SS*HN, (long long)HDD, Z0, NHD,
            1.f, nullptr, nullptr);

        // proj = ao @ Wout^T + b -> big
        tc_k<0,1,false,false><<<dim3(HN/BN, TK/BM, 1), 256>>>(
            t1, nullptr, wh + OFF_OUT + (long long)l*HN*HN, wl + OFF_OUT + (long long)l*HN*HN,
            outb + (long long)l*HN, big, TK, HN, HN, HN, HN, HN,
            Z0,Z0,Z0,Z0,Z0,Z0,Z0, 0, 1.f, nullptr, nullptr);

        ln_k<<<TK,256>>>(x, big, ln1g + (long long)l*HN, ln1b + (long long)l*HN, x);

        // ffn
        tc_k<1,1,false,false><<<dim3(FFD/BN, TK/BM, 1), 256>>>(
            x, nullptr, wh + OFF_FF1 + (long long)l*HN*FFD, wl + OFF_FF1 + (long long)l*HN*FFD,
            ffb1 + (long long)l*FFD, big, TK, FFD, HN, HN, HN, FFD,
            Z0,Z0,Z0,Z0,Z0,Z0,Z0, 0, 1.f, nullptr, nullptr);
        tc_k<0,1,false,false><<<dim3(HN/BN, TK/BM, 1), 256>>>(
            big, nullptr, wh + OFF_FF2 + (long long)l*FFD*HN, wl + OFF_FF2 + (long long)l*FFD*HN,
            ffb2 + (long long)l*HN, t1, TK, HN, FFD, FFD, FFD, HN,
            Z0,Z0,Z0,Z0,Z0,Z0,Z0, 0, 1.f, nullptr, nullptr);

        ln_k<<<TK,256>>>(x, t1, ln2g + (long long)l*HN, ln2b + (long long)l*HN, x);

        // MoE
        zero_i<<<1, NE>>>(cnt, NE);
        gate_k<<<TK,256>>>(x, gw + (long long)l*HN*NE, gb + (long long)l*NE, cnt, tok);
        zero_f<<<(TK*HN)/256, 256>>>(t1, (long long)TK*HN);

        // up: eh[e][compact, EHD] = relu(x[gather] @ W1_e + b1_e), batched over experts
        tc_k<2,1,true,false><<<dim3(EHD/BN, TK/BM, NE), 256>>>(
            x, nullptr, wh + OFF_E1 + (long long)l*NE*HN*EHD, wl + OFF_E1 + (long long)l*NE*HN*EHD,
            eb1 + (long long)l*NE*EHD, eh, TK, EHD, HN, HN, HN, EHD,
            Z0, Z0, (long long)EHD*HN, Z0, (long long)TK*EHD, Z0, (long long)EHD, 1,
            1.f, tok, cnt);
        // down: t1[token] += eh[e] @ W2_e + b2_e  (atomic scatter)
        tc_k<0,1,false,true><<<dim3(HN/BN, TK/BM, NE), 256>>>(
            eh, nullptr, wh + OFF_E2 + (long long)l*NE*EHD*HN, wl + OFF_E2 + (long long)l*NE*EHD*HN,
            eb2 + (long long)l*NE*HN, t1, TK, HN, EHD, EHD, EHD, HN,
            (long long)TK*EHD, Z0, (long long)HN*EHD, Z0, Z0, Z0, (long long)HN, 1,
            1.f, tok, cnt);

        copy_f<<<(TK*HN)/256, 256>>>(x, t1, (long long)TK*HN);
    }

    // lm head
    tc_k<0,1,false,false><<<dim3(VS/BN, TK/BM, 1), 256>>>(
        x, nullptr, wh + OFF_LM, wl + OFF_LM, lmb, out,
        TK, VS, HN, HN, HN, VS,
        Z0,Z0,Z0,Z0,Z0,Z0,Z0, 0, 1.f, nullptr, nullptr);
}

// round 7
// speedup vs baseline: 2.8066x; 1.1021x over previous
#include <cuda_runtime.h>
#include <cuda_bf16.h>
#include <math.h>

// ---------------- problem constants ----------------
#define TK   4096
#define HN   1024
#define NHD  4
#define HDD  256
#define BB   4
#define SS   1024
#define FFD  4096
#define NE   8
#define EHD  2048
#define VS   32000
#define NL   2

// ---------------- split-weight offsets (elements) ----------------
#define OFF_QKV 0LL
#define OFF_OUT  (OFF_QKV + (long long)NL*3*HN*HN)
#define OFF_FF1  (OFF_OUT + (long long)NL*HN*HN)
#define OFF_FF2  (OFF_FF1 + (long long)NL*HN*FFD)
#define OFF_E1   (OFF_FF2 + (long long)NL*FFD*HN)
#define OFF_E2   (OFF_E1  + (long long)NL*NE*HN*EHD)
#define OFF_LM   (OFF_E2  + (long long)NL*NE*EHD*HN)
#define TOTW     (OFF_LM  + (long long)HN*VS)

// ---------------- scratch ----------------
__device__ float g_x  [(size_t)TK*HN];
__device__ float g_t1 [(size_t)TK*HN];
__device__ float g_big[(size_t)TK*FFD];
__device__ float g_sc [(size_t)BB*NHD*SS*SS];
__device__ int   g_cnt[NE];
__device__ int   g_tok[NE*TK];
__device__ __nv_bfloat16 g_wh[TOTW];
__device__ __nv_bfloat16 g_wl[TOTW];
__device__ __nv_bfloat16 g_vth[(size_t)BB*NHD*HDD*SS];
__device__ __nv_bfloat16 g_vtl[(size_t)BB*NHD*HDD*SS];
// split activations
__device__ __nv_bfloat16 g_xh [(size_t)TK*HN];
__device__ __nv_bfloat16 g_xl [(size_t)TK*HN];
__device__ __nv_bfloat16 g_bh [(size_t)TK*FFD];
__device__ __nv_bfloat16 g_bl [(size_t)TK*FFD];
__device__ __nv_bfloat16 g_ph [(size_t)BB*NHD*SS*SS];
__device__ __nv_bfloat16 g_pl [(size_t)BB*NHD*SS*SS];
__device__ __nv_bfloat16 g_ehh[(size_t)NE*TK*EHD];
__device__ __nv_bfloat16 g_ehl[(size_t)NE*TK*EHD];
__device__ __nv_bfloat16 g_t1h[(size_t)TK*HN];
__device__ __nv_bfloat16 g_t1l[(size_t)TK*HN];

// ================= helpers =================
__device__ __forceinline__ unsigned smem_u32(const void* p){
    unsigned a;
    asm("{ .reg .u64 t; cvta.to.shared.u64 t, %1; cvt.u32.u64 %0, t; }" : "=r"(a) : "l"(p));
    return a;
}
__device__ __forceinline__ void split1(float v, __nv_bfloat16& h, __nv_bfloat16& l) {
    h = __float2bfloat16(v);
    l = __float2bfloat16(v - __bfloat162float(h));
}
__device__ __forceinline__ void split2w(float v0, float v1, unsigned& hw, unsigned& lw) {
    __nv_bfloat16 h0, l0, h1, l1;
    split1(v0, h0, l0); split1(v1, h1, l1);
    hw = (unsigned)__bfloat16_as_ushort(h0) | ((unsigned)__bfloat16_as_ushort(h1) << 16);
    lw = (unsigned)__bfloat16_as_ushort(l0) | ((unsigned)__bfloat16_as_ushort(l1) << 16);
}

#define LDSM_X4(r0, r1, r2, r3, a) \
    asm volatile("ldmatrix.sync.aligned.m8n8.x4.shared.b16 {%0,%1,%2,%3}, [%4];" \
                 : "=r"(r0), "=r"(r1), "=r"(r2), "=r"(r3) : "r"(a))
#define LDSM_X2(r0, r1, a) \
    asm volatile("ldmatrix.sync.aligned.m8n8.x2.shared.b16 {%0,%1}, [%2];" \
                 : "=r"(r0), "=r"(r1) : "r"(a))
#define MMA16816(d, a, b) \
    asm volatile("mma.sync.aligned.m16n8k16.row.col.f32.bf16.bf16.f32 " \
                 "{%0,%1,%2,%3}, {%4,%5,%6,%7}, {%8,%9}, {%0,%1,%2,%3};" \
                 : "+f"((d)[0]), "+f"((d)[1]), "+f"((d)[2]), "+f"((d)[3]) \
                 : "r"((a)[0]), "r"((a)[1]), "r"((a)[2]), "r"((a)[3]), \
                   "r"((b)[0]), "r"((b)[1]))
#define CP_ASYNC16(sa, gp) \
    asm volatile("cp.async.cg.shared.global [%0], [%1], 16;" :: "r"(sa), "l"(gp) : "memory")
#define CP_COMMIT() asm volatile("cp.async.commit_group;" ::: "memory")
#define CP_WAIT1()  asm volatile("cp.async.wait_group 1;" ::: "memory")
#define CP_WAIT0()  asm volatile("cp.async.wait_group 0;" ::: "memory")

// ================= bf16x3 MMA GEMM (cp.async 3-stage) =================
// C[M,N] = act(alpha*(A@B^T) + bias); A,B pre-split bf16 hi/lo; B^T stored [N,K]
#define BM 128
#define BN 256
#define KC 32
#define ROWB 80          // 80B row stride: ldmatrix conflict-free, 16B aligned
#define RG_AL 10240
#define RG_BH 20480
#define RG_BL 40960
#define STGB  61440
#define NSTG  3
#define SMEMB (NSTG*STGB)

template<int ACT, bool GATHER, bool SCATTER, bool OSPLIT, bool OF32>
__global__ void __launch_bounds__(512, 1)
tc_k(const __nv_bfloat16* __restrict__ Ah, const __nv_bfloat16* __restrict__ Al,
     const __nv_bfloat16* __restrict__ Bh, const __nv_bfloat16* __restrict__ Bl,
     const float* __restrict__ bias,
     float* __restrict__ C, __nv_bfloat16* __restrict__ Ch, __nv_bfloat16* __restrict__ Cl,
     int M, int N, int Kd, int lda, int ldb, int ldc,
     long long sAb, long long sAh_, long long sBb, long long sBh_,
     long long sCb, long long sCh_, long long sBias, int nh, float alpha,
     const int* __restrict__ ridx, const int* __restrict__ cptr)
{
    if (nh > 0) {
        int z = blockIdx.z, zb = z / nh, zh = z % nh;
        long long ao = zb*sAb + zh*sAh_;
        Ah += ao; Al += ao;
        long long bo = zb*sBb + zh*sBh_;
        Bh += bo; Bl += bo;
        long long co = zb*sCb + zh*sCh_;
        if (OF32 || SCATTER) C += co;
        if (OSPLIT) { Ch += co; Cl += co; }
        if (bias) bias += zb*sBias;
        if (GATHER || SCATTER) ridx += (long long)zb*TK;
        if (cptr) cptr += zb;
    }
    if (cptr) M = *cptr;
    int m0 = blockIdx.y*BM, n0 = blockIdx.x*BN;
    if (m0 >= M) return;

    extern __shared__ char sm[];
    unsigned sb = smem_u32(sm);
    int tid = threadIdx.x, lane = tid & 31, wid = tid >> 5;
    int wm = wid & 1, wn = wid >> 1;       // 2 x 8 warp grid; warp tile 64x32

    float acc[4][4][4];
#pragma unroll
    for (int i = 0; i < 4; i++)
#pragma unroll
        for (int j = 0; j < 4; j++)
#pragma unroll
            for (int e = 0; e < 4; e++) acc[i][j][e] = 0.f;

    // ---- load mapping: 512 threads; row = tid>>2 (0..127), 16B chunk = tid&3 ----
    int lr = tid >> 2, lc = tid & 3;
    long long arow;
    { int gm = m0 + lr; if (gm >= M) gm = M - 1;
      arow = GATHER ? (long long)ridx[gm] : (long long)gm; }
    const __nv_bfloat16* pAh  = Ah + arow*lda + lc*8;
    const __nv_bfloat16* pAl  = Al + arow*lda + lc*8;
    const __nv_bfloat16* pBh0 = Bh + (long long)(n0 + lr)*ldb + lc*8;
    const __nv_bfloat16* pBl0 = Bl + (long long)(n0 + lr)*ldb + lc*8;
    const __nv_bfloat16* pBh1 = pBh0 + (long long)128*ldb;
    const __nv_bfloat16* pBl1 = pBl0 + (long long)128*ldb;
    unsigned offR = (unsigned)lr*ROWB + (unsigned)lc*16;

    int NC = Kd / KC;

    auto issue = [&](int s) {
        unsigned base = sb + (unsigned)(s % NSTG)*STGB;
        int k0 = s*KC;
        CP_ASYNC16(base + offR,                 pAh  + k0);
        CP_ASYNC16(base + RG_AL + offR,         pAl  + k0);
        CP_ASYNC16(base + RG_BH + offR,         pBh0 + k0);
        CP_ASYNC16(base + RG_BH + 10240 + offR, pBh1 + k0);
        CP_ASYNC16(base + RG_BL + offR,         pBl0 + k0);
        CP_ASYNC16(base + RG_BL + 10240 + offR, pBl1 + k0);
        CP_COMMIT();
    };

    issue(0);
    if (NC > 1) issue(1);

    unsigned aoff = (unsigned)(lane & 15)*ROWB + (unsigned)(lane >> 4)*16;
    unsigned boff = (unsigned)(lane & 7)*ROWB + (unsigned)((lane >> 3) & 1)*16;

    for (int i = 0; i < NC; i++) {
        if (i + 1 < NC) { CP_WAIT1(); } else { CP_WAIT0(); }
        __syncthreads();
        if (i + 2 < NC) issue(i + 2);

        unsigned st = sb + (unsigned)(i % NSTG)*STGB;
        unsigned abase = st + (unsigned)(wm*64)*ROWB;
        unsigned bbase = st + RG_BH + (unsigned)(wn*32)*ROWB;
#pragma unroll
        for (int ks = 0; ks < 2; ks++) {
            unsigned ah[4][4], al[4][4], bh[4][2], bl[4][2];
#pragma unroll
            for (int mt = 0; mt < 4; mt++) {
                unsigned ad = abase + (unsigned)(mt*16)*ROWB + aoff + ks*32;
                LDSM_X4(ah[mt][0], ah[mt][1], ah[mt][2], ah[mt][3], ad);
                LDSM_X4(al[mt][0], al[mt][1], al[mt][2], al[mt][3], ad + RG_AL);
            }
#pragma unroll
            for (int nt = 0; nt < 4; nt++) {
                unsigned bd = bbase + (unsigned)(nt*8)*ROWB + boff + ks*32;
                LDSM_X2(bh[nt][0], bh[nt][1], bd);
                LDSM_X2(bl[nt][0], bl[nt][1], bd + (RG_BL - RG_BH));
            }
#pragma unroll
            for (int mt = 0; mt < 4; mt++)
#pragma unroll
                for (int nt = 0; nt < 4; nt++) {
                    MMA16816(acc[mt][nt], ah[mt], bh[nt]);
                    MMA16816(acc[mt][nt], ah[mt], bl[nt]);
                    MMA16816(acc[mt][nt], al[mt], bh[nt]);
                }
        }
    }

    // ---- epilogue ----
#pragma unroll
    for (int mt = 0; mt < 4; mt++) {
#pragma unroll
        for (int half = 0; half < 2; half++) {
            int gm = m0 + wm*64 + mt*16 + (lane >> 2) + half*8;
            if (gm >= M) continue;
            long long crow = SCATTER ? (long long)ridx[gm]*ldc : (long long)gm*ldc;
#pragma unroll
            for (int nt = 0; nt < 4; nt++) {
                int gn = n0 + wn*32 + nt*8 + (lane & 3)*2;
                float v0 = acc[mt][nt][half*2 + 0] * alpha;
                float v1 = acc[mt][nt][half*2 + 1] * alpha;
                if (bias) { v0 += bias[gn]; v1 += bias[gn+1]; }
                if (ACT == 1) {
                    v0 = 0.5f*v0*(1.0f + erff(v0*0.7071067811865475f));
                    v1 = 0.5f*v1*(1.0f + erff(v1*0.7071067811865475f));
                } else if (ACT == 2) {
                    v0 = v0 > 0.f ? v0 : 0.f;
                    v1 = v1 > 0.f ? v1 : 0.f;
                }
                if (SCATTER) {
                    atomicAdd(C + crow + gn,     v0);
                    atomicAdd(C + crow + gn + 1, v1);
                } else {
                    if (OF32) *(float2*)(C + crow + gn) = make_float2(v0, v1);
                    if (OSPLIT) {
                        unsigned hw, lw; split2w(v0, v1, hw, lw);
                        *(unsigned*)(Ch + crow + gn) = hw;
                        *(unsigned*)(Cl + crow + gn) = lw;
                    }
                }
            }
        }
    }
}

// ================= weight prep =================
__global__ void split_k(const float* __restrict__ W, __nv_bfloat16* __restrict__ hi,
                        __nv_bfloat16* __restrict__ lo, long long n) {
    long long i = (long long)blockIdx.x*256 + threadIdx.x;
    if (i >= n) return;
    __nv_bfloat16 h, l; split1(W[i], h, l);
    hi[i] = h; lo[i] = l;
}
__global__ void transsplit_k(const float* __restrict__ W, int ldw,
                             __nv_bfloat16* __restrict__ hi, __nv_bfloat16* __restrict__ lo,
                             int Kd, int Nd, long long sWb, long long sWh,
                             long long sOb, long long sOh, int nhz) {
    int z = blockIdx.z, zb = z / nhz, zh = z % nhz;
    W += zb*sWb + zh*sWh; hi += zb*sOb + zh*sOh; lo += zb*sOb + zh*sOh;
    __shared__ float ts[32][33];
    int n0 = blockIdx.x*32, k0 = blockIdx.y*32;
    int tx = threadIdx.x & 31, ty = threadIdx.x >> 5;
    for (int r = ty; r < 32; r += 8)
        ts[r][tx] = W[(long long)(k0 + r)*ldw + n0 + tx];
    __syncthreads();
    for (int r = ty; r < 32; r += 8) {
        __nv_bfloat16 h, l; split1(ts[tx][r], h, l);
        long long o = (long long)(n0 + r)*Kd + k0 + tx;
        hi[o] = h; lo[o] = l;
    }
}

// ================= misc kernels =================
__global__ void embed_k(const int* __restrict__ ids, const float* __restrict__ emb,
                        float* __restrict__ out,
                        __nv_bfloat16* __restrict__ oh, __nv_bfloat16* __restrict__ ol) {
    int t = blockIdx.x;
    const float* src = emb + (size_t)ids[t]*HN;
    for (int i = threadIdx.x; i < HN; i += blockDim.x) {
        float v = src[i];
        out[(size_t)t*HN + i] = v;
        __nv_bfloat16 h, l; split1(v, h, l);
        oh[(size_t)t*HN + i] = h; ol[(size_t)t*HN + i] = l;
    }
}
__global__ void softmax_k(float* __restrict__ p,
                          __nv_bfloat16* __restrict__ oh, __nv_bfloat16* __restrict__ ol) {
    long long row = blockIdx.x;
    float* r = p + row*SS;
    int tid = threadIdx.x;
    __shared__ float red[256];
    float mx = -1e30f;
    for (int i = tid; i < SS; i += 256) mx = fmaxf(mx, r[i]);
    red[tid] = mx; __syncthreads();
    for (int s = 128; s > 0; s >>= 1) { if (tid < s) red[tid] = fmaxf(red[tid], red[tid+s]); __syncthreads(); }
    mx = red[0]; __syncthreads();
    float sum = 0.f;
    for (int i = tid; i < SS; i += 256) { float e = expf(r[i]-mx); r[i] = e; sum += e; }
    red[tid] = sum; __syncthreads();
    for (int s = 128; s > 0; s >>= 1) { if (tid < s) red[tid] += red[tid+s]; __syncthreads(); }
    float inv = 1.f/red[0];
    for (int i = tid; i < SS; i += 256) {
        float v = r[i]*inv;
        __nv_bfloat16 h, l; split1(v, h, l);
        oh[row*SS + i] = h; ol[row*SS + i] = l;
    }
}
__global__ void ln_k(const float* __restrict__ resid, const float* __restrict__ delta,
                     const float* __restrict__ g, const float* __restrict__ b,
                     float* __restrict__ out,
                     __nv_bfloat16* __restrict__ oh, __nv_bfloat16* __restrict__ ol) {
    long long t = blockIdx.x;
    int tid = threadIdx.x;
    __shared__ float buf[HN];
    __shared__ float red[256];
    float s = 0.f;
    for (int i = tid; i < HN; i += 256) { float v = resid[t*HN+i] + delta[t*HN+i]; buf[i] = v; s += v; }
    red[tid] = s; __syncthreads();
    for (int st = 128; st > 0; st >>= 1) { if (tid < st) red[tid] += red[tid+st]; __syncthreads(); }
    float m = red[0]*(1.0f/HN); __syncthreads();
    float s2 = 0.f;
    for (int i = tid; i < HN; i += 256) { float d = buf[i]-m; s2 += d*d; }
    red[tid] = s2; __syncthreads();
    for (int st = 128; st > 0; st >>= 1) { if (tid < st) red[tid] += red[tid+st]; __syncthreads(); }
    float inv = rsqrtf(red[0]*(1.0f/HN) + 1e-5f);
    for (int i = tid; i < HN; i += 256) {
        float v = (buf[i]-m)*inv*g[i] + b[i];
        out[t*HN+i] = v;
        __nv_bfloat16 h, l; split1(v, h, l);
        oh[t*HN+i] = h; ol[t*HN+i] = l;
    }
}
__global__ void gate_k(const float* __restrict__ x, const float* __restrict__ gw,
                       const float* __restrict__ gb, int* __restrict__ cnt,
                       int* __restrict__ toks) {
    int t = blockIdx.x;
    int tid = threadIdx.x;
    __shared__ float xs[HN];
    __shared__ float red[256];
    for (int i = tid; i < HN; i += 256) xs[i] = x[(long long)t*HN+i];
    __syncthreads();
    int e = tid & 7, g = tid >> 3;
    float p = 0.f;
    for (int j = g; j < HN; j += 32) p += xs[j]*gw[j*NE+e];
    red[tid] = p; __syncthreads();
    if (tid < 8) {
        float s = 0.f;
        for (int j = 0; j < 32; j++) s += red[j*8 + tid];
        red[tid] = s + gb[tid];
    }
    __syncthreads();
    if (tid == 0) {
        float l[NE];
        for (int i = 0; i < NE; i++) l[i] = red[i];
        int i1 = 0;
        for (int i = 1; i < NE; i++) if (l[i] > l[i1]) i1 = i;
        int i2 = (i1 == 0) ? 1 : 0;
        for (int i = 0; i < NE; i++) if (i != i1 && l[i] > l[i2]) i2 = i;
        int p1 = atomicAdd(&cnt[i1], 1); toks[i1*TK+p1] = t;
        int p2 = atomicAdd(&cnt[i2], 1); toks[i2*TK+p2] = t;
    }
}
__global__ void zero_f(float* p, long long n) {
    long long i = (long long)blockIdx.x*blockDim.x + threadIdx.x;
    if (i < n) p[i] = 0.f;
}
__global__ void zero_i(int* p, int n) {
    int i = blockIdx.x*blockDim.x + threadIdx.x;
    if (i < n) p[i] = 0;
}
__global__ void copysplit_k(float* __restrict__ dst, __nv_bfloat16* __restrict__ oh,
                            __nv_bfloat16* __restrict__ ol, const float* __restrict__ src,
                            long long n) {
    long long i = (long long)blockIdx.x*blockDim.x + threadIdx.x;
    if (i >= n) return;
    float v = src[i];
    dst[i] = v;
    __nv_bfloat16 h, l; split1(v, h, l);
    oh[i] = h; ol[i] = l;
}

// ================= launch =================
extern "C" void kernel_launch(void* const* d_in, const int* in_sizes, int n_in,
                              void* d_out, int out_size)
{
    const int*   ids   = (const int*)d_in[0];
    const float* emb   = (const float*)d_in[1];
    const float* qkvw  = (const float*)d_in[2];
    const float* qkvb  = (const float*)d_in[3];
    const float* outw  = (const float*)d_in[4];
    const float* outb  = (const float*)d_in[5];
    const float* ln1g  = (const float*)d_in[6];
    const float* ln1b  = (const float*)d_in[7];
    const float* ffw1  = (const float*)d_in[8];
    const float* ffb1  = (const float*)d_in[9];
    const float* ffw2  = (const float*)d_in[10];
    const float* ffb2  = (const float*)d_in[11];
    const float* ln2g  = (const float*)d_in[12];
    const float* ln2b  = (const float*)d_in[13];
    const float* gw    = (const float*)d_in[14];
    const float* gb    = (const float*)d_in[15];
    const float* ew1   = (const float*)d_in[16];
    const float* eb1   = (const float*)d_in[17];
    const float* ew2   = (const float*)d_in[18];
    const float* eb2   = (const float*)d_in[19];
    const float* lmw   = (const float*)d_in[20];
    const float* lmb   = (const float*)d_in[21];
    float* out = (float*)d_out;

    float *x, *t1, *big, *sc; int *cnt, *tok;
    __nv_bfloat16 *wh, *wl, *vth, *vtl, *xh, *xl, *bh, *bl, *ph, *pl, *ehh, *ehl, *t1h, *t1l;
    cudaGetSymbolAddress((void**)&x,   g_x);
    cudaGetSymbolAddress((void**)&t1,  g_t1);
    cudaGetSymbolAddress((void**)&big, g_big);
    cudaGetSymbolAddress((void**)&sc,  g_sc);
    cudaGetSymbolAddress((void**)&cnt, g_cnt);
    cudaGetSymbolAddress((void**)&tok, g_tok);
    cudaGetSymbolAddress((void**)&wh,  g_wh);
    cudaGetSymbolAddress((void**)&wl,  g_wl);
    cudaGetSymbolAddress((void**)&vth, g_vth);
    cudaGetSymbolAddress((void**)&vtl, g_vtl);
    cudaGetSymbolAddress((void**)&xh,  g_xh);
    cudaGetSymbolAddress((void**)&xl,  g_xl);
    cudaGetSymbolAddress((void**)&bh,  g_bh);
    cudaGetSymbolAddress((void**)&bl,  g_bl);
    cudaGetSymbolAddress((void**)&ph,  g_ph);
    cudaGetSymbolAddress((void**)&pl,  g_pl);
    cudaGetSymbolAddress((void**)&ehh, g_ehh);
    cudaGetSymbolAddress((void**)&ehl, g_ehl);
    cudaGetSymbolAddress((void**)&t1h, g_t1h);
    cudaGetSymbolAddress((void**)&t1l, g_t1l);

    cudaFuncSetAttribute(tc_k<0,false,false,true, true >, cudaFuncAttributeMaxDynamicSharedMemorySize, SMEMB);
    cudaFuncSetAttribute(tc_k<0,false,false,false,true >, cudaFuncAttributeMaxDynamicSharedMemorySize, SMEMB);
    cudaFuncSetAttribute(tc_k<0,false,false,true, false>, cudaFuncAttributeMaxDynamicSharedMemorySize, SMEMB);
    cudaFuncSetAttribute(tc_k<1,false,false,true, false>, cudaFuncAttributeMaxDynamicSharedMemorySize, SMEMB);
    cudaFuncSetAttribute(tc_k<2,true, false,true, false>, cudaFuncAttributeMaxDynamicSharedMemorySize, SMEMB);
    cudaFuncSetAttribute(tc_k<0,false,true, false,false>, cudaFuncAttributeMaxDynamicSharedMemorySize, SMEMB);

    const long long Z0 = 0;

    // ---- weight pre-split ----
    split_k<<<(unsigned)(((long long)NL*3*HN*HN + 255)/256), 256>>>(qkvw, wh + OFF_QKV, wl + OFF_QKV, (long long)NL*3*HN*HN);
    split_k<<<(unsigned)(((long long)NL*HN*HN + 255)/256), 256>>>(outw, wh + OFF_OUT, wl + OFF_OUT, (long long)NL*HN*HN);
    transsplit_k<<<dim3(FFD/32, HN/32, NL), 256>>>(ffw1, FFD, wh + OFF_FF1, wl + OFF_FF1,
        HN, FFD, (long long)HN*FFD, Z0, (long long)HN*FFD, Z0, 1);
    transsplit_k<<<dim3(HN/32, FFD/32, NL), 256>>>(ffw2, HN, wh + OFF_FF2, wl + OFF_FF2,
        FFD, HN, (long long)FFD*HN, Z0, (long long)FFD*HN, Z0, 1);
    transsplit_k<<<dim3(EHD/32, HN/32, NL*NE), 256>>>(ew1, EHD, wh + OFF_E1, wl + OFF_E1,
        HN, EHD, (long long)HN*EHD, Z0, (long long)HN*EHD, Z0, 1);
    transsplit_k<<<dim3(HN/32, EHD/32, NL*NE), 256>>>(ew2, HN, wh + OFF_E2, wl + OFF_E2,
        EHD, HN, (long long)EHD*HN, Z0, (long long)EHD*HN, Z0, 1);
    transsplit_k<<<dim3(VS/32, HN/32, 1), 256>>>(lmw, VS, wh + OFF_LM, wl + OFF_LM,
        HN, VS, Z0, Z0, Z0, Z0, 1);

    embed_k<<<TK, 256>>>(ids, emb, x, xh, xl);

    for (int l = 0; l < NL; l++) {
        // qkv = x @ Wqkv^T + b  -> big fp32 + bigh/bigl
        tc_k<0,false,false,true,true><<<dim3(3*HN/BN, TK/BM, 1), 512, SMEMB>>>(
            xh, xl, wh + OFF_QKV + (long long)l*3*HN*HN, wl + OFF_QKV + (long long)l*3*HN*HN,
            qkvb + (long long)l*3*HN, big, bh, bl, TK, 3*HN, HN, HN, HN, 3*HN,
            Z0,Z0,Z0,Z0,Z0,Z0,Z0, 0, 1.f, nullptr, nullptr);

        // V^T split per (b,h)
        transsplit_k<<<dim3(HDD/32, SS/32, BB*NHD), 256>>>(
            big + 2*HN, 3*HN, vth, vtl, SS, HDD,
            (long long)SS*3*HN, (long long)HDD,
            (long long)NHD*HDD*SS, (long long)HDD*SS, NHD);

        // scores = Q @ K^T / 16 -> sc fp32
        tc_k<0,false,false,false,true><<<dim3(SS/BN, SS/BM, BB*NHD), 512, SMEMB>>>(
            bh, bl, bh + HN, bl + HN, nullptr, sc, nullptr, nullptr,
            SS, SS, HDD, 3*HN, 3*HN, SS,
            (long long)SS*3*HN, (long long)HDD,
            (long long)SS*3*HN, (long long)HDD,
            (long long)NHD*SS*SS, (long long)SS*SS, Z0, NHD,
            0.0625f, nullptr, nullptr);

        softmax_k<<<BB*NHD*SS, 256>>>(sc, ph, pl);

        // ao = probs @ V -> t1h/t1l
        tc_k<0,false,false,true,false><<<dim3(HDD/BN, SS/BM, BB*NHD), 512, SMEMB>>>(
            ph, pl, vth, vtl, nullptr, nullptr, t1h, t1l,
            SS, HDD, SS, SS, SS, HN,
            (long long)NHD*SS*SS, (long long)SS*SS,
            (long long)NHD*HDD*SS, (long long)HDD*SS,
            (long long)SS*HN, (long long)HDD, Z0, NHD,
            1.f, nullptr, nullptr);

        // proj = ao @ Wout^T + b -> big fp32
        tc_k<0,false,false,false,true><<<dim3(HN/BN, TK/BM, 1), 512, SMEMB>>>(
            t1h, t1l, wh + OFF_OUT + (long long)l*HN*HN, wl + OFF_OUT + (long long)l*HN*HN,
            outb + (long long)l*HN, big, nullptr, nullptr, TK, HN, HN, HN, HN, HN,
            Z0,Z0,Z0,Z0,Z0,Z0,Z0, 0, 1.f, nullptr, nullptr);

        ln_k<<<TK,256>>>(x, big, ln1g + (long long)l*HN, ln1b + (long long)l*HN, x, xh, xl);

        // ffn
        tc_k<1,false,false,true,false><<<dim3(FFD/BN, TK/BM, 1), 512, SMEMB>>>(
            xh, xl, wh + OFF_FF1 + (long long)l*HN*FFD, wl + OFF_FF1 + (long long)l*HN*FFD,
            ffb1 + (long long)l*FFD, nullptr, bh, bl, TK, FFD, HN, HN, HN, FFD,
            Z0,Z0,Z0,Z0,Z0,Z0,Z0, 0, 1.f, nullptr, nullptr);
        tc_k<0,false,false,false,true><<<dim3(HN/BN, TK/BM, 1), 512, SMEMB>>>(
            bh, bl, wh + OFF_FF2 + (long long)l*FFD*HN, wl + OFF_FF2 + (long long)l*FFD*HN,
            ffb2 + (long long)l*HN, t1, nullptr, nullptr, TK, HN, FFD, FFD, FFD, HN,
            Z0,Z0,Z0,Z0,Z0,Z0,Z0, 0, 1.f, nullptr, nullptr);

        ln_k<<<TK,256>>>(x, t1, ln2g + (long long)l*HN, ln2b + (long long)l*HN, x, xh, xl);

        // MoE
        zero_i<<<1, NE>>>(cnt, NE);
        gate_k<<<TK,256>>>(x, gw + (long long)l*HN*NE, gb + (long long)l*NE, cnt, tok);
        zero_f<<<(TK*HN)/256, 256>>>(t1, (long long)TK*HN);

        // up: ehh/ehl[e] = relu(x[gather] @ W1_e + b1_e)
        tc_k<2,true,false,true,false><<<dim3(EHD/BN, TK/BM, NE), 512, SMEMB>>>(
            xh, xl, wh + OFF_E1 + (long long)l*NE*HN*EHD, wl + OFF_E1 + (long long)l*NE*HN*EHD,
            eb1 + (long long)l*NE*EHD, nullptr, ehh, ehl, TK, EHD, HN, HN, HN, EHD,
            Z0, Z0, (long long)EHD*HN, Z0, (long long)TK*EHD, Z0, (long long)EHD, 1,
            1.f, tok, cnt);
        // down: t1[token] += eh[e] @ W2_e + b2_e  (atomic scatter)
        tc_k<0,false,true,false,false><<<dim3(HN/BN, TK/BM, NE), 512, SMEMB>>>(
            ehh, ehl, wh + OFF_E2 + (long long)l*NE*EHD*HN, wl + OFF_E2 + (long long)l*NE*EHD*HN,
            eb2 + (long long)l*NE*HN, t1, nullptr, nullptr, TK, HN, EHD, EHD, EHD, HN,
            (long long)TK*EHD, Z0, (long long)HN*EHD, Z0, Z0, Z0, (long long)HN, 1,
            1.f, tok, cnt);

        copysplit_k<<<(TK*HN)/256, 256>>>(x, xh, xl, t1, (long long)TK*HN);
    }

    // lm head
    tc_k<0,false,false,false,true><<<dim3(VS/BN, TK/BM, 1), 512, SMEMB>>>(
        xh, xl, wh + OFF_LM, wl + OFF_LM, lmb, out, nullptr, nullptr,
        TK, VS, HN, HN, HN, VS,
        Z0,Z0,Z0,Z0,Z0,Z0,Z0, 0, 1.f, nullptr, nullptr);
}

// round 10
// speedup vs baseline: 2.9865x; 1.0641x over previous
#include <cuda_runtime.h>
#include <cuda_bf16.h>
#include <math.h>

// ---------------- problem constants ----------------
#define TK   4096
#define HN   1024
#define NHD  4
#define HDD  256
#define BB   4
#define SS   1024
#define FFD  4096
#define NE   8
#define EHD  2048
#define VS   32000
#define NL   2

// ---------------- split-weight offsets (elements) ----------------
#define OFF_QKV 0LL
#define OFF_OUT  (OFF_QKV + (long long)NL*3*HN*HN)
#define OFF_FF1  (OFF_OUT + (long long)NL*HN*HN)
#define OFF_FF2  (OFF_FF1 + (long long)NL*HN*FFD)
#define OFF_E1   (OFF_FF2 + (long long)NL*FFD*HN)
#define OFF_E2   (OFF_E1  + (long long)NL*NE*HN*EHD)
#define OFF_LM   (OFF_E2  + (long long)NL*NE*EHD*HN)
#define TOTW     (OFF_LM  + (long long)HN*VS)

// ---------------- scratch ----------------
__device__ float g_x  [(size_t)TK*HN];
__device__ float g_t1 [(size_t)TK*HN];
__device__ float g_big[(size_t)TK*FFD];
__device__ float g_sc [(size_t)BB*NHD*SS*SS];
__device__ int   g_cnt[NE];
__device__ int   g_tok[NE*TK];
__device__ __nv_bfloat16 g_wh[TOTW];
__device__ __nv_bfloat16 g_wl[TOTW];
__device__ __nv_bfloat16 g_vth[(size_t)BB*NHD*HDD*SS];
__device__ __nv_bfloat16 g_vtl[(size_t)BB*NHD*HDD*SS];
// split activations
__device__ __nv_bfloat16 g_xh [(size_t)TK*HN];
__device__ __nv_bfloat16 g_xl [(size_t)TK*HN];
__device__ __nv_bfloat16 g_bh [(size_t)TK*FFD];
__device__ __nv_bfloat16 g_bl [(size_t)TK*FFD];
__device__ __nv_bfloat16 g_ph [(size_t)BB*NHD*SS*SS];
__device__ __nv_bfloat16 g_pl [(size_t)BB*NHD*SS*SS];
__device__ __nv_bfloat16 g_ehh[(size_t)NE*TK*EHD];
__device__ __nv_bfloat16 g_ehl[(size_t)NE*TK*EHD];
__device__ __nv_bfloat16 g_t1h[(size_t)TK*HN];
__device__ __nv_bfloat16 g_t1l[(size_t)TK*HN];

// ================= helpers =================
__device__ __forceinline__ unsigned smem_u32(const void* p){
    unsigned a;
    asm("{ .reg .u64 t; cvta.to.shared.u64 t, %1; cvt.u32.u64 %0, t; }" : "=r"(a) : "l"(p));
    return a;
}
__device__ __forceinline__ void split1(float v, __nv_bfloat16& h, __nv_bfloat16& l) {
    h = __float2bfloat16(v);
    l = __float2bfloat16(v - __bfloat162float(h));
}
__device__ __forceinline__ void split2w(float v0, float v1, unsigned& hw, unsigned& lw) {
    __nv_bfloat16 h0, l0, h1, l1;
    split1(v0, h0, l0); split1(v1, h1, l1);
    hw = (unsigned)__bfloat16_as_ushort(h0) | ((unsigned)__bfloat16_as_ushort(h1) << 16);
    lw = (unsigned)__bfloat16_as_ushort(l0) | ((unsigned)__bfloat16_as_ushort(l1) << 16);
}

#define LDSM_X4(r0, r1, r2, r3, a) \
    asm volatile("ldmatrix.sync.aligned.m8n8.x4.shared.b16 {%0,%1,%2,%3}, [%4];" \
                 : "=r"(r0), "=r"(r1), "=r"(r2), "=r"(r3) : "r"(a))
#define MMA16816(d, a, b) \
    asm volatile("mma.sync.aligned.m16n8k16.row.col.f32.bf16.bf16.f32 " \
                 "{%0,%1,%2,%3}, {%4,%5,%6,%7}, {%8,%9}, {%0,%1,%2,%3};" \
                 : "+f"((d)[0]), "+f"((d)[1]), "+f"((d)[2]), "+f"((d)[3]) \
                 : "r"((a)[0]), "r"((a)[1]), "r"((a)[2]), "r"((a)[3]), \
                   "r"((b)[0]), "r"((b)[1]))
#define CP_ASYNC16(sa, gp) \
    asm volatile("cp.async.cg.shared.global [%0], [%1], 16;" :: "r"(sa), "l"(gp) : "memory")
#define CP_COMMIT() asm volatile("cp.async.commit_group;" ::: "memory")
#define CP_WAIT1()  asm volatile("cp.async.wait_group 1;" ::: "memory")
#define CP_WAIT0()  asm volatile("cp.async.wait_group 0;" ::: "memory")

// ================= bf16x3 MMA GEMM (cp.async 3-stage) =================
#define BM 128
#define BN 256
#define KC 32
#define ROWB 80
#define RG_AL 10240
#define RG_BH 20480
#define RG_BL 40960
#define STGB  61440
#define NSTG  3
#define SMEMB (NSTG*STGB)

template<int ACT, bool GATHER, bool SCATTER, bool OSPLIT, bool OF32, bool SWAP>
__global__ void __launch_bounds__(512, 1)
tc_k(const __nv_bfloat16* __restrict__ Ah, const __nv_bfloat16* __restrict__ Al,
     const __nv_bfloat16* __restrict__ Bh, const __nv_bfloat16* __restrict__ Bl,
     const float* __restrict__ bias,
     float* __restrict__ C, __nv_bfloat16* __restrict__ Ch, __nv_bfloat16* __restrict__ Cl,
     int M, int N, int Kd, int lda, int ldb, int ldc,
     long long sAb, long long sAh_, long long sBb, long long sBh_,
     long long sCb, long long sCh_, long long sBias, int nh, float alpha,
     const int* __restrict__ ridx, const int* __restrict__ cptr)
{
    if (nh > 0) {
        int z = blockIdx.z, zb = z / nh, zh = z % nh;
        long long ao = zb*sAb + zh*sAh_;
        Ah += ao; Al += ao;
        long long bo = zb*sBb + zh*sBh_;
        Bh += bo; Bl += bo;
        long long co = zb*sCb + zh*sCh_;
        if (OF32 || SCATTER) C += co;
        if (OSPLIT) { Ch += co; Cl += co; }
        if (bias) bias += zb*sBias;
        if (GATHER || SCATTER) ridx += (long long)zb*TK;
        if (cptr) cptr += zb;
    }
    if (cptr) M = *cptr;
    // SWAP: M-inner rasterization (consecutive CTAs share the B tile) for
    // GEMMs whose B exceeds L2 (LM head).
    int m0 = SWAP ? blockIdx.x*BM : blockIdx.y*BM;
    int n0 = SWAP ? blockIdx.y*BN : blockIdx.x*BN;
    if (m0 >= M) return;

    extern __shared__ char sm[];
    unsigned sb = smem_u32(sm);
    int tid = threadIdx.x, lane = tid & 31, wid = tid >> 5;
    int wm = wid & 1, wn = wid >> 1;       // 2 x 8 warp grid; warp tile 64x32

    float acc[4][4][4];
#pragma unroll
    for (int i = 0; i < 4; i++)
#pragma unroll
        for (int j = 0; j < 4; j++)
#pragma unroll
            for (int e = 0; e < 4; e++) acc[i][j][e] = 0.f;

    // ---- load mapping: 512 threads; row = tid>>2 (0..127), 16B chunk = tid&3 ----
    int lr = tid >> 2, lc = tid & 3;
    long long arow;
    { int gm = m0 + lr; if (gm >= M) gm = M - 1;
      arow = GATHER ? (long long)ridx[gm] : (long long)gm; }
    const __nv_bfloat16* pAh  = Ah + arow*lda + lc*8;
    const __nv_bfloat16* pAl  = Al + arow*lda + lc*8;
    const __nv_bfloat16* pBh0 = Bh + (long long)(n0 + lr)*ldb + lc*8;
    const __nv_bfloat16* pBl0 = Bl + (long long)(n0 + lr)*ldb + lc*8;
    const __nv_bfloat16* pBh1 = pBh0 + (long long)128*ldb;
    const __nv_bfloat16* pBl1 = pBl0 + (long long)128*ldb;
    unsigned offR = (unsigned)lr*ROWB + (unsigned)lc*16;

    int NC = Kd / KC;

    auto issue = [&](int s) {
        unsigned base = sb + (unsigned)(s % NSTG)*STGB;
        int k0 = s*KC;
        CP_ASYNC16(base + offR,                 pAh  + k0);
        CP_ASYNC16(base + RG_AL + offR,         pAl  + k0);
        CP_ASYNC16(base + RG_BH + offR,         pBh0 + k0);
        CP_ASYNC16(base + RG_BH + 10240 + offR, pBh1 + k0);
        CP_ASYNC16(base + RG_BL + offR,         pBl0 + k0);
        CP_ASYNC16(base + RG_BL + 10240 + offR, pBl1 + k0);
        CP_COMMIT();
    };

    issue(0);
    if (NC > 1) issue(1);

    unsigned aoff = (unsigned)(lane & 15)*ROWB + (unsigned)(lane >> 4)*16;
    // paired-B ldmatrix x4: lanes 0-15 -> tile nt (k-lo/k-hi), lanes 16-31 -> tile nt+1
    unsigned boff = (unsigned)(lane & 7)*ROWB + (unsigned)((lane >> 3) & 1)*16
                  + (unsigned)(lane >> 4)*(8*ROWB);

    for (int i = 0; i < NC; i++) {
        if (i + 1 < NC) { CP_WAIT1(); } else { CP_WAIT0(); }
        __syncthreads();
        if (i + 2 < NC) issue(i + 2);

        unsigned st = sb + (unsigned)(i % NSTG)*STGB;
        unsigned abase = st + (unsigned)(wm*64)*ROWB;
        unsigned bbase = st + RG_BH + (unsigned)(wn*32)*ROWB;
#pragma unroll
        for (int ks = 0; ks < 2; ks++) {
            unsigned ah[4][4], al[4][4], bh[4][2], bl[4][2];
#pragma unroll
            for (int mt = 0; mt < 4; mt++) {
                unsigned ad = abase + (unsigned)(mt*16)*ROWB + aoff + ks*32;
                LDSM_X4(ah[mt][0], ah[mt][1], ah[mt][2], ah[mt][3], ad);
                LDSM_X4(al[mt][0], al[mt][1], al[mt][2], al[mt][3], ad + RG_AL);
            }
#pragma unroll
            for (int nt = 0; nt < 4; nt += 2) {
                unsigned bd = bbase + (unsigned)(nt*8)*ROWB + boff + ks*32;
                LDSM_X4(bh[nt][0], bh[nt][1], bh[nt+1][0], bh[nt+1][1], bd);
                LDSM_X4(bl[nt][0], bl[nt][1], bl[nt+1][0], bl[nt+1][1], bd + (RG_BL - RG_BH));
            }
#pragma unroll
            for (int mt = 0; mt < 4; mt++)
#pragma unroll
                for (int nt = 0; nt < 4; nt++) {
                    MMA16816(acc[mt][nt], ah[mt], bh[nt]);
                    MMA16816(acc[mt][nt], ah[mt], bl[nt]);
                    MMA16816(acc[mt][nt], al[mt], bh[nt]);
                }
        }
    }

    // ---- epilogue ----
#pragma unroll
    for (int mt = 0; mt < 4; mt++) {
#pragma unroll
        for (int half = 0; half < 2; half++) {
            int gm = m0 + wm*64 + mt*16 + (lane >> 2) + half*8;
            if (gm >= M) continue;
            long long crow = SCATTER ? (long long)ridx[gm]*ldc : (long long)gm*ldc;
#pragma unroll
            for (int nt = 0; nt < 4; nt++) {
                int gn = n0 + wn*32 + nt*8 + (lane & 3)*2;
                float v0 = acc[mt][nt][half*2 + 0] * alpha;
                float v1 = acc[mt][nt][half*2 + 1] * alpha;
                if (bias) { v0 += bias[gn]; v1 += bias[gn+1]; }
                if (ACT == 1) {
                    v0 = 0.5f*v0*(1.0f + erff(v0*0.7071067811865475f));
                    v1 = 0.5f*v1*(1.0f + erff(v1*0.7071067811865475f));
                } else if (ACT == 2) {
                    v0 = v0 > 0.f ? v0 : 0.f;
                    v1 = v1 > 0.f ? v1 : 0.f;
                }
                if (SCATTER) {
                    atomicAdd(C + crow + gn,     v0);
                    atomicAdd(C + crow + gn + 1, v1);
                } else {
                    if (OF32) *(float2*)(C + crow + gn) = make_float2(v0, v1);
                    if (OSPLIT) {
                        unsigned hw, lw; split2w(v0, v1, hw, lw);
                        *(unsigned*)(Ch + crow + gn) = hw;
                        *(unsigned*)(Cl + crow + gn) = lw;
                    }
                }
            }
        }
    }
}

// ================= weight prep =================
__global__ void split_k(const float* __restrict__ W, __nv_bfloat16* __restrict__ hi,
                        __nv_bfloat16* __restrict__ lo, long long n) {
    long long i = (long long)blockIdx.x*256 + threadIdx.x;
    if (i >= n) return;
    __nv_bfloat16 h, l; split1(W[i], h, l);
    hi[i] = h; lo[i] = l;
}
__global__ void transsplit_k(const float* __restrict__ W, int ldw,
                             __nv_bfloat16* __restrict__ hi, __nv_bfloat16* __restrict__ lo,
                             int Kd, int Nd, long long sWb, long long sWh,
                             long long sOb, long long sOh, int nhz) {
    int z = blockIdx.z, zb = z / nhz, zh = z % nhz;
    W += zb*sWb + zh*sWh; hi += zb*sOb + zh*sOh; lo += zb*sOb + zh*sOh;
    __shared__ float ts[32][33];
    int n0 = blockIdx.x*32, k0 = blockIdx.y*32;
    int tx = threadIdx.x & 31, ty = threadIdx.x >> 5;
    for (int r = ty; r < 32; r += 8)
        ts[r][tx] = W[(long long)(k0 + r)*ldw + n0 + tx];
    __syncthreads();
    for (int r = ty; r < 32; r += 8) {
        __nv_bfloat16 h, l; split1(ts[tx][r], h, l);
        long long o = (long long)(n0 + r)*Kd + k0 + tx;
        hi[o] = h; lo[o] = l;
    }
}

// ================= block reduce helpers (FIXED: smem broadcast) =================
__device__ __forceinline__ float blk_sum(float v, float* red, int tid) {
#pragma unroll
    for (int o = 16; o > 0; o >>= 1) v += __shfl_xor_sync(0xffffffffu, v, o);
    if ((tid & 31) == 0) red[tid >> 5] = v;
    __syncthreads();
    if (tid < 32) {
        float s = (tid < 8) ? red[tid] : 0.f;
#pragma unroll
        for (int o = 4; o > 0; o >>= 1) s += __shfl_xor_sync(0xffffffffu, s, o);
        if (tid == 0) red[0] = s;
    }
    __syncthreads();
    float r = red[0];
    __syncthreads();
    return r;
}
__device__ __forceinline__ float blk_max(float v, float* red, int tid) {
#pragma unroll
    for (int o = 16; o > 0; o >>= 1) v = fmaxf(v, __shfl_xor_sync(0xffffffffu, v, o));
    if ((tid & 31) == 0) red[tid >> 5] = v;
    __syncthreads();
    if (tid < 32) {
        float s = (tid < 8) ? red[tid] : -1e30f;
#pragma unroll
        for (int o = 4; o > 0; o >>= 1) s = fmaxf(s, __shfl_xor_sync(0xffffffffu, s, o));
        if (tid == 0) red[0] = s;
    }
    __syncthreads();
    float r = red[0];
    __syncthreads();
    return r;
}

// ================= misc kernels (vectorized) =================
__global__ void embed_k(const int* __restrict__ ids, const float* __restrict__ emb,
                        float* __restrict__ out,
                        __nv_bfloat16* __restrict__ oh, __nv_bfloat16* __restrict__ ol) {
    long long t = blockIdx.x;
    int tid = threadIdx.x;                         // 256
    float4 v = ((const float4*)(emb + (size_t)ids[t]*HN))[tid];
    ((float4*)(out + t*HN))[tid] = v;
    unsigned h0, l0, h1, l1;
    split2w(v.x, v.y, h0, l0); split2w(v.z, v.w, h1, l1);
    ((uint2*)(oh + t*HN))[tid] = make_uint2(h0, h1);
    ((uint2*)(ol + t*HN))[tid] = make_uint2(l0, l1);
}
__global__ void softmax_k(const float* __restrict__ p,
                          __nv_bfloat16* __restrict__ oh, __nv_bfloat16* __restrict__ ol) {
    long long row = blockIdx.x;
    int tid = threadIdx.x;                         // 256, SS=1024 -> 1 float4/thread
    __shared__ float red[8];
    float4 v = ((const float4*)(p + row*SS))[tid];
    float mx = blk_max(fmaxf(fmaxf(v.x, v.y), fmaxf(v.z, v.w)), red, tid);
    v.x = expf(v.x - mx); v.y = expf(v.y - mx); v.z = expf(v.z - mx); v.w = expf(v.w - mx);
    float inv = 1.f / blk_sum(v.x + v.y + v.z + v.w, red, tid);
    v.x *= inv; v.y *= inv; v.z *= inv; v.w *= inv;
    unsigned h0, l0, h1, l1;
    split2w(v.x, v.y, h0, l0); split2w(v.z, v.w, h1, l1);
    ((uint2*)(oh + row*SS))[tid] = make_uint2(h0, h1);
    ((uint2*)(ol + row*SS))[tid] = make_uint2(l0, l1);
}
__global__ void ln_k(const float* __restrict__ resid, const float* __restrict__ delta,
                     const float* __restrict__ g, const float* __restrict__ b,
                     float* __restrict__ out,
                     __nv_bfloat16* __restrict__ oh, __nv_bfloat16* __restrict__ ol) {
    long long t = blockIdx.x;
    int tid = threadIdx.x;                         // 256, HN=1024 -> 1 float4/thread
    __shared__ float red[8];
    float4 r = ((const float4*)(resid + t*HN))[tid];
    float4 d = ((const float4*)(delta + t*HN))[tid];
    float4 v = make_float4(r.x + d.x, r.y + d.y, r.z + d.z, r.w + d.w);
    float m = blk_sum(v.x + v.y + v.z + v.w, red, tid) * (1.0f/HN);
    float4 c = make_float4(v.x - m, v.y - m, v.z - m, v.w - m);
    float var = blk_sum(c.x*c.x + c.y*c.y + c.z*c.z + c.w*c.w, red, tid) * (1.0f/HN);
    float inv = rsqrtf(var + 1e-5f);
    float4 gg = ((const float4*)g)[tid];
    float4 bb = ((const float4*)b)[tid];
    float4 o = make_float4(c.x*inv*gg.x + bb.x, c.y*inv*gg.y + bb.y,
                           c.z*inv*gg.z + bb.z, c.w*inv*gg.w + bb.w);
    ((float4*)(out + t*HN))[tid] = o;
    unsigned h0, l0, h1, l1;
    split2w(o.x, o.y, h0, l0); split2w(o.z, o.w, h1, l1);
    ((uint2*)(oh + t*HN))[tid] = make_uint2(h0, h1);
    ((uint2*)(ol + t*HN))[tid] = make_uint2(l0, l1);
}
__global__ void gate_k(const float* __restrict__ x, const float* __restrict__ gw,
                       const float* __restrict__ gb, int* __restrict__ cnt,
                       int* __restrict__ toks) {
    int t = blockIdx.x;
    int tid = threadIdx.x;
    __shared__ float xs[HN];
    __shared__ float red[256];
    for (int i = tid; i < HN; i += 256) xs[i] = x[(long long)t*HN+i];
    __syncthreads();
    int e = tid & 7, g = tid >> 3;
    float p = 0.f;
    for (int j = g; j < HN; j += 32) p += xs[j]*gw[j*NE+e];
    red[tid] = p; __syncthreads();
    if (tid < 8) {
        float s = 0.f;
        for (int j = 0; j < 32; j++) s += red[j*8 + tid];
        red[tid] = s + gb[tid];
    }
    __syncthreads();
    if (tid == 0) {
        float l[NE];
        for (int i = 0; i < NE; i++) l[i] = red[i];
        int i1 = 0;
        for (int i = 1; i < NE; i++) if (l[i] > l[i1]) i1 = i;
        int i2 = (i1 == 0) ? 1 : 0;
        for (int i = 0; i < NE; i++) if (i != i1 && l[i] > l[i2]) i2 = i;
        int p1 = atomicAdd(&cnt[i1], 1); toks[i1*TK+p1] = t;
        int p2 = atomicAdd(&cnt[i2], 1); toks[i2*TK+p2] = t;
    }
}
__global__ void copysplit_k(float* __restrict__ dst, __nv_bfloat16* __restrict__ oh,
                            __nv_bfloat16* __restrict__ ol, const float* __restrict__ src,
                            long long n4) {
    long long i = (long long)blockIdx.x*blockDim.x + threadIdx.x;
    if (i >= n4) return;
    float4 v = ((const float4*)src)[i];
    ((float4*)dst)[i] = v;
    unsigned h0, l0, h1, l1;
    split2w(v.x, v.y, h0, l0); split2w(v.z, v.w, h1, l1);
    ((uint2*)oh)[i] = make_uint2(h0, h1);
    ((uint2*)ol)[i] = make_uint2(l0, l1);
}

// ================= launch =================
extern "C" void kernel_launch(void* const* d_in, const int* in_sizes, int n_in,
                              void* d_out, int out_size)
{
    const int*   ids   = (const int*)d_in[0];
    const float* emb   = (const float*)d_in[1];
    const float* qkvw  = (const float*)d_in[2];
    const float* qkvb  = (const float*)d_in[3];
    const float* outw  = (const float*)d_in[4];
    const float* outb  = (const float*)d_in[5];
    const float* ln1g  = (const float*)d_in[6];
    const float* ln1b  = (const float*)d_in[7];
    const float* ffw1  = (const float*)d_in[8];
    const float* ffb1  = (const float*)d_in[9];
    const float* ffw2  = (const float*)d_in[10];
    const float* ffb2  = (const float*)d_in[11];
    const float* ln2g  = (const float*)d_in[12];
    const float* ln2b  = (const float*)d_in[13];
    const float* gw    = (const float*)d_in[14];
    const float* gb    = (const float*)d_in[15];
    const float* ew1   = (const float*)d_in[16];
    const float* eb1   = (const float*)d_in[17];
    const float* ew2   = (const float*)d_in[18];
    const float* eb2   = (const float*)d_in[19];
    const float* lmw   = (const float*)d_in[20];
    const float* lmb   = (const float*)d_in[21];
    float* out = (float*)d_out;

    float *x, *t1, *big, *sc; int *cnt, *tok;
    __nv_bfloat16 *wh, *wl, *vth, *vtl, *xh, *xl, *bh, *bl, *ph, *pl, *ehh, *ehl, *t1h, *t1l;
    cudaGetSymbolAddress((void**)&x,   g_x);
    cudaGetSymbolAddress((void**)&t1,  g_t1);
    cudaGetSymbolAddress((void**)&big, g_big);
    cudaGetSymbolAddress((void**)&sc,  g_sc);
    cudaGetSymbolAddress((void**)&cnt, g_cnt);
    cudaGetSymbolAddress((void**)&tok, g_tok);
    cudaGetSymbolAddress((void**)&wh,  g_wh);
    cudaGetSymbolAddress((void**)&wl,  g_wl);
    cudaGetSymbolAddress((void**)&vth, g_vth);
    cudaGetSymbolAddress((void**)&vtl, g_vtl);
    cudaGetSymbolAddress((void**)&xh,  g_xh);
    cudaGetSymbolAddress((void**)&xl,  g_xl);
    cudaGetSymbolAddress((void**)&bh,  g_bh);
    cudaGetSymbolAddress((void**)&bl,  g_bl);
    cudaGetSymbolAddress((void**)&ph,  g_ph);
    cudaGetSymbolAddress((void**)&pl,  g_pl);
    cudaGetSymbolAddress((void**)&ehh, g_ehh);
    cudaGetSymbolAddress((void**)&ehl, g_ehl);
    cudaGetSymbolAddress((void**)&t1h, g_t1h);
    cudaGetSymbolAddress((void**)&t1l, g_t1l);

    cudaFuncSetAttribute(tc_k<0,false,false,true, true, false>, cudaFuncAttributeMaxDynamicSharedMemorySize, SMEMB);
    cudaFuncSetAttribute(tc_k<0,false,false,false,true, false>, cudaFuncAttributeMaxDynamicSharedMemorySize, SMEMB);
    cudaFuncSetAttribute(tc_k<0,false,false,true, false,false>, cudaFuncAttributeMaxDynamicSharedMemorySize, SMEMB);
    cudaFuncSetAttribute(tc_k<1,false,false,true, false,false>, cudaFuncAttributeMaxDynamicSharedMemorySize, SMEMB);
    cudaFuncSetAttribute(tc_k<2,true, false,true, false,false>, cudaFuncAttributeMaxDynamicSharedMemorySize, SMEMB);
    cudaFuncSetAttribute(tc_k<0,false,true, false,false,false>, cudaFuncAttributeMaxDynamicSharedMemorySize, SMEMB);
    cudaFuncSetAttribute(tc_k<0,false,false,false,true, true >, cudaFuncAttributeMaxDynamicSharedMemorySize, SMEMB);

    const long long Z0 = 0;

    // ---- weight pre-split ----
    split_k<<<(unsigned)(((long long)NL*3*HN*HN + 255)/256), 256>>>(qkvw, wh + OFF_QKV, wl + OFF_QKV, (long long)NL*3*HN*HN);
    split_k<<<(unsigned)(((long long)NL*HN*HN + 255)/256), 256>>>(outw, wh + OFF_OUT, wl + OFF_OUT, (long long)NL*HN*HN);
    transsplit_k<<<dim3(FFD/32, HN/32, NL), 256>>>(ffw1, FFD, wh + OFF_FF1, wl + OFF_FF1,
        HN, FFD, (long long)HN*FFD, Z0, (long long)HN*FFD, Z0, 1);
    transsplit_k<<<dim3(HN/32, FFD/32, NL), 256>>>(ffw2, HN, wh + OFF_FF2, wl + OFF_FF2,
        FFD, HN, (long long)FFD*HN, Z0, (long long)FFD*HN, Z0, 1);
    transsplit_k<<<dim3(EHD/32, HN/32, NL*NE), 256>>>(ew1, EHD, wh + OFF_E1, wl + OFF_E1,
        HN, EHD, (long long)HN*EHD, Z0, (long long)HN*EHD, Z0, 1);
    transsplit_k<<<dim3(HN/32, EHD/32, NL*NE), 256>>>(ew2, HN, wh + OFF_E2, wl + OFF_E2,
        EHD, HN, (long long)EHD*HN, Z0, (long long)EHD*HN, Z0, 1);
    transsplit_k<<<dim3(VS/32, HN/32, 1), 256>>>(lmw, VS, wh + OFF_LM, wl + OFF_LM,
        HN, VS, Z0, Z0, Z0, Z0, 1);

    embed_k<<<TK, 256>>>(ids, emb, x, xh, xl);

    for (int l = 0; l < NL; l++) {
        // qkv = x @ Wqkv^T + b  -> big fp32 + bh/bl
        tc_k<0,false,false,true,true,false><<<dim3(3*HN/BN, TK/BM, 1), 512, SMEMB>>>(
            xh, xl, wh + OFF_QKV + (long long)l*3*HN*HN, wl + OFF_QKV + (long long)l*3*HN*HN,
            qkvb + (long long)l*3*HN, big, bh, bl, TK, 3*HN, HN, HN, HN, 3*HN,
            Z0,Z0,Z0,Z0,Z0,Z0,Z0, 0, 1.f, nullptr, nullptr);

        // V^T split per (b,h)
        transsplit_k<<<dim3(HDD/32, SS/32, BB*NHD), 256>>>(
            big + 2*HN, 3*HN, vth, vtl, SS, HDD,
            (long long)SS*3*HN, (long long)HDD,
            (long long)NHD*HDD*SS, (long long)HDD*SS, NHD);

        // scores = Q @ K^T / 16 -> sc fp32
        tc_k<0,false,false,false,true,false><<<dim3(SS/BN, SS/BM, BB*NHD), 512, SMEMB>>>(
            bh, bl, bh + HN, bl + HN, nullptr, sc, nullptr, nullptr,
            SS, SS, HDD, 3*HN, 3*HN, SS,
            (long long)SS*3*HN, (long long)HDD,
            (long long)SS*3*HN, (long long)HDD,
            (long long)NHD*SS*SS, (long long)SS*SS, Z0, NHD,
            0.0625f, nullptr, nullptr);

        softmax_k<<<BB*NHD*SS, 256>>>(sc, ph, pl);

        // ao = probs @ V -> t1h/t1l
        tc_k<0,false,false,true,false,false><<<dim3(HDD/BN, SS/BM, BB*NHD), 512, SMEMB>>>(
            ph, pl, vth, vtl, nullptr, nullptr, t1h, t1l,
            SS, HDD, SS, SS, SS, HN,
            (long long)NHD*SS*SS, (long long)SS*SS,
            (long long)NHD*HDD*SS, (long long)HDD*SS,
            (long long)SS*HN, (long long)HDD, Z0, NHD,
            1.f, nullptr, nullptr);

        // proj = ao @ Wout^T + b -> big fp32
        tc_k<0,false,false,false,true,false><<<dim3(HN/BN, TK/BM, 1), 512, SMEMB>>>(
            t1h, t1l, wh + OFF_OUT + (long long)l*HN*HN, wl + OFF_OUT + (long long)l*HN*HN,
            outb + (long long)l*HN, big, nullptr, nullptr, TK, HN, HN, HN, HN, HN,
            Z0,Z0,Z0,Z0,Z0,Z0,Z0, 0, 1.f, nullptr, nullptr);

        ln_k<<<TK,256>>>(x, big, ln1g + (long long)l*HN, ln1b + (long long)l*HN, x, xh, xl);

        // ffn
        tc_k<1,false,false,true,false,false><<<dim3(FFD/BN, TK/BM, 1), 512, SMEMB>>>(
            xh, xl, wh + OFF_FF1 + (long long)l*HN*FFD, wl + OFF_FF1 + (long long)l*HN*FFD,
            ffb1 + (long long)l*FFD, nullptr, bh, bl, TK, FFD, HN, HN, HN, FFD,
            Z0,Z0,Z0,Z0,Z0,Z0,Z0, 0, 1.f, nullptr, nullptr);
        tc_k<0,false,false,false,true,false><<<dim3(HN/BN, TK/BM, 1), 512, SMEMB>>>(
            bh, bl, wh + OFF_FF2 + (long long)l*FFD*HN, wl + OFF_FF2 + (long long)l*FFD*HN,
            ffb2 + (long long)l*HN, t1, nullptr, nullptr, TK, HN, FFD, FFD, FFD, HN,
            Z0,Z0,Z0,Z0,Z0,Z0,Z0, 0, 1.f, nullptr, nullptr);

        ln_k<<<TK,256>>>(x, t1, ln2g + (long long)l*HN, ln2b + (long long)l*HN, x, xh, xl);

        // MoE
        cudaMemsetAsync(cnt, 0, NE*sizeof(int));
        gate_k<<<TK,256>>>(x, gw + (long long)l*HN*NE, gb + (long long)l*NE, cnt, tok);
        cudaMemsetAsync(t1, 0, (size_t)TK*HN*sizeof(float));

        // up: ehh/ehl[e] = relu(x[gather] @ W1_e + b1_e)
        tc_k<2,true,false,true,false,false><<<dim3(EHD/BN, TK/BM, NE), 512, SMEMB>>>(
            xh, xl, wh + OFF_E1 + (long long)l*NE*HN*EHD, wl + OFF_E1 + (long long)l*NE*HN*EHD,
            eb1 + (long long)l*NE*EHD, nullptr, ehh, ehl, TK, EHD, HN, HN, HN, EHD,
            Z0, Z0, (long long)EHD*HN, Z0, (long long)TK*EHD, Z0, (long long)EHD, 1,
            1.f, tok, cnt);
        // down: t1[token] += eh[e] @ W2_e + b2_e  (atomic scatter)
        tc_k<0,false,true,false,false,false><<<dim3(HN/BN, TK/BM, NE), 512, SMEMB>>>(
            ehh, ehl, wh + OFF_E2 + (long long)l*NE*EHD*HN, wl + OFF_E2 + (long long)l*NE*EHD*HN,
            eb2 + (long long)l*NE*HN, t1, nullptr, nullptr, TK, HN, EHD, EHD, EHD, HN,
            (long long)TK*EHD, Z0, (long long)HN*EHD, Z0, Z0, Z0, (long long)HN, 1,
            1.f, tok, cnt);

        copysplit_k<<<(TK*HN/4)/256, 256>>>(x, xh, xl, t1, (long long)TK*HN/4);
    }

    // lm head: M-inner rasterization (B = 131MB > L2)
    tc_k<0,false,false,false,true,true><<<dim3(TK/BM, VS/BN, 1), 512, SMEMB>>>(
        xh, xl, wh + OFF_LM, wl + OFF_LM, lmb, out, nullptr, nullptr,
        TK, VS, HN, HN, HN, VS,
        Z0,Z0,Z0,Z0,Z0,Z0,Z0, 0, 1.f, nullptr, nullptr);
}

// round 12
// speedup vs baseline: 3.0902x; 1.0347x over previous
#include <cuda_runtime.h>
#include <cuda_bf16.h>
#include <math.h>

// ---------------- problem constants ----------------
#define TK   4096
#define HN   1024
#define NHD  4
#define HDD  256
#define BB   4
#define SS   1024
#define FFD  4096
#define NE   8
#define EHD  2048
#define VS   32000
#define NL   2

// ---------------- split-weight offsets (elements) ----------------
#define OFF_QKV 0LL
#define OFF_OUT  (OFF_QKV + (long long)NL*3*HN*HN)
#define OFF_FF1  (OFF_OUT + (long long)NL*HN*HN)
#define OFF_FF2  (OFF_FF1 + (long long)NL*HN*FFD)
#define OFF_E1   (OFF_FF2 + (long long)NL*FFD*HN)
#define OFF_E2   (OFF_E1  + (long long)NL*NE*HN*EHD)
#define OFF_LM   (OFF_E2  + (long long)NL*NE*EHD*HN)
#define TOTW     (OFF_LM  + (long long)HN*VS)

// ---------------- scratch ----------------
__device__ float g_x  [(size_t)TK*HN];
__device__ float g_t1 [(size_t)TK*HN];
__device__ float g_big[(size_t)TK*FFD];
__device__ float g_sc [(size_t)BB*NHD*SS*SS];
__device__ int   g_cnt[NE];
__device__ int   g_tok[NE*TK];
__device__ __nv_bfloat16 g_wh[TOTW];
__device__ __nv_bfloat16 g_wl[TOTW];
__device__ __nv_bfloat16 g_vth[(size_t)BB*NHD*HDD*SS];
__device__ __nv_bfloat16 g_vtl[(size_t)BB*NHD*HDD*SS];
// split activations
__device__ __nv_bfloat16 g_xh [(size_t)TK*HN];
__device__ __nv_bfloat16 g_xl [(size_t)TK*HN];
__device__ __nv_bfloat16 g_bh [(size_t)TK*FFD];
__device__ __nv_bfloat16 g_bl [(size_t)TK*FFD];
__device__ __nv_bfloat16 g_ph [(size_t)BB*NHD*SS*SS];
__device__ __nv_bfloat16 g_pl [(size_t)BB*NHD*SS*SS];
__device__ __nv_bfloat16 g_ehh[(size_t)NE*TK*EHD];
__device__ __nv_bfloat16 g_ehl[(size_t)NE*TK*EHD];
__device__ __nv_bfloat16 g_t1h[(size_t)TK*HN];
__device__ __nv_bfloat16 g_t1l[(size_t)TK*HN];

// ================= helpers =================
__device__ __forceinline__ unsigned smem_u32(const void* p){
    unsigned a;
    asm("{ .reg .u64 t; cvta.to.shared.u64 t, %1; cvt.u32.u64 %0, t; }" : "=r"(a) : "l"(p));
    return a;
}
__device__ __forceinline__ void split1(float v, __nv_bfloat16& h, __nv_bfloat16& l) {
    h = __float2bfloat16(v);
    l = __float2bfloat16(v - __bfloat162float(h));
}
__device__ __forceinline__ void split2w(float v0, float v1, unsigned& hw, unsigned& lw) {
    __nv_bfloat16 h0, l0, h1, l1;
    split1(v0, h0, l0); split1(v1, h1, l1);
    hw = (unsigned)__bfloat16_as_ushort(h0) | ((unsigned)__bfloat16_as_ushort(h1) << 16);
    lw = (unsigned)__bfloat16_as_ushort(l0) | ((unsigned)__bfloat16_as_ushort(l1) << 16);
}

#define LDSM_X4(r0, r1, r2, r3, a) \
    asm volatile("ldmatrix.sync.aligned.m8n8.x4.shared.b16 {%0,%1,%2,%3}, [%4];" \
                 : "=r"(r0), "=r"(r1), "=r"(r2), "=r"(r3) : "r"(a))
#define MMA16816(d, a, b) \
    asm volatile("mma.sync.aligned.m16n8k16.row.col.f32.bf16.bf16.f32 " \
                 "{%0,%1,%2,%3}, {%4,%5,%6,%7}, {%8,%9}, {%0,%1,%2,%3};" \
                 : "+f"((d)[0]), "+f"((d)[1]), "+f"((d)[2]), "+f"((d)[3]) \
                 : "r"((a)[0]), "r"((a)[1]), "r"((a)[2]), "r"((a)[3]), \
                   "r"((b)[0]), "r"((b)[1]))
#define CP_ASYNC16(sa, gp) \
    asm volatile("cp.async.cg.shared.global [%0], [%1], 16;" :: "r"(sa), "l"(gp) : "memory")
#define CP_COMMIT() asm volatile("cp.async.commit_group;" ::: "memory")
#define CP_WAIT1()  asm volatile("cp.async.wait_group 1;" ::: "memory")
#define CP_WAIT0()  asm volatile("cp.async.wait_group 0;" ::: "memory")

// ================= bf16x3 MMA GEMM (cp.async 3-stage) =================
#define BM 128
#define BN 256
#define KC 32
#define ROWB 80
#define RG_AL 10240
#define RG_BH 20480
#define RG_BL 40960
#define STGB  61440
#define NSTG  3
#define SMEMB (NSTG*STGB)

template<int ACT, bool GATHER, bool SCATTER, bool OSPLIT, bool OF32, bool SWAP>
__global__ void __launch_bounds__(512, 1)
tc_k(const __nv_bfloat16* __restrict__ Ah, const __nv_bfloat16* __restrict__ Al,
     const __nv_bfloat16* __restrict__ Bh, const __nv_bfloat16* __restrict__ Bl,
     const float* __restrict__ bias,
     float* __restrict__ C, __nv_bfloat16* __restrict__ Ch, __nv_bfloat16* __restrict__ Cl,
     int M, int N, int Kd, int lda, int ldb, int ldc,
     long long sAb, long long sAh_, long long sBb, long long sBh_,
     long long sCb, long long sCh_, long long sBias, int nh, float alpha,
     const int* __restrict__ ridx, const int* __restrict__ cptr)
{
    if (nh > 0) {
        int z = blockIdx.z, zb = z / nh, zh = z % nh;
        long long ao = zb*sAb + zh*sAh_;
        Ah += ao; Al += ao;
        long long bo = zb*sBb + zh*sBh_;
        Bh += bo; Bl += bo;
        long long co = zb*sCb + zh*sCh_;
        if (OF32 || SCATTER) C += co;
        if (OSPLIT) { Ch += co; Cl += co; }
        if (bias) bias += zb*sBias;
        if (GATHER || SCATTER) ridx += (long long)zb*TK;
        if (cptr) cptr += zb;
    }
    if (cptr) M = *cptr;
    // SWAP: M-inner rasterization (consecutive CTAs share the B tile) for
    // GEMMs whose B exceeds L2 (LM head).
    int m0 = SWAP ? blockIdx.x*BM : blockIdx.y*BM;
    int n0 = SWAP ? blockIdx.y*BN : blockIdx.x*BN;
    if (m0 >= M) return;

    extern __shared__ char sm[];
    unsigned sb = smem_u32(sm);
    int tid = threadIdx.x, lane = tid & 31, wid = tid >> 5;
    int wm = wid & 1, wn = wid >> 1;       // 2 x 8 warp grid; warp tile 64x32

    float acc[4][4][4];
#pragma unroll
    for (int i = 0; i < 4; i++)
#pragma unroll
        for (int j = 0; j < 4; j++)
#pragma unroll
            for (int e = 0; e < 4; e++) acc[i][j][e] = 0.f;

    // ---- load mapping: 512 threads; row = tid>>2 (0..127), 16B chunk = tid&3 ----
    int lr = tid >> 2, lc = tid & 3;
    long long arow;
    { int gm = m0 + lr; if (gm >= M) gm = M - 1;
      arow = GATHER ? (long long)ridx[gm] : (long long)gm; }
    const __nv_bfloat16* pAh  = Ah + arow*lda + lc*8;
    const __nv_bfloat16* pAl  = Al + arow*lda + lc*8;
    const __nv_bfloat16* pBh0 = Bh + (long long)(n0 + lr)*ldb + lc*8;
    const __nv_bfloat16* pBl0 = Bl + (long long)(n0 + lr)*ldb + lc*8;
    const __nv_bfloat16* pBh1 = pBh0 + (long long)128*ldb;
    const __nv_bfloat16* pBl1 = pBl0 + (long long)128*ldb;
    unsigned offR = (unsigned)lr*ROWB + (unsigned)lc*16;

    int NC = Kd / KC;

    auto issue = [&](int s) {
        unsigned base = sb + (unsigned)(s % NSTG)*STGB;
        int k0 = s*KC;
        CP_ASYNC16(base + offR,                 pAh  + k0);
        CP_ASYNC16(base + RG_AL + offR,         pAl  + k0);
        CP_ASYNC16(base + RG_BH + offR,         pBh0 + k0);
        CP_ASYNC16(base + RG_BH + 10240 + offR, pBh1 + k0);
        CP_ASYNC16(base + RG_BL + offR,         pBl0 + k0);
        CP_ASYNC16(base + RG_BL + 10240 + offR, pBl1 + k0);
        CP_COMMIT();
    };

    issue(0);
    if (NC > 1) issue(1);

    unsigned aoff = (unsigned)(lane & 15)*ROWB + (unsigned)(lane >> 4)*16;
    // paired-B ldmatrix x4: lanes 0-15 -> tile nt (k-lo/k-hi), lanes 16-31 -> tile nt+1
    unsigned boff = (unsigned)(lane & 7)*ROWB + (unsigned)((lane >> 3) & 1)*16
                  + (unsigned)(lane >> 4)*(8*ROWB);

    for (int i = 0; i < NC; i++) {
        if (i + 1 < NC) { CP_WAIT1(); } else { CP_WAIT0(); }
        __syncthreads();
        if (i + 2 < NC) issue(i + 2);

        unsigned st = sb + (unsigned)(i % NSTG)*STGB;
        unsigned abase = st + (unsigned)(wm*64)*ROWB;
        unsigned bbase = st + RG_BH + (unsigned)(wn*32)*ROWB;
#pragma unroll
        for (int ks = 0; ks < 2; ks++) {
            unsigned ah[4][4], al[4][4], bh[4][2], bl[4][2];
#pragma unroll
            for (int mt = 0; mt < 4; mt++) {
                unsigned ad = abase + (unsigned)(mt*16)*ROWB + aoff + ks*32;
                LDSM_X4(ah[mt][0], ah[mt][1], ah[mt][2], ah[mt][3], ad);
                LDSM_X4(al[mt][0], al[mt][1], al[mt][2], al[mt][3], ad + RG_AL);
            }
#pragma unroll
            for (int nt = 0; nt < 4; nt += 2) {
                unsigned bd = bbase + (unsigned)(nt*8)*ROWB + boff + ks*32;
                LDSM_X4(bh[nt][0], bh[nt][1], bh[nt+1][0], bh[nt+1][1], bd);
                LDSM_X4(bl[nt][0], bl[nt][1], bl[nt+1][0], bl[nt+1][1], bd + (RG_BL - RG_BH));
            }
#pragma unroll
            for (int mt = 0; mt < 4; mt++)
#pragma unroll
                for (int nt = 0; nt < 4; nt++) {
                    MMA16816(acc[mt][nt], ah[mt], bh[nt]);
                    MMA16816(acc[mt][nt], ah[mt], bl[nt]);
                    MMA16816(acc[mt][nt], al[mt], bh[nt]);
                }
        }
    }

    // ---- epilogue ----
#pragma unroll
    for (int mt = 0; mt < 4; mt++) {
#pragma unroll
        for (int half = 0; half < 2; half++) {
            int gm = m0 + wm*64 + mt*16 + (lane >> 2) + half*8;
            if (gm >= M) continue;
            long long crow = SCATTER ? (long long)ridx[gm]*ldc : (long long)gm*ldc;
#pragma unroll
            for (int nt = 0; nt < 4; nt++) {
                int gn = n0 + wn*32 + nt*8 + (lane & 3)*2;
                float v0 = acc[mt][nt][half*2 + 0] * alpha;
                float v1 = acc[mt][nt][half*2 + 1] * alpha;
                if (bias) { v0 += bias[gn]; v1 += bias[gn+1]; }
                if (ACT == 1) {
                    v0 = 0.5f*v0*(1.0f + erff(v0*0.7071067811865475f));
                    v1 = 0.5f*v1*(1.0f + erff(v1*0.7071067811865475f));
                } else if (ACT == 2) {
                    v0 = v0 > 0.f ? v0 : 0.f;
                    v1 = v1 > 0.f ? v1 : 0.f;
                }
                if (SCATTER) {
                    atomicAdd(C + crow + gn,     v0);
                    atomicAdd(C + crow + gn + 1, v1);
                } else {
                    if (OF32) *(float2*)(C + crow + gn) = make_float2(v0, v1);
                    if (OSPLIT) {
                        unsigned hw, lw; split2w(v0, v1, hw, lw);
                        *(unsigned*)(Ch + crow + gn) = hw;
                        *(unsigned*)(Cl + crow + gn) = lw;
                    }
                }
            }
        }
    }
}

// ================= weight prep (bandwidth-optimized) =================
__global__ void split_k(const float* __restrict__ W, __nv_bfloat16* __restrict__ hi,
                        __nv_bfloat16* __restrict__ lo, long long n4) {
    long long i = (long long)blockIdx.x*256 + threadIdx.x;
    if (i >= n4) return;
    float4 v = ((const float4*)W)[i];
    unsigned h0, l0, h1, l1;
    split2w(v.x, v.y, h0, l0); split2w(v.z, v.w, h1, l1);
    ((uint2*)hi)[i] = make_uint2(h0, h1);
    ((uint2*)lo)[i] = make_uint2(l0, l1);
}
// out[N,K] = split(W[K,N])  (W row stride ldw), batched via z=(zb,zh)
// 64x64 tiles, float4 loads, uint2 (4xbf16) coalesced writes.
__global__ void transsplit_k(const float* __restrict__ W, int ldw,
                             __nv_bfloat16* __restrict__ hi, __nv_bfloat16* __restrict__ lo,
                             int Kd, int Nd, long long sWb, long long sWh,
                             long long sOb, long long sOh, int nhz) {
    int z = blockIdx.z, zb = z / nhz, zh = z % nhz;
    W += zb*sWb + zh*sWh; hi += zb*sOb + zh*sOh; lo += zb*sOb + zh*sOh;
    __shared__ float ts[64][65];
    int n0 = blockIdx.x*64, k0 = blockIdx.y*64;
    int tid = threadIdx.x;                     // 256
    // load: 16 rows x 16 float4 (=64 floats) per pass, 4 passes -> full 64x64
    {
        int rr = tid >> 4, c4 = (tid & 15)*4;
#pragma unroll
        for (int it = 0; it < 4; it++) {
            int r = rr + it*16;
            float4 v = *(const float4*)(W + (long long)(k0 + r)*ldw + n0 + c4);
            ts[r][c4+0] = v.x; ts[r][c4+1] = v.y; ts[r][c4+2] = v.z; ts[r][c4+3] = v.w;
        }
    }
    __syncthreads();
    int nb = tid >> 4, kq = (tid & 15)*4;      // 16 n-rows per pass, 4 k per thread
#pragma unroll
    for (int it = 0; it < 4; it++) {
        int nn = nb + it*16;
        float a = ts[kq+0][nn], b = ts[kq+1][nn];
        float c = ts[kq+2][nn], d = ts[kq+3][nn];
        unsigned h0, l0, h1, l1;
        split2w(a, b, h0, l0); split2w(c, d, h1, l1);
        long long o = (long long)(n0 + nn)*Kd + k0 + kq;
        *(uint2*)(hi + o) = make_uint2(h0, h1);
        *(uint2*)(lo + o) = make_uint2(l0, l1);
    }
}

// ================= block reduce helpers (smem broadcast) =================
__device__ __forceinline__ float blk_sum(float v, float* red, int tid) {
#pragma unroll
    for (int o = 16; o > 0; o >>= 1) v += __shfl_xor_sync(0xffffffffu, v, o);
    if ((tid & 31) == 0) red[tid >> 5] = v;
    __syncthreads();
    if (tid < 32) {
        float s = (tid < 8) ? red[tid] : 0.f;
#pragma unroll
        for (int o = 4; o > 0; o >>= 1) s += __shfl_xor_sync(0xffffffffu, s, o);
        if (tid == 0) red[0] = s;
    }
    __syncthreads();
    float r = red[0];
    __syncthreads();
    return r;
}
__device__ __forceinline__ float blk_max(float v, float* red, int tid) {
#pragma unroll
    for (int o = 16; o > 0; o >>= 1) v = fmaxf(v, __shfl_xor_sync(0xffffffffu, v, o));
    if ((tid & 31) == 0) red[tid >> 5] = v;
    __syncthreads();
    if (tid < 32) {
        float s = (tid < 8) ? red[tid] : -1e30f;
#pragma unroll
        for (int o = 4; o > 0; o >>= 1) s = fmaxf(s, __shfl_xor_sync(0xffffffffu, s, o));
        if (tid == 0) red[0] = s;
    }
    __syncthreads();
    float r = red[0];
    __syncthreads();
    return r;
}

// ================= misc kernels (vectorized) =================
__global__ void embed_k(const int* __restrict__ ids, const float* __restrict__ emb,
                        float* __restrict__ out,
                        __nv_bfloat16* __restrict__ oh, __nv_bfloat16* __restrict__ ol) {
    long long t = blockIdx.x;
    int tid = threadIdx.x;                         // 256
    float4 v = ((const float4*)(emb + (size_t)ids[t]*HN))[tid];
    ((float4*)(out + t*HN))[tid] = v;
    unsigned h0, l0, h1, l1;
    split2w(v.x, v.y, h0, l0); split2w(v.z, v.w, h1, l1);
    ((uint2*)(oh + t*HN))[tid] = make_uint2(h0, h1);
    ((uint2*)(ol + t*HN))[tid] = make_uint2(l0, l1);
}
__global__ void softmax_k(const float* __restrict__ p,
                          __nv_bfloat16* __restrict__ oh, __nv_bfloat16* __restrict__ ol) {
    long long row = blockIdx.x;
    int tid = threadIdx.x;                         // 256, SS=1024 -> 1 float4/thread
    __shared__ float red[8];
    float4 v = ((const float4*)(p + row*SS))[tid];
    float mx = blk_max(fmaxf(fmaxf(v.x, v.y), fmaxf(v.z, v.w)), red, tid);
    v.x = expf(v.x - mx); v.y = expf(v.y - mx); v.z = expf(v.z - mx); v.w = expf(v.w - mx);
    float inv = 1.f / blk_sum(v.x + v.y + v.z + v.w, red, tid);
    v.x *= inv; v.y *= inv; v.z *= inv; v.w *= inv;
    unsigned h0, l0, h1, l1;
    split2w(v.x, v.y, h0, l0); split2w(v.z, v.w, h1, l1);
    ((uint2*)(oh + row*SS))[tid] = make_uint2(h0, h1);
    ((uint2*)(ol + row*SS))[tid] = make_uint2(l0, l1);
}
__global__ void ln_k(const float* __restrict__ resid, const float* __restrict__ delta,
                     const float* __restrict__ g, const float* __restrict__ b,
                     float* __restrict__ out,
                     __nv_bfloat16* __restrict__ oh, __nv_bfloat16* __restrict__ ol) {
    long long t = blockIdx.x;
    int tid = threadIdx.x;                         // 256, HN=1024 -> 1 float4/thread
    __shared__ float red[8];
    float4 r = ((const float4*)(resid + t*HN))[tid];
    float4 d = ((const float4*)(delta + t*HN))[tid];
    float4 v = make_float4(r.x + d.x, r.y + d.y, r.z + d.z, r.w + d.w);
    float m = blk_sum(v.x + v.y + v.z + v.w, red, tid) * (1.0f/HN);
    float4 c = make_float4(v.x - m, v.y - m, v.z - m, v.w - m);
    float var = blk_sum(c.x*c.x + c.y*c.y + c.z*c.z + c.w*c.w, red, tid) * (1.0f/HN);
    float inv = rsqrtf(var + 1e-5f);
    float4 gg = ((const float4*)g)[tid];
    float4 bb = ((const float4*)b)[tid];
    float4 o = make_float4(c.x*inv*gg.x + bb.x, c.y*inv*gg.y + bb.y,
                           c.z*inv*gg.z + bb.z, c.w*inv*gg.w + bb.w);
    ((float4*)(out + t*HN))[tid] = o;
    unsigned h0, l0, h1, l1;
    split2w(o.x, o.y, h0, l0); split2w(o.z, o.w, h1, l1);
    ((uint2*)(oh + t*HN))[tid] = make_uint2(h0, h1);
    ((uint2*)(ol + t*HN))[tid] = make_uint2(l0, l1);
}
__global__ void gate_k(const float* __restrict__ x, const float* __restrict__ gw,
                       const float* __restrict__ gb, int* __restrict__ cnt,
                       int* __restrict__ toks) {
    int t = blockIdx.x;
    int tid = threadIdx.x;
    __shared__ float xs[HN];
    __shared__ float red[256];
    for (int i = tid; i < HN; i += 256) xs[i] = x[(long long)t*HN+i];
    __syncthreads();
    int e = tid & 7, g = tid >> 3;
    float p = 0.f;
    for (int j = g; j < HN; j += 32) p += xs[j]*gw[j*NE+e];
    red[tid] = p; __syncthreads();
    if (tid < 8) {
        float s = 0.f;
        for (int j = 0; j < 32; j++) s += red[j*8 + tid];
        red[tid] = s + gb[tid];
    }
    __syncthreads();
    if (tid == 0) {
        float l[NE];
        for (int i = 0; i < NE; i++) l[i] = red[i];
        int i1 = 0;
        for (int i = 1; i < NE; i++) if (l[i] > l[i1]) i1 = i;
        int i2 = (i1 == 0) ? 1 : 0;
        for (int i = 0; i < NE; i++) if (i != i1 && l[i] > l[i2]) i2 = i;
        int p1 = atomicAdd(&cnt[i1], 1); toks[i1*TK+p1] = t;
        int p2 = atomicAdd(&cnt[i2], 1); toks[i2*TK+p2] = t;
    }
}
__global__ void copysplit_k(float* __restrict__ dst, __nv_bfloat16* __restrict__ oh,
                            __nv_bfloat16* __restrict__ ol, const float* __restrict__ src,
                            long long n4) {
    long long i = (long long)blockIdx.x*blockDim.x + threadIdx.x;
    if (i >= n4) return;
    float4 v = ((const float4*)src)[i];
    ((float4*)dst)[i] = v;
    unsigned h0, l0, h1, l1;
    split2w(v.x, v.y, h0, l0); split2w(v.z, v.w, h1, l1);
    ((uint2*)oh)[i] = make_uint2(h0, h1);
    ((uint2*)ol)[i] = make_uint2(l0, l1);
}

// ================= launch =================
extern "C" void kernel_launch(void* const* d_in, const int* in_sizes, int n_in,
                              void* d_out, int out_size)
{
    const int*   ids   = (const int*)d_in[0];
    const float* emb   = (const float*)d_in[1];
    const float* qkvw  = (const float*)d_in[2];
    const float* qkvb  = (const float*)d_in[3];
    const float* outw  = (const float*)d_in[4];
    const float* outb  = (const float*)d_in[5];
    const float* ln1g  = (const float*)d_in[6];
    const float* ln1b  = (const float*)d_in[7];
    const float* ffw1  = (const float*)d_in[8];
    const float* ffb1  = (const float*)d_in[9];
    const float* ffw2  = (const float*)d_in[10];
    const float* ffb2  = (const float*)d_in[11];
    const float* ln2g  = (const float*)d_in[12];
    const float* ln2b  = (const float*)d_in[13];
    const float* gw    = (const float*)d_in[14];
    const float* gb    = (const float*)d_in[15];
    const float* ew1   = (const float*)d_in[16];
    const float* eb1   = (const float*)d_in[17];
    const float* ew2   = (const float*)d_in[18];
    const float* eb2   = (const float*)d_in[19];
    const float* lmw   = (const float*)d_in[20];
    const float* lmb   = (const float*)d_in[21];
    float* out = (float*)d_out;

    float *x, *t1, *big, *sc; int *cnt, *tok;
    __nv_bfloat16 *wh, *wl, *vth, *vtl, *xh, *xl, *bh, *bl, *ph, *pl, *ehh, *ehl, *t1h, *t1l;
    cudaGetSymbolAddress((void**)&x,   g_x);
    cudaGetSymbolAddress((void**)&t1,  g_t1);
    cudaGetSymbolAddress((void**)&big, g_big);
    cudaGetSymbolAddress((void**)&sc,  g_sc);
    cudaGetSymbolAddress((void**)&cnt, g_cnt);
    cudaGetSymbolAddress((void**)&tok, g_tok);
    cudaGetSymbolAddress((void**)&wh,  g_wh);
    cudaGetSymbolAddress((void**)&wl,  g_wl);
    cudaGetSymbolAddress((void**)&vth, g_vth);
    cudaGetSymbolAddress((void**)&vtl, g_vtl);
    cudaGetSymbolAddress((void**)&xh,  g_xh);
    cudaGetSymbolAddress((void**)&xl,  g_xl);
    cudaGetSymbolAddress((void**)&bh,  g_bh);
    cudaGetSymbolAddress((void**)&bl,  g_bl);
    cudaGetSymbolAddress((void**)&ph,  g_ph);
    cudaGetSymbolAddress((void**)&pl,  g_pl);
    cudaGetSymbolAddress((void**)&ehh, g_ehh);
    cudaGetSymbolAddress((void**)&ehl, g_ehl);
    cudaGetSymbolAddress((void**)&t1h, g_t1h);
    cudaGetSymbolAddress((void**)&t1l, g_t1l);

    cudaFuncSetAttribute(tc_k<0,false,false,true, true, false>, cudaFuncAttributeMaxDynamicSharedMemorySize, SMEMB);
    cudaFuncSetAttribute(tc_k<0,false,false,false,true, false>, cudaFuncAttributeMaxDynamicSharedMemorySize, SMEMB);
    cudaFuncSetAttribute(tc_k<0,false,false,true, false,false>, cudaFuncAttributeMaxDynamicSharedMemorySize, SMEMB);
    cudaFuncSetAttribute(tc_k<1,false,false,true, false,false>, cudaFuncAttributeMaxDynamicSharedMemorySize, SMEMB);
    cudaFuncSetAttribute(tc_k<2,true, false,true, false,false>, cudaFuncAttributeMaxDynamicSharedMemorySize, SMEMB);
    cudaFuncSetAttribute(tc_k<0,false,true, false,false,false>, cudaFuncAttributeMaxDynamicSharedMemorySize, SMEMB);
    cudaFuncSetAttribute(tc_k<0,false,false,false,true, true >, cudaFuncAttributeMaxDynamicSharedMemorySize, SMEMB);

    const long long Z0 = 0;

    // ---- weight pre-split ----
    split_k<<<(unsigned)(((long long)NL*3*HN*HN/4 + 255)/256), 256>>>(qkvw, wh + OFF_QKV, wl + OFF_QKV, (long long)NL*3*HN*HN/4);
    split_k<<<(unsigned)(((long long)NL*HN*HN/4 + 255)/256), 256>>>(outw, wh + OFF_OUT, wl + OFF_OUT, (long long)NL*HN*HN/4);
    transsplit_k<<<dim3(FFD/64, HN/64, NL), 256>>>(ffw1, FFD, wh + OFF_FF1, wl + OFF_FF1,
        HN, FFD, (long long)HN*FFD, Z0, (long long)HN*FFD, Z0, 1);
    transsplit_k<<<dim3(HN/64, FFD/64, NL), 256>>>(ffw2, HN, wh + OFF_FF2, wl + OFF_FF2,
        FFD, HN, (long long)FFD*HN, Z0, (long long)FFD*HN, Z0, 1);
    transsplit_k<<<dim3(EHD/64, HN/64, NL*NE), 256>>>(ew1, EHD, wh + OFF_E1, wl + OFF_E1,
        HN, EHD, (long long)HN*EHD, Z0, (long long)HN*EHD, Z0, 1);
    transsplit_k<<<dim3(HN/64, EHD/64, NL*NE), 256>>>(ew2, HN, wh + OFF_E2, wl + OFF_E2,
        EHD, HN, (long long)EHD*HN, Z0, (long long)EHD*HN, Z0, 1);
    transsplit_k<<<dim3(VS/64, HN/64, 1), 256>>>(lmw, VS, wh + OFF_LM, wl + OFF_LM,
        HN, VS, Z0, Z0, Z0, Z0, 1);

    embed_k<<<TK, 256>>>(ids, emb, x, xh, xl);

    for (int l = 0; l < NL; l++) {
        // qkv = x @ Wqkv^T + b  -> big fp32 + bh/bl
        tc_k<0,false,false,true,true,false><<<dim3(3*HN/BN, TK/BM, 1), 512, SMEMB>>>(
            xh, xl, wh + OFF_QKV + (long long)l*3*HN*HN, wl + OFF_QKV + (long long)l*3*HN*HN,
            qkvb + (long long)l*3*HN, big, bh, bl, TK, 3*HN, HN, HN, HN, 3*HN,
            Z0,Z0,Z0,Z0,Z0,Z0,Z0, 0, 1.f, nullptr, nullptr);

        // V^T split per (b,h)
        transsplit_k<<<dim3(HDD/64, SS/64, BB*NHD), 256>>>(
            big + 2*HN, 3*HN, vth, vtl, SS, HDD,
            (long long)SS*3*HN, (long long)HDD,
            (long long)NHD*HDD*SS, (long long)HDD*SS, NHD);

        // scores = Q @ K^T / 16 -> sc fp32
        tc_k<0,false,false,false,true,false><<<dim3(SS/BN, SS/BM, BB*NHD), 512, SMEMB>>>(
            bh, bl, bh + HN, bl + HN, nullptr, sc, nullptr, nullptr,
            SS, SS, HDD, 3*HN, 3*HN, SS,
            (long long)SS*3*HN, (long long)HDD,
            (long long)SS*3*HN, (long long)HDD,
            (long long)NHD*SS*SS, (long long)SS*SS, Z0, NHD,
            0.0625f, nullptr, nullptr);

        softmax_k<<<BB*NHD*SS, 256>>>(sc, ph, pl);

        // ao = probs @ V -> t1h/t1l
        tc_k<0,false,false,true,false,false><<<dim3(HDD/BN, SS/BM, BB*NHD), 512, SMEMB>>>(
            ph, pl, vth, vtl, nullptr, nullptr, t1h, t1l,
            SS, HDD, SS, SS, SS, HN,
            (long long)NHD*SS*SS, (long long)SS*SS,
            (long long)NHD*HDD*SS, (long long)HDD*SS,
            (long long)SS*HN, (long long)HDD, Z0, NHD,
            1.f, nullptr, nullptr);

        // proj = ao @ Wout^T + b -> big fp32
        tc_k<0,false,false,false,true,false><<<dim3(HN/BN, TK/BM, 1), 512, SMEMB>>>(
            t1h, t1l, wh + OFF_OUT + (long long)l*HN*HN, wl + OFF_OUT + (long long)l*HN*HN,
            outb + (long long)l*HN, big, nullptr, nullptr, TK, HN, HN, HN, HN, HN,
            Z0,Z0,Z0,Z0,Z0,Z0,Z0, 0, 1.f, nullptr, nullptr);

        ln_k<<<TK,256>>>(x, big, ln1g + (long long)l*HN, ln1b + (long long)l*HN, x, xh, xl);

        // ffn
        tc_k<1,false,false,true,false,false><<<dim3(FFD/BN, TK/BM, 1), 512, SMEMB>>>(
            xh, xl, wh + OFF_FF1 + (long long)l*HN*FFD, wl + OFF_FF1 + (long long)l*HN*FFD,
            ffb1 + (long long)l*FFD, nullptr, bh, bl, TK, FFD, HN, HN, HN, FFD,
            Z0,Z0,Z0,Z0,Z0,Z0,Z0, 0, 1.f, nullptr, nullptr);
        tc_k<0,false,false,false,true,false><<<dim3(HN/BN, TK/BM, 1), 512, SMEMB>>>(
            bh, bl, wh + OFF_FF2 + (long long)l*FFD*HN, wl + OFF_FF2 + (long long)l*FFD*HN,
            ffb2 + (long long)l*HN, t1, nullptr, nullptr, TK, HN, FFD, FFD, FFD, HN,
            Z0,Z0,Z0,Z0,Z0,Z0,Z0, 0, 1.f, nullptr, nullptr);

        ln_k<<<TK,256>>>(x, t1, ln2g + (long long)l*HN, ln2b + (long long)l*HN, x, xh, xl);

        // MoE
        cudaMemsetAsync(cnt, 0, NE*sizeof(int));
        gate_k<<<TK,256>>>(x, gw + (long long)l*HN*NE, gb + (long long)l*NE, cnt, tok);
        cudaMemsetAsync(t1, 0, (size_t)TK*HN*sizeof(float));

        // up: ehh/ehl[e] = relu(x[gather] @ W1_e + b1_e)
        tc_k<2,true,false,true,false,false><<<dim3(EHD/BN, TK/BM, NE), 512, SMEMB>>>(
            xh, xl, wh + OFF_E1 + (long long)l*NE*HN*EHD, wl + OFF_E1 + (long long)l*NE*HN*EHD,
            eb1 + (long long)l*NE*EHD, nullptr, ehh, ehl, TK, EHD, HN, HN, HN, EHD,
            Z0, Z0, (long long)EHD*HN, Z0, (long long)TK*EHD, Z0, (long long)EHD, 1,
            1.f, tok, cnt);
        // down: t1[token] += eh[e] @ W2_e + b2_e  (atomic scatter)
        tc_k<0,false,true,false,false,false><<<dim3(HN/BN, TK/BM, NE), 512, SMEMB>>>(
            ehh, ehl, wh + OFF_E2 + (long long)l*NE*EHD*HN, wl + OFF_E2 + (long long)l*NE*EHD*HN,
            eb2 + (long long)l*NE*HN, t1, nullptr, nullptr, TK, HN, EHD, EHD, EHD, HN,
            (long long)TK*EHD, Z0, (long long)HN*EHD, Z0, Z0, Z0, (long long)HN, 1,
            1.f, tok, cnt);

        copysplit_k<<<(TK*HN/4)/256, 256>>>(x, xh, xl, t1, (long long)TK*HN/4);
    }

    // lm head: M-inner rasterization (B = 131MB > L2)
    tc_k<0,false,false,false,true,true><<<dim3(TK/BM, VS/BN, 1), 512, SMEMB>>>(
        xh, xl, wh + OFF_LM, wl + OFF_LM, lmb, out, nullptr, nullptr,
        TK, VS, HN, HN, HN, VS,
        Z0,Z0,Z0,Z0,Z0,Z0,Z0, 0, 1.f, nullptr, nullptr);
}

// round 13
// speedup vs baseline: 3.3956x; 1.0988x over previous
#include <cuda_runtime.h>
#include <cuda_bf16.h>
#include <cuda_fp16.h>
#include <math.h>

// ---------------- problem constants ----------------
#define TK   4096
#define HN   1024
#define NHD  4
#define HDD  256
#define BB   4
#define SS   1024
#define FFD  4096
#define NE   8
#define EHD  2048
#define VS   32000
#define NL   2

// ---------------- split-weight offsets (elements) ----------------
#define OFF_QKV 0LL
#define OFF_OUT  (OFF_QKV + (long long)NL*3*HN*HN)
#define OFF_FF1  (OFF_OUT + (long long)NL*HN*HN)
#define OFF_FF2  (OFF_FF1 + (long long)NL*HN*FFD)
#define OFF_E1   (OFF_FF2 + (long long)NL*FFD*HN)
#define OFF_E2   (OFF_E1  + (long long)NL*NE*HN*EHD)
#define TOTW     (OFF_E2  + (long long)NL*NE*EHD*HN)

// ---------------- scratch ----------------
__device__ float g_x  [(size_t)TK*HN];
__device__ float g_t1 [(size_t)TK*HN];
__device__ float g_big[(size_t)TK*FFD];
__device__ float g_sc [(size_t)BB*NHD*SS*SS];
__device__ int   g_cnt[NE];
__device__ int   g_tok[NE*TK];
__device__ __nv_bfloat16 g_wh[TOTW];
__device__ __nv_bfloat16 g_wl[TOTW];
__device__ __nv_bfloat16 g_vth[(size_t)BB*NHD*HDD*SS];
__device__ __nv_bfloat16 g_vtl[(size_t)BB*NHD*HDD*SS];
// split activations
__device__ __nv_bfloat16 g_xh [(size_t)TK*HN];
__device__ __nv_bfloat16 g_xl [(size_t)TK*HN];
__device__ __nv_bfloat16 g_bh [(size_t)TK*FFD];
__device__ __nv_bfloat16 g_bl [(size_t)TK*FFD];
__device__ __nv_bfloat16 g_ph [(size_t)BB*NHD*SS*SS];
__device__ __nv_bfloat16 g_pl [(size_t)BB*NHD*SS*SS];
__device__ __nv_bfloat16 g_ehh[(size_t)NE*TK*EHD];
__device__ __nv_bfloat16 g_ehl[(size_t)NE*TK*EHD];
__device__ __nv_bfloat16 g_t1h[(size_t)TK*HN];
__device__ __nv_bfloat16 g_t1l[(size_t)TK*HN];
// fp16 LM-head path
__device__ __half g_lmh[(size_t)HN*VS];
__device__ __half g_lml[(size_t)HN*VS];
__device__ __half g_xf [(size_t)TK*HN];

// ================= helpers =================
__device__ __forceinline__ unsigned smem_u32(const void* p){
    unsigned a;
    asm("{ .reg .u64 t; cvta.to.shared.u64 t, %1; cvt.u32.u64 %0, t; }" : "=r"(a) : "l"(p));
    return a;
}
__device__ __forceinline__ void split1(float v, __nv_bfloat16& h, __nv_bfloat16& l) {
    h = __float2bfloat16(v);
    l = __float2bfloat16(v - __bfloat162float(h));
}
__device__ __forceinline__ void split2w(float v0, float v1, unsigned& hw, unsigned& lw) {
    __nv_bfloat16 h0, l0, h1, l1;
    split1(v0, h0, l0); split1(v1, h1, l1);
    hw = (unsigned)__bfloat16_as_ushort(h0) | ((unsigned)__bfloat16_as_ushort(h1) << 16);
    lw = (unsigned)__bfloat16_as_ushort(l0) | ((unsigned)__bfloat16_as_ushort(l1) << 16);
}
__device__ __forceinline__ void split2wh(float v0, float v1, unsigned& hw, unsigned& lw) {
    __half h0 = __float2half(v0), h1 = __float2half(v1);
    __half l0 = __float2half(v0 - __half2float(h0));
    __half l1 = __float2half(v1 - __half2float(h1));
    hw = (unsigned)__half_as_ushort(h0) | ((unsigned)__half_as_ushort(h1) << 16);
    lw = (unsigned)__half_as_ushort(l0) | ((unsigned)__half_as_ushort(l1) << 16);
}

#define LDSM_X4(r0, r1, r2, r3, a) \
    asm volatile("ldmatrix.sync.aligned.m8n8.x4.shared.b16 {%0,%1,%2,%3}, [%4];" \
                 : "=r"(r0), "=r"(r1), "=r"(r2), "=r"(r3) : "r"(a))
#define MMA16816(d, a, b) \
    asm volatile("mma.sync.aligned.m16n8k16.row.col.f32.bf16.bf16.f32 " \
                 "{%0,%1,%2,%3}, {%4,%5,%6,%7}, {%8,%9}, {%0,%1,%2,%3};" \
                 : "+f"((d)[0]), "+f"((d)[1]), "+f"((d)[2]), "+f"((d)[3]) \
                 : "r"((a)[0]), "r"((a)[1]), "r"((a)[2]), "r"((a)[3]), \
                   "r"((b)[0]), "r"((b)[1]))
#define MMA16816H(d, a, b) \
    asm volatile("mma.sync.aligned.m16n8k16.row.col.f32.f16.f16.f32 " \
                 "{%0,%1,%2,%3}, {%4,%5,%6,%7}, {%8,%9}, {%0,%1,%2,%3};" \
                 : "+f"((d)[0]), "+f"((d)[1]), "+f"((d)[2]), "+f"((d)[3]) \
                 : "r"((a)[0]), "r"((a)[1]), "r"((a)[2]), "r"((a)[3]), \
                   "r"((b)[0]), "r"((b)[1]))
#define CP_ASYNC16(sa, gp) \
    asm volatile("cp.async.cg.shared.global [%0], [%1], 16;" :: "r"(sa), "l"(gp) : "memory")
#define CP_COMMIT() asm volatile("cp.async.commit_group;" ::: "memory")
#define CP_WAIT1()  asm volatile("cp.async.wait_group 1;" ::: "memory")
#define CP_WAIT0()  asm volatile("cp.async.wait_group 0;" ::: "memory")

// ================= bf16x3 / fp16x2 MMA GEMM (cp.async 3-stage) =================
#define BM 128
#define BN 256
#define KC 32
#define ROWB 80
#define RG_AL 10240
#define RG_BH 20480
#define RG_BL 40960
#define STGB  61440
#define NSTG  3
#define SMEMB (NSTG*STGB)

template<int ACT, bool GATHER, bool SCATTER, bool OSPLIT, bool OF32, bool SWAP, int TERMS>
__global__ void __launch_bounds__(512, 1)
tc_k(const __nv_bfloat16* __restrict__ Ah, const __nv_bfloat16* __restrict__ Al,
     const __nv_bfloat16* __restrict__ Bh, const __nv_bfloat16* __restrict__ Bl,
     const float* __restrict__ bias,
     float* __restrict__ C, __nv_bfloat16* __restrict__ Ch, __nv_bfloat16* __restrict__ Cl,
     int M, int N, int Kd, int lda, int ldb, int ldc,
     long long sAb, long long sAh_, long long sBb, long long sBh_,
     long long sCb, long long sCh_, long long sBias, int nh, float alpha,
     const int* __restrict__ ridx, const int* __restrict__ cptr)
{
    if (nh > 0) {
        int z = blockIdx.z, zb = z / nh, zh = z % nh;
        long long ao = zb*sAb + zh*sAh_;
        Ah += ao; Al += ao;
        long long bo = zb*sBb + zh*sBh_;
        Bh += bo; Bl += bo;
        long long co = zb*sCb + zh*sCh_;
        if (OF32 || SCATTER) C += co;
        if (OSPLIT) { Ch += co; Cl += co; }
        if (bias) bias += zb*sBias;
        if (GATHER || SCATTER) ridx += (long long)zb*TK;
        if (cptr) cptr += zb;
    }
    if (cptr) M = *cptr;
    int m0 = SWAP ? blockIdx.x*BM : blockIdx.y*BM;
    int n0 = SWAP ? blockIdx.y*BN : blockIdx.x*BN;
    if (m0 >= M) return;

    extern __shared__ char sm[];
    unsigned sb = smem_u32(sm);
    int tid = threadIdx.x, lane = tid & 31, wid = tid >> 5;
    int wm = wid & 1, wn = wid >> 1;       // 2 x 8 warp grid; warp tile 64x32

    float acc[4][4][4];
#pragma unroll
    for (int i = 0; i < 4; i++)
#pragma unroll
        for (int j = 0; j < 4; j++)
#pragma unroll
            for (int e = 0; e < 4; e++) acc[i][j][e] = 0.f;

    int lr = tid >> 2, lc = tid & 3;
    long long arow;
    { int gm = m0 + lr; if (gm >= M) gm = M - 1;
      arow = GATHER ? (long long)ridx[gm] : (long long)gm; }
    const __nv_bfloat16* pAh  = Ah + arow*lda + lc*8;
    const __nv_bfloat16* pAl  = Al + arow*lda + lc*8;
    const __nv_bfloat16* pBh0 = Bh + (long long)(n0 + lr)*ldb + lc*8;
    const __nv_bfloat16* pBl0 = Bl + (long long)(n0 + lr)*ldb + lc*8;
    const __nv_bfloat16* pBh1 = pBh0 + (long long)128*ldb;
    const __nv_bfloat16* pBl1 = pBl0 + (long long)128*ldb;
    unsigned offR = (unsigned)lr*ROWB + (unsigned)lc*16;

    int NC = Kd / KC;

    auto issue = [&](int s) {
        unsigned base = sb + (unsigned)(s % NSTG)*STGB;
        int k0 = s*KC;
        CP_ASYNC16(base + offR,                 pAh  + k0);
        if (TERMS == 3)
            CP_ASYNC16(base + RG_AL + offR,     pAl  + k0);
        CP_ASYNC16(base + RG_BH + offR,         pBh0 + k0);
        CP_ASYNC16(base + RG_BH + 10240 + offR, pBh1 + k0);
        CP_ASYNC16(base + RG_BL + offR,         pBl0 + k0);
        CP_ASYNC16(base + RG_BL + 10240 + offR, pBl1 + k0);
        CP_COMMIT();
    };

    issue(0);
    if (NC > 1) issue(1);

    unsigned aoff = (unsigned)(lane & 15)*ROWB + (unsigned)(lane >> 4)*16;
    unsigned boff = (unsigned)(lane & 7)*ROWB + (unsigned)((lane >> 3) & 1)*16
                  + (unsigned)(lane >> 4)*(8*ROWB);

    for (int i = 0; i < NC; i++) {
        if (i + 1 < NC) { CP_WAIT1(); } else { CP_WAIT0(); }
        __syncthreads();
        if (i + 2 < NC) issue(i + 2);

        unsigned st = sb + (unsigned)(i % NSTG)*STGB;
        unsigned abase = st + (unsigned)(wm*64)*ROWB;
        unsigned bbase = st + RG_BH + (unsigned)(wn*32)*ROWB;
#pragma unroll
        for (int ks = 0; ks < 2; ks++) {
            unsigned ah[4][4], al[4][4], bh[4][2], bl[4][2];
#pragma unroll
            for (int mt = 0; mt < 4; mt++) {
                unsigned ad = abase + (unsigned)(mt*16)*ROWB + aoff + ks*32;
                LDSM_X4(ah[mt][0], ah[mt][1], ah[mt][2], ah[mt][3], ad);
                if (TERMS == 3)
                    LDSM_X4(al[mt][0], al[mt][1], al[mt][2], al[mt][3], ad + RG_AL);
            }
#pragma unroll
            for (int nt = 0; nt < 4; nt += 2) {
                unsigned bd = bbase + (unsigned)(nt*8)*ROWB + boff + ks*32;
                LDSM_X4(bh[nt][0], bh[nt][1], bh[nt+1][0], bh[nt+1][1], bd);
                LDSM_X4(bl[nt][0], bl[nt][1], bl[nt+1][0], bl[nt+1][1], bd + (RG_BL - RG_BH));
            }
#pragma unroll
            for (int mt = 0; mt < 4; mt++)
#pragma unroll
                for (int nt = 0; nt < 4; nt++) {
                    if (TERMS == 3) {
                        MMA16816(acc[mt][nt], ah[mt], bh[nt]);
                        MMA16816(acc[mt][nt], ah[mt], bl[nt]);
                        MMA16816(acc[mt][nt], al[mt], bh[nt]);
                    } else {
                        MMA16816H(acc[mt][nt], ah[mt], bh[nt]);
                        MMA16816H(acc[mt][nt], ah[mt], bl[nt]);
                    }
                }
        }
    }

    // ---- epilogue ----
#pragma unroll
    for (int mt = 0; mt < 4; mt++) {
#pragma unroll
        for (int half = 0; half < 2; half++) {
            int gm = m0 + wm*64 + mt*16 + (lane >> 2) + half*8;
            if (gm >= M) continue;
            long long crow = SCATTER ? (long long)ridx[gm]*ldc : (long long)gm*ldc;
#pragma unroll
            for (int nt = 0; nt < 4; nt++) {
                int gn = n0 + wn*32 + nt*8 + (lane & 3)*2;
                float v0 = acc[mt][nt][half*2 + 0] * alpha;
                float v1 = acc[mt][nt][half*2 + 1] * alpha;
                if (bias) { v0 += bias[gn]; v1 += bias[gn+1]; }
                if (ACT == 1) {
                    v0 = 0.5f*v0*(1.0f + erff(v0*0.7071067811865475f));
                    v1 = 0.5f*v1*(1.0f + erff(v1*0.7071067811865475f));
                } else if (ACT == 2) {
                    v0 = v0 > 0.f ? v0 : 0.f;
                    v1 = v1 > 0.f ? v1 : 0.f;
                }
                if (SCATTER) {
                    atomicAdd(C + crow + gn,     v0);
                    atomicAdd(C + crow + gn + 1, v1);
                } else {
                    if (OF32) *(float2*)(C + crow + gn) = make_float2(v0, v1);
                    if (OSPLIT) {
                        unsigned hw, lw; split2w(v0, v1, hw, lw);
                        *(unsigned*)(Ch + crow + gn) = hw;
                        *(unsigned*)(Cl + crow + gn) = lw;
                    }
                }
            }
        }
    }
}

// ================= weight prep (bandwidth-optimized) =================
__global__ void split_k(const float* __restrict__ W, __nv_bfloat16* __restrict__ hi,
                        __nv_bfloat16* __restrict__ lo, long long n4) {
    long long i = (long long)blockIdx.x*256 + threadIdx.x;
    if (i >= n4) return;
    float4 v = ((const float4*)W)[i];
    unsigned h0, l0, h1, l1;
    split2w(v.x, v.y, h0, l0); split2w(v.z, v.w, h1, l1);
    ((uint2*)hi)[i] = make_uint2(h0, h1);
    ((uint2*)lo)[i] = make_uint2(l0, l1);
}
// out[N,K] = split(W[K,N]), 64x64 tiles; HALFOUT selects fp16 vs bf16 split.
template<bool HALFOUT>
__global__ void transsplit_k(const float* __restrict__ W, int ldw,
                             void* __restrict__ hip, void* __restrict__ lop,
                             int Kd, int Nd, long long sWb, long long sWh,
                             long long sOb, long long sOh, int nhz) {
    int z = blockIdx.z, zb = z / nhz, zh = z % nhz;
    W += zb*sWb + zh*sWh;
    __nv_bfloat16* hi = (__nv_bfloat16*)hip + zb*sOb + zh*sOh;
    __nv_bfloat16* lo = (__nv_bfloat16*)lop + zb*sOb + zh*sOh;
    __shared__ float ts[64][65];
    int n0 = blockIdx.x*64, k0 = blockIdx.y*64;
    int tid = threadIdx.x;                     // 256
    {
        int rr = tid >> 4, c4 = (tid & 15)*4;
#pragma unroll
        for (int it = 0; it < 4; it++) {
            int r = rr + it*16;
            float4 v = *(const float4*)(W + (long long)(k0 + r)*ldw + n0 + c4);
            ts[r][c4+0] = v.x; ts[r][c4+1] = v.y; ts[r][c4+2] = v.z; ts[r][c4+3] = v.w;
        }
    }
    __syncthreads();
    int nb = tid >> 4, kq = (tid & 15)*4;
#pragma unroll
    for (int it = 0; it < 4; it++) {
        int nn = nb + it*16;
        float a = ts[kq+0][nn], b = ts[kq+1][nn];
        float c = ts[kq+2][nn], d = ts[kq+3][nn];
        unsigned h0, l0, h1, l1;
        if (HALFOUT) { split2wh(a, b, h0, l0); split2wh(c, d, h1, l1); }
        else         { split2w (a, b, h0, l0); split2w (c, d, h1, l1); }
        long long o = (long long)(n0 + nn)*Kd + k0 + kq;
        *(uint2*)(hi + o) = make_uint2(h0, h1);
        *(uint2*)(lo + o) = make_uint2(l0, l1);
    }
}

// ================= block reduce helpers (smem broadcast) =================
__device__ __forceinline__ float blk_sum(float v, float* red, int tid) {
#pragma unroll
    for (int o = 16; o > 0; o >>= 1) v += __shfl_xor_sync(0xffffffffu, v, o);
    if ((tid & 31) == 0) red[tid >> 5] = v;
    __syncthreads();
    if (tid < 32) {
        float s = (tid < 8) ? red[tid] : 0.f;
#pragma unroll
        for (int o = 4; o > 0; o >>= 1) s += __shfl_xor_sync(0xffffffffu, s, o);
        if (tid == 0) red[0] = s;
    }
    __syncthreads();
    float r = red[0];
    __syncthreads();
    return r;
}
__device__ __forceinline__ float blk_max(float v, float* red, int tid) {
#pragma unroll
    for (int o = 16; o > 0; o >>= 1) v = fmaxf(v, __shfl_xor_sync(0xffffffffu, v, o));
    if ((tid & 31) == 0) red[tid >> 5] = v;
    __syncthreads();
    if (tid < 32) {
        float s = (tid < 8) ? red[tid] : -1e30f;
#pragma unroll
        for (int o = 4; o > 0; o >>= 1) s = fmaxf(s, __shfl_xor_sync(0xffffffffu, s, o));
        if (tid == 0) red[0] = s;
    }
    __syncthreads();
    float r = red[0];
    __syncthreads();
    return r;
}

// ================= misc kernels (vectorized) =================
__global__ void embed_k(const int* __restrict__ ids, const float* __restrict__ emb,
                        float* __restrict__ out,
                        __nv_bfloat16* __restrict__ oh, __nv_bfloat16* __restrict__ ol) {
    long long t = blockIdx.x;
    int tid = threadIdx.x;
    float4 v = ((const float4*)(emb + (size_t)ids[t]*HN))[tid];
    ((float4*)(out + t*HN))[tid] = v;
    unsigned h0, l0, h1, l1;
    split2w(v.x, v.y, h0, l0); split2w(v.z, v.w, h1, l1);
    ((uint2*)(oh + t*HN))[tid] = make_uint2(h0, h1);
    ((uint2*)(ol + t*HN))[tid] = make_uint2(l0, l1);
}
__global__ void softmax_k(const float* __restrict__ p,
                          __nv_bfloat16* __restrict__ oh, __nv_bfloat16* __restrict__ ol) {
    long long row = blockIdx.x;
    int tid = threadIdx.x;
    __shared__ float red[8];
    float4 v = ((const float4*)(p + row*SS))[tid];
    float mx = blk_max(fmaxf(fmaxf(v.x, v.y), fmaxf(v.z, v.w)), red, tid);
    v.x = expf(v.x - mx); v.y = expf(v.y - mx); v.z = expf(v.z - mx); v.w = expf(v.w - mx);
    float inv = 1.f / blk_sum(v.x + v.y + v.z + v.w, red, tid);
    v.x *= inv; v.y *= inv; v.z *= inv; v.w *= inv;
    unsigned h0, l0, h1, l1;
    split2w(v.x, v.y, h0, l0); split2w(v.z, v.w, h1, l1);
    ((uint2*)(oh + row*SS))[tid] = make_uint2(h0, h1);
    ((uint2*)(ol + row*SS))[tid] = make_uint2(l0, l1);
}
__global__ void ln_k(const float* __restrict__ resid, const float* __restrict__ delta,
                     const float* __restrict__ g, const float* __restrict__ b,
                     float* __restrict__ out,
                     __nv_bfloat16* __restrict__ oh, __nv_bfloat16* __restrict__ ol) {
    long long t = blockIdx.x;
    int tid = threadIdx.x;
    __shared__ float red[8];
    float4 r = ((const float4*)(resid + t*HN))[tid];
    float4 d = ((const float4*)(delta + t*HN))[tid];
    float4 v = make_float4(r.x + d.x, r.y + d.y, r.z + d.z, r.w + d.w);
    float m = blk_sum(v.x + v.y + v.z + v.w, red, tid) * (1.0f/HN);
    float4 c = make_float4(v.x - m, v.y - m, v.z - m, v.w - m);
    float var = blk_sum(c.x*c.x + c.y*c.y + c.z*c.z + c.w*c.w, red, tid) * (1.0f/HN);
    float inv = rsqrtf(var + 1e-5f);
    float4 gg = ((const float4*)g)[tid];
    float4 bb = ((const float4*)b)[tid];
    float4 o = make_float4(c.x*inv*gg.x + bb.x, c.y*inv*gg.y + bb.y,
                           c.z*inv*gg.z + bb.z, c.w*inv*gg.w + bb.w);
    ((float4*)(out + t*HN))[tid] = o;
    unsigned h0, l0, h1, l1;
    split2w(o.x, o.y, h0, l0); split2w(o.z, o.w, h1, l1);
    ((uint2*)(oh + t*HN))[tid] = make_uint2(h0, h1);
    ((uint2*)(ol + t*HN))[tid] = make_uint2(l0, l1);
}
__global__ void gate_k(const float* __restrict__ x, const float* __restrict__ gw,
                       const float* __restrict__ gb, int* __restrict__ cnt,
                       int* __restrict__ toks) {
    int t = blockIdx.x;
    int tid = threadIdx.x;
    __shared__ float xs[HN];
    __shared__ float red[256];
    for (int i = tid; i < HN; i += 256) xs[i] = x[(long long)t*HN+i];
    __syncthreads();
    int e = tid & 7, g = tid >> 3;
    float p = 0.f;
    for (int j = g; j < HN; j += 32) p += xs[j]*gw[j*NE+e];
    red[tid] = p; __syncthreads();
    if (tid < 8) {
        float s = 0.f;
        for (int j = 0; j < 32; j++) s += red[j*8 + tid];
        red[tid] = s + gb[tid];
    }
    __syncthreads();
    if (tid == 0) {
        float l[NE];
        for (int i = 0; i < NE; i++) l[i] = red[i];
        int i1 = 0;
        for (int i = 1; i < NE; i++) if (l[i] > l[i1]) i1 = i;
        int i2 = (i1 == 0) ? 1 : 0;
        for (int i = 0; i < NE; i++) if (i != i1 && l[i] > l[i2]) i2 = i;
        int p1 = atomicAdd(&cnt[i1], 1); toks[i1*TK+p1] = t;
        int p2 = atomicAdd(&cnt[i2], 1); toks[i2*TK+p2] = t;
    }
}
__global__ void copysplit_k(float* __restrict__ dst, __nv_bfloat16* __restrict__ oh,
                            __nv_bfloat16* __restrict__ ol, const float* __restrict__ src,
                            long long n4) {
    long long i = (long long)blockIdx.x*blockDim.x + threadIdx.x;
    if (i >= n4) return;
    float4 v = ((const float4*)src)[i];
    ((float4*)dst)[i] = v;
    unsigned h0, l0, h1, l1;
    split2w(v.x, v.y, h0, l0); split2w(v.z, v.w, h1, l1);
    ((uint2*)oh)[i] = make_uint2(h0, h1);
    ((uint2*)ol)[i] = make_uint2(l0, l1);
}
__global__ void xtohalf_k(const float* __restrict__ src, __half* __restrict__ dst,
                          long long n4) {
    long long i = (long long)blockIdx.x*blockDim.x + threadIdx.x;
    if (i >= n4) return;
    float4 v = ((const float4*)src)[i];
    __half2 a = __floats2half2_rn(v.x, v.y);
    __half2 b = __floats2half2_rn(v.z, v.w);
    ((uint2*)dst)[i] = make_uint2(*(unsigned*)&a, *(unsigned*)&b);
}

// ================= launch =================
extern "C" void kernel_launch(void* const* d_in, const int* in_sizes, int n_in,
                              void* d_out, int out_size)
{
    const int*   ids   = (const int*)d_in[0];
    const float* emb   = (const float*)d_in[1];
    const float* qkvw  = (const float*)d_in[2];
    const float* qkvb  = (const float*)d_in[3];
    const float* outw  = (const float*)d_in[4];
    const float* outb  = (const float*)d_in[5];
    const float* ln1g  = (const float*)d_in[6];
    const float* ln1b  = (const float*)d_in[7];
    const float* ffw1  = (const float*)d_in[8];
    const float* ffb1  = (const float*)d_in[9];
    const float* ffw2  = (const float*)d_in[10];
    const float* ffb2  = (const float*)d_in[11];
    const float* ln2g  = (const float*)d_in[12];
    const float* ln2b  = (const float*)d_in[13];
    const float* gw    = (const float*)d_in[14];
    const float* gb    = (const float*)d_in[15];
    const float* ew1   = (const float*)d_in[16];
    const float* eb1   = (const float*)d_in[17];
    const float* ew2   = (const float*)d_in[18];
    const float* eb2   = (const float*)d_in[19];
    const float* lmw   = (const float*)d_in[20];
    const float* lmb   = (const float*)d_in[21];
    float* out = (float*)d_out;

    float *x, *t1, *big, *sc; int *cnt, *tok;
    __nv_bfloat16 *wh, *wl, *vth, *vtl, *xh, *xl, *bh, *bl, *ph, *pl, *ehh, *ehl, *t1h, *t1l;
    __half *lmh, *lml, *xf;
    cudaGetSymbolAddress((void**)&x,   g_x);
    cudaGetSymbolAddress((void**)&t1,  g_t1);
    cudaGetSymbolAddress((void**)&big, g_big);
    cudaGetSymbolAddress((void**)&sc,  g_sc);
    cudaGetSymbolAddress((void**)&cnt, g_cnt);
    cudaGetSymbolAddress((void**)&tok, g_tok);
    cudaGetSymbolAddress((void**)&wh,  g_wh);
    cudaGetSymbolAddress((void**)&wl,  g_wl);
    cudaGetSymbolAddress((void**)&vth, g_vth);
    cudaGetSymbolAddress((void**)&vtl, g_vtl);
    cudaGetSymbolAddress((void**)&xh,  g_xh);
    cudaGetSymbolAddress((void**)&xl,  g_xl);
    cudaGetSymbolAddress((void**)&bh,  g_bh);
    cudaGetSymbolAddress((void**)&bl,  g_bl);
    cudaGetSymbolAddress((void**)&ph,  g_ph);
    cudaGetSymbolAddress((void**)&pl,  g_pl);
    cudaGetSymbolAddress((void**)&ehh, g_ehh);
    cudaGetSymbolAddress((void**)&ehl, g_ehl);
    cudaGetSymbolAddress((void**)&t1h, g_t1h);
    cudaGetSymbolAddress((void**)&t1l, g_t1l);
    cudaGetSymbolAddress((void**)&lmh, g_lmh);
    cudaGetSymbolAddress((void**)&lml, g_lml);
    cudaGetSymbolAddress((void**)&xf,  g_xf);

    cudaFuncSetAttribute(tc_k<0,false,false,true, true, false,3>, cudaFuncAttributeMaxDynamicSharedMemorySize, SMEMB);
    cudaFuncSetAttribute(tc_k<0,false,false,false,true, false,3>, cudaFuncAttributeMaxDynamicSharedMemorySize, SMEMB);
    cudaFuncSetAttribute(tc_k<0,false,false,true, false,false,3>, cudaFuncAttributeMaxDynamicSharedMemorySize, SMEMB);
    cudaFuncSetAttribute(tc_k<1,false,false,true, false,false,3>, cudaFuncAttributeMaxDynamicSharedMemorySize, SMEMB);
    cudaFuncSetAttribute(tc_k<2,true, false,true, false,false,3>, cudaFuncAttributeMaxDynamicSharedMemorySize, SMEMB);
    cudaFuncSetAttribute(tc_k<0,false,true, false,false,false,3>, cudaFuncAttributeMaxDynamicSharedMemorySize, SMEMB);
    cudaFuncSetAttribute(tc_k<0,false,false,false,true, true, 2>, cudaFuncAttributeMaxDynamicSharedMemorySize, SMEMB);

    const long long Z0 = 0;

    // ---- weight pre-split ----
    split_k<<<(unsigned)(((long long)NL*3*HN*HN/4 + 255)/256), 256>>>(qkvw, wh + OFF_QKV, wl + OFF_QKV, (long long)NL*3*HN*HN/4);
    split_k<<<(unsigned)(((long long)NL*HN*HN/4 + 255)/256), 256>>>(outw, wh + OFF_OUT, wl + OFF_OUT, (long long)NL*HN*HN/4);
    transsplit_k<false><<<dim3(FFD/64, HN/64, NL), 256>>>(ffw1, FFD, wh + OFF_FF1, wl + OFF_FF1,
        HN, FFD, (long long)HN*FFD, Z0, (long long)HN*FFD, Z0, 1);
    transsplit_k<false><<<dim3(HN/64, FFD/64, NL), 256>>>(ffw2, HN, wh + OFF_FF2, wl + OFF_FF2,
        FFD, HN, (long long)FFD*HN, Z0, (long long)FFD*HN, Z0, 1);
    transsplit_k<false><<<dim3(EHD/64, HN/64, NL*NE), 256>>>(ew1, EHD, wh + OFF_E1, wl + OFF_E1,
        HN, EHD, (long long)HN*EHD, Z0, (long long)HN*EHD, Z0, 1);
    transsplit_k<false><<<dim3(HN/64, EHD/64, NL*NE), 256>>>(ew2, HN, wh + OFF_E2, wl + OFF_E2,
        EHD, HN, (long long)EHD*HN, Z0, (long long)EHD*HN, Z0, 1);
    transsplit_k<true><<<dim3(VS/64, HN/64, 1), 256>>>(lmw, VS, lmh, lml,
        HN, VS, Z0, Z0, Z0, Z0, 1);

    embed_k<<<TK, 256>>>(ids, emb, x, xh, xl);

    for (int l = 0; l < NL; l++) {
        // qkv = x @ Wqkv^T + b  -> big fp32 + bh/bl
        tc_k<0,false,false,true,true,false,3><<<dim3(3*HN/BN, TK/BM, 1), 512, SMEMB>>>(
            xh, xl, wh + OFF_QKV + (long long)l*3*HN*HN, wl + OFF_QKV + (long long)l*3*HN*HN,
            qkvb + (long long)l*3*HN, big, bh, bl, TK, 3*HN, HN, HN, HN, 3*HN,
            Z0,Z0,Z0,Z0,Z0,Z0,Z0, 0, 1.f, nullptr, nullptr);

        // V^T split per (b,h)
        transsplit_k<false><<<dim3(HDD/64, SS/64, BB*NHD), 256>>>(
            big + 2*HN, 3*HN, vth, vtl, SS, HDD,
            (long long)SS*3*HN, (long long)HDD,
            (long long)NHD*HDD*SS, (long long)HDD*SS, NHD);

        // scores = Q @ K^T / 16 -> sc fp32
        tc_k<0,false,false,false,true,false,3><<<dim3(SS/BN, SS/BM, BB*NHD), 512, SMEMB>>>(
            bh, bl, bh + HN, bl + HN, nullptr, sc, nullptr, nullptr,
            SS, SS, HDD, 3*HN, 3*HN, SS,
            (long long)SS*3*HN, (long long)HDD,
            (long long)SS*3*HN, (long long)HDD,
            (long long)NHD*SS*SS, (long long)SS*SS, Z0, NHD,
            0.0625f, nullptr, nullptr);

        softmax_k<<<BB*NHD*SS, 256>>>(sc, ph, pl);

        // ao = probs @ V -> t1h/t1l
        tc_k<0,false,false,true,false,false,3><<<dim3(HDD/BN, SS/BM, BB*NHD), 512, SMEMB>>>(
            ph, pl, vth, vtl, nullptr, nullptr, t1h, t1l,
            SS, HDD, SS, SS, SS, HN,
            (long long)NHD*SS*SS, (long long)SS*SS,
            (long long)NHD*HDD*SS, (long long)HDD*SS,
            (long long)SS*HN, (long long)HDD, Z0, NHD,
            1.f, nullptr, nullptr);

        // proj = ao @ Wout^T + b -> big fp32
        tc_k<0,false,false,false,true,false,3><<<dim3(HN/BN, TK/BM, 1), 512, SMEMB>>>(
            t1h, t1l, wh + OFF_OUT + (long long)l*HN*HN, wl + OFF_OUT + (long long)l*HN*HN,
            outb + (long long)l*HN, big, nullptr, nullptr, TK, HN, HN, HN, HN, HN,
            Z0,Z0,Z0,Z0,Z0,Z0,Z0, 0, 1.f, nullptr, nullptr);

        ln_k<<<TK,256>>>(x, big, ln1g + (long long)l*HN, ln1b + (long long)l*HN, x, xh, xl);

        // ffn
        tc_k<1,false,false,true,false,false,3><<<dim3(FFD/BN, TK/BM, 1), 512, SMEMB>>>(
            xh, xl, wh + OFF_FF1 + (long long)l*HN*FFD, wl + OFF_FF1 + (long long)l*HN*FFD,
            ffb1 + (long long)l*FFD, nullptr, bh, bl, TK, FFD, HN, HN, HN, FFD,
            Z0,Z0,Z0,Z0,Z0,Z0,Z0, 0, 1.f, nullptr, nullptr);
        tc_k<0,false,false,false,true,false,3><<<dim3(HN/BN, TK/BM, 1), 512, SMEMB>>>(
            bh, bl, wh + OFF_FF2 + (long long)l*FFD*HN, wl + OFF_FF2 + (long long)l*FFD*HN,
            ffb2 + (long long)l*HN, t1, nullptr, nullptr, TK, HN, FFD, FFD, FFD, HN,
            Z0,Z0,Z0,Z0,Z0,Z0,Z0, 0, 1.f, nullptr, nullptr);

        ln_k<<<TK,256>>>(x, t1, ln2g + (long long)l*HN, ln2b + (long long)l*HN, x, xh, xl);

        // MoE
        cudaMemsetAsync(cnt, 0, NE*sizeof(int));
        gate_k<<<TK,256>>>(x, gw + (long long)l*HN*NE, gb + (long long)l*NE, cnt, tok);
        cudaMemsetAsync(t1, 0, (size_t)TK*HN*sizeof(float));

        // up: ehh/ehl[e] = relu(x[gather] @ W1_e + b1_e)
        tc_k<2,true,false,true,false,false,3><<<dim3(EHD/BN, TK/BM, NE), 512, SMEMB>>>(
            xh, xl, wh + OFF_E1 + (long long)l*NE*HN*EHD, wl + OFF_E1 + (long long)l*NE*HN*EHD,
            eb1 + (long long)l*NE*EHD, nullptr, ehh, ehl, TK, EHD, HN, HN, HN, EHD,
            Z0, Z0, (long long)EHD*HN, Z0, (long long)TK*EHD, Z0, (long long)EHD, 1,
            1.f, tok, cnt);
        // down: t1[token] += eh[e] @ W2_e + b2_e  (atomic scatter)
        tc_k<0,false,true,false,false,false,3><<<dim3(HN/BN, TK/BM, NE), 512, SMEMB>>>(
            ehh, ehl, wh + OFF_E2 + (long long)l*NE*EHD*HN, wl + OFF_E2 + (long long)l*NE*EHD*HN,
            eb2 + (long long)l*NE*HN, t1, nullptr, nullptr, TK, HN, EHD, EHD, EHD, HN,
            (long long)TK*EHD, Z0, (long long)HN*EHD, Z0, Z0, Z0, (long long)HN, 1,
            1.f, tok, cnt);

        copysplit_k<<<(TK*HN/4)/256, 256>>>(x, xh, xl, t1, (long long)TK*HN/4);
    }

    // lm head: fp16x2 (A = fp16(x); B = fp16 hi/lo), M-inner rasterization
    xtohalf_k<<<(TK*HN/4)/256, 256>>>(x, xf, (long long)TK*HN/4);
    tc_k<0,false,false,false,true,true,2><<<dim3(TK/BM, VS/BN, 1), 512, SMEMB>>>(
        (const __nv_bfloat16*)xf, (const __nv_bfloat16*)xf,
        (const __nv_bfloat16*)lmh, (const __nv_bfloat16*)lml,
        lmb, out, nullptr, nullptr,
        TK, VS, HN, HN, HN, VS,
        Z0,Z0,Z0,Z0,Z0,Z0,Z0, 0, 1.f, nullptr, nullptr);
}

// round 14
// speedup vs baseline: 3.8320x; 1.1285x over previous
#include <cuda_runtime.h>
#include <cuda_bf16.h>
#include <cuda_fp16.h>
#include <math.h>

// ---------------- problem constants ----------------
#define TK   4096
#define HN   1024
#define NHD  4
#define HDD  256
#define BB   4
#define SS   1024
#define FFD  4096
#define NE   8
#define EHD  2048
#define VS   32000
#define NL   2

// ---------------- split-weight offsets (elements) ----------------
#define OFF_QKV 0LL
#define OFF_OUT  (OFF_QKV + (long long)NL*3*HN*HN)
#define OFF_FF1  (OFF_OUT + (long long)NL*HN*HN)
#define OFF_FF2  (OFF_FF1 + (long long)NL*HN*FFD)
#define OFF_E1   (OFF_FF2 + (long long)NL*FFD*HN)
#define OFF_E2   (OFF_E1  + (long long)NL*NE*HN*EHD)
#define TOTW     (OFF_E2  + (long long)NL*NE*EHD*HN)

// ---------------- scratch ----------------
__device__ float g_x  [(size_t)TK*HN];
__device__ float g_t1 [(size_t)TK*HN];
__device__ float g_big[(size_t)TK*FFD];
__device__ float g_sc [(size_t)BB*NHD*SS*SS];
__device__ int   g_cnt[NE];
__device__ int   g_tok[NE*TK];
__device__ __nv_bfloat16 g_wh[TOTW];
__device__ __nv_bfloat16 g_wl[TOTW];
__device__ __nv_bfloat16 g_vth[(size_t)BB*NHD*HDD*SS];
__device__ __nv_bfloat16 g_vtl[(size_t)BB*NHD*HDD*SS];
// split activations
__device__ __nv_bfloat16 g_xh [(size_t)TK*HN];
__device__ __nv_bfloat16 g_xl [(size_t)TK*HN];
__device__ __nv_bfloat16 g_bh [(size_t)TK*FFD];
__device__ __nv_bfloat16 g_bl [(size_t)TK*FFD];
__device__ __nv_bfloat16 g_ph [(size_t)BB*NHD*SS*SS];
__device__ __nv_bfloat16 g_pl [(size_t)BB*NHD*SS*SS];
__device__ __nv_bfloat16 g_ehh[(size_t)NE*TK*EHD];
__device__ __nv_bfloat16 g_ehl[(size_t)NE*TK*EHD];
__device__ __nv_bfloat16 g_t1h[(size_t)TK*HN];
__device__ __nv_bfloat16 g_t1l[(size_t)TK*HN];
// fp16 LM-head path
__device__ __half g_lmh[(size_t)HN*VS];
__device__ __half g_lml[(size_t)HN*VS];
__device__ __half g_xf [(size_t)TK*HN];

// ================= helpers =================
__device__ __forceinline__ unsigned smem_u32(const void* p){
    unsigned a;
    asm("{ .reg .u64 t; cvta.to.shared.u64 t, %1; cvt.u32.u64 %0, t; }" : "=r"(a) : "l"(p));
    return a;
}
__device__ __forceinline__ void split1(float v, __nv_bfloat16& h, __nv_bfloat16& l) {
    h = __float2bfloat16(v);
    l = __float2bfloat16(v - __bfloat162float(h));
}
__device__ __forceinline__ void split2w(float v0, float v1, unsigned& hw, unsigned& lw) {
    __nv_bfloat16 h0, l0, h1, l1;
    split1(v0, h0, l0); split1(v1, h1, l1);
    hw = (unsigned)__bfloat16_as_ushort(h0) | ((unsigned)__bfloat16_as_ushort(h1) << 16);
    lw = (unsigned)__bfloat16_as_ushort(l0) | ((unsigned)__bfloat16_as_ushort(l1) << 16);
}
__device__ __forceinline__ void split2wh(float v0, float v1, unsigned& hw, unsigned& lw) {
    __half h0 = __float2half(v0), h1 = __float2half(v1);
    __half l0 = __float2half(v0 - __half2float(h0));
    __half l1 = __float2half(v1 - __half2float(h1));
    hw = (unsigned)__half_as_ushort(h0) | ((unsigned)__half_as_ushort(h1) << 16);
    lw = (unsigned)__half_as_ushort(l0) | ((unsigned)__half_as_ushort(l1) << 16);
}

#define LDSM_X4(r0, r1, r2, r3, a) \
    asm volatile("ldmatrix.sync.aligned.m8n8.x4.shared.b16 {%0,%1,%2,%3}, [%4];" \
                 : "=r"(r0), "=r"(r1), "=r"(r2), "=r"(r3) : "r"(a))
#define MMA16816(d, a, b) \
    asm volatile("mma.sync.aligned.m16n8k16.row.col.f32.bf16.bf16.f32 " \
                 "{%0,%1,%2,%3}, {%4,%5,%6,%7}, {%8,%9}, {%0,%1,%2,%3};" \
                 : "+f"((d)[0]), "+f"((d)[1]), "+f"((d)[2]), "+f"((d)[3]) \
                 : "r"((a)[0]), "r"((a)[1]), "r"((a)[2]), "r"((a)[3]), \
                   "r"((b)[0]), "r"((b)[1]))
#define MMA16816H(d, a, b) \
    asm volatile("mma.sync.aligned.m16n8k16.row.col.f32.f16.f16.f32 " \
                 "{%0,%1,%2,%3}, {%4,%5,%6,%7}, {%8,%9}, {%0,%1,%2,%3};" \
                 : "+f"((d)[0]), "+f"((d)[1]), "+f"((d)[2]), "+f"((d)[3]) \
                 : "r"((a)[0]), "r"((a)[1]), "r"((a)[2]), "r"((a)[3]), \
                   "r"((b)[0]), "r"((b)[1]))
#define CP_ASYNC16(sa, gp) \
    asm volatile("cp.async.cg.shared.global [%0], [%1], 16;" :: "r"(sa), "l"(gp) : "memory")
#define CP_COMMIT() asm volatile("cp.async.commit_group;" ::: "memory")
#define CP_WAIT1()  asm volatile("cp.async.wait_group 1;" ::: "memory")
#define CP_WAIT0()  asm volatile("cp.async.wait_group 0;" ::: "memory")

// ================= bf16x3 / fp16x2 / fp16x1 MMA GEMM (cp.async 3-stage) ======
#define BM 128
#define BN 256
#define KC 32
#define ROWB 80
#define RG_AL 10240
#define RG_BH 20480
#define RG_BL 40960
#define STGB  61440
#define NSTG  3
#define SMEMB (NSTG*STGB)

template<int ACT, bool GATHER, bool SCATTER, bool OSPLIT, bool OF32, bool SWAP, int TERMS>
__global__ void __launch_bounds__(512, 1)
tc_k(const __nv_bfloat16* __restrict__ Ah, const __nv_bfloat16* __restrict__ Al,
     const __nv_bfloat16* __restrict__ Bh, const __nv_bfloat16* __restrict__ Bl,
     const float* __restrict__ bias,
     float* __restrict__ C, __nv_bfloat16* __restrict__ Ch, __nv_bfloat16* __restrict__ Cl,
     int M, int N, int Kd, int lda, int ldb, int ldc,
     long long sAb, long long sAh_, long long sBb, long long sBh_,
     long long sCb, long long sCh_, long long sBias, int nh, float alpha,
     const int* __restrict__ ridx, const int* __restrict__ cptr)
{
    if (nh > 0) {
        int z = blockIdx.z, zb = z / nh, zh = z % nh;
        long long ao = zb*sAb + zh*sAh_;
        Ah += ao; Al += ao;
        long long bo = zb*sBb + zh*sBh_;
        Bh += bo; Bl += bo;
        long long co = zb*sCb + zh*sCh_;
        if (OF32 || SCATTER) C += co;
        if (OSPLIT) { Ch += co; Cl += co; }
        if (bias) bias += zb*sBias;
        if (GATHER || SCATTER) ridx += (long long)zb*TK;
        if (cptr) cptr += zb;
    }
    if (cptr) M = *cptr;
    int m0 = SWAP ? blockIdx.x*BM : blockIdx.y*BM;
    int n0 = SWAP ? blockIdx.y*BN : blockIdx.x*BN;
    if (m0 >= M) return;

    extern __shared__ char sm[];
    unsigned sb = smem_u32(sm);
    int tid = threadIdx.x, lane = tid & 31, wid = tid >> 5;
    int wm = wid & 1, wn = wid >> 1;       // 2 x 8 warp grid; warp tile 64x32

    float acc[4][4][4];
#pragma unroll
    for (int i = 0; i < 4; i++)
#pragma unroll
        for (int j = 0; j < 4; j++)
#pragma unroll
            for (int e = 0; e < 4; e++) acc[i][j][e] = 0.f;

    int lr = tid >> 2, lc = tid & 3;
    long long arow;
    { int gm = m0 + lr; if (gm >= M) gm = M - 1;
      arow = GATHER ? (long long)ridx[gm] : (long long)gm; }
    const __nv_bfloat16* pAh  = Ah + arow*lda + lc*8;
    const __nv_bfloat16* pAl  = Al + arow*lda + lc*8;
    const __nv_bfloat16* pBh0 = Bh + (long long)(n0 + lr)*ldb + lc*8;
    const __nv_bfloat16* pBl0 = Bl + (long long)(n0 + lr)*ldb + lc*8;
    const __nv_bfloat16* pBh1 = pBh0 + (long long)128*ldb;
    const __nv_bfloat16* pBl1 = pBl0 + (long long)128*ldb;
    unsigned offR = (unsigned)lr*ROWB + (unsigned)lc*16;

    int NC = Kd / KC;

    auto issue = [&](int s) {
        unsigned base = sb + (unsigned)(s % NSTG)*STGB;
        int k0 = s*KC;
        CP_ASYNC16(base + offR,                 pAh  + k0);
        if (TERMS == 3)
            CP_ASYNC16(base + RG_AL + offR,     pAl  + k0);
        CP_ASYNC16(base + RG_BH + offR,         pBh0 + k0);
        CP_ASYNC16(base + RG_BH + 10240 + offR, pBh1 + k0);
        if (TERMS >= 2) {
            CP_ASYNC16(base + RG_BL + offR,         pBl0 + k0);
            CP_ASYNC16(base + RG_BL + 10240 + offR, pBl1 + k0);
        }
        CP_COMMIT();
    };

    issue(0);
    if (NC > 1) issue(1);

    unsigned aoff = (unsigned)(lane & 15)*ROWB + (unsigned)(lane >> 4)*16;
    unsigned boff = (unsigned)(lane & 7)*ROWB + (unsigned)((lane >> 3) & 1)*16
                  + (unsigned)(lane >> 4)*(8*ROWB);

    for (int i = 0; i < NC; i++) {
        if (i + 1 < NC) { CP_WAIT1(); } else { CP_WAIT0(); }
        __syncthreads();
        if (i + 2 < NC) issue(i + 2);

        unsigned st = sb + (unsigned)(i % NSTG)*STGB;
        unsigned abase = st + (unsigned)(wm*64)*ROWB;
        unsigned bbase = st + RG_BH + (unsigned)(wn*32)*ROWB;
#pragma unroll
        for (int ks = 0; ks < 2; ks++) {
            unsigned ah[4][4], al[4][4], bh[4][2], bl[4][2];
#pragma unroll
            for (int mt = 0; mt < 4; mt++) {
                unsigned ad = abase + (unsigned)(mt*16)*ROWB + aoff + ks*32;
                LDSM_X4(ah[mt][0], ah[mt][1], ah[mt][2], ah[mt][3], ad);
                if (TERMS == 3)
                    LDSM_X4(al[mt][0], al[mt][1], al[mt][2], al[mt][3], ad + RG_AL);
            }
#pragma unroll
            for (int nt = 0; nt < 4; nt += 2) {
                unsigned bd = bbase + (unsigned)(nt*8)*ROWB + boff + ks*32;
                LDSM_X4(bh[nt][0], bh[nt][1], bh[nt+1][0], bh[nt+1][1], bd);
                if (TERMS >= 2)
                    LDSM_X4(bl[nt][0], bl[nt][1], bl[nt+1][0], bl[nt+1][1], bd + (RG_BL - RG_BH));
            }
#pragma unroll
            for (int mt = 0; mt < 4; mt++)
#pragma unroll
                for (int nt = 0; nt < 4; nt++) {
                    if (TERMS == 3) {
                        MMA16816(acc[mt][nt], ah[mt], bh[nt]);
                        MMA16816(acc[mt][nt], ah[mt], bl[nt]);
                        MMA16816(acc[mt][nt], al[mt], bh[nt]);
                    } else if (TERMS == 2) {
                        MMA16816H(acc[mt][nt], ah[mt], bh[nt]);
                        MMA16816H(acc[mt][nt], ah[mt], bl[nt]);
                    } else {
                        MMA16816H(acc[mt][nt], ah[mt], bh[nt]);
                    }
                }
        }
    }

    // ---- epilogue ----
#pragma unroll
    for (int mt = 0; mt < 4; mt++) {
#pragma unroll
        for (int half = 0; half < 2; half++) {
            int gm = m0 + wm*64 + mt*16 + (lane >> 2) + half*8;
            if (gm >= M) continue;
            long long crow = SCATTER ? (long long)ridx[gm]*ldc : (long long)gm*ldc;
#pragma unroll
            for (int nt = 0; nt < 4; nt++) {
                int gn = n0 + wn*32 + nt*8 + (lane & 3)*2;
                float v0 = acc[mt][nt][half*2 + 0] * alpha;
                float v1 = acc[mt][nt][half*2 + 1] * alpha;
                if (bias) { v0 += bias[gn]; v1 += bias[gn+1]; }
                if (ACT == 1) {
                    v0 = 0.5f*v0*(1.0f + erff(v0*0.7071067811865475f));
                    v1 = 0.5f*v1*(1.0f + erff(v1*0.7071067811865475f));
                } else if (ACT == 2) {
                    v0 = v0 > 0.f ? v0 : 0.f;
                    v1 = v1 > 0.f ? v1 : 0.f;
                }
                if (SCATTER) {
                    atomicAdd(C + crow + gn,     v0);
                    atomicAdd(C + crow + gn + 1, v1);
                } else {
                    if (OF32) *(float2*)(C + crow + gn) = make_float2(v0, v1);
                    if (OSPLIT) {
                        unsigned hw, lw; split2w(v0, v1, hw, lw);
                        *(unsigned*)(Ch + crow + gn) = hw;
                        *(unsigned*)(Cl + crow + gn) = lw;
                    }
                }
            }
        }
    }
}

// ================= weight prep (bandwidth-optimized) =================
__global__ void split_k(const float* __restrict__ W, __nv_bfloat16* __restrict__ hi,
                        __nv_bfloat16* __restrict__ lo, long long n4) {
    long long i = (long long)blockIdx.x*256 + threadIdx.x;
    if (i >= n4) return;
    float4 v = ((const float4*)W)[i];
    unsigned h0, l0, h1, l1;
    split2w(v.x, v.y, h0, l0); split2w(v.z, v.w, h1, l1);
    ((uint2*)hi)[i] = make_uint2(h0, h1);
    ((uint2*)lo)[i] = make_uint2(l0, l1);
}
// out[N,K] = split(W[K,N]), 64x64 tiles; HALFOUT selects fp16 vs bf16 split.
template<bool HALFOUT>
__global__ void transsplit_k(const float* __restrict__ W, int ldw,
                             void* __restrict__ hip, void* __restrict__ lop,
                             int Kd, int Nd, long long sWb, long long sWh,
                             long long sOb, long long sOh, int nhz) {
    int z = blockIdx.z, zb = z / nhz, zh = z % nhz;
    W += zb*sWb + zh*sWh;
    __nv_bfloat16* hi = (__nv_bfloat16*)hip + zb*sOb + zh*sOh;
    __nv_bfloat16* lo = (__nv_bfloat16*)lop + zb*sOb + zh*sOh;
    __shared__ float ts[64][65];
    int n0 = blockIdx.x*64, k0 = blockIdx.y*64;
    int tid = threadIdx.x;                     // 256
    {
        int rr = tid >> 4, c4 = (tid & 15)*4;
#pragma unroll
        for (int it = 0; it < 4; it++) {
            int r = rr + it*16;
            float4 v = *(const float4*)(W + (long long)(k0 + r)*ldw + n0 + c4);
            ts[r][c4+0] = v.x; ts[r][c4+1] = v.y; ts[r][c4+2] = v.z; ts[r][c4+3] = v.w;
        }
    }
    __syncthreads();
    int nb = tid >> 4, kq = (tid & 15)*4;
#pragma unroll
    for (int it = 0; it < 4; it++) {
        int nn = nb + it*16;
        float a = ts[kq+0][nn], b = ts[kq+1][nn];
        float c = ts[kq+2][nn], d = ts[kq+3][nn];
        unsigned h0, l0, h1, l1;
        if (HALFOUT) { split2wh(a, b, h0, l0); split2wh(c, d, h1, l1); }
        else         { split2w (a, b, h0, l0); split2w (c, d, h1, l1); }
        long long o = (long long)(n0 + nn)*Kd + k0 + kq;
        *(uint2*)(hi + o) = make_uint2(h0, h1);
        *(uint2*)(lo + o) = make_uint2(l0, l1);
    }
}

// ================= block reduce helpers (smem broadcast) =================
__device__ __forceinline__ float blk_sum(float v, float* red, int tid) {
#pragma unroll
    for (int o = 16; o > 0; o >>= 1) v += __shfl_xor_sync(0xffffffffu, v, o);
    if ((tid & 31) == 0) red[tid >> 5] = v;
    __syncthreads();
    if (tid < 32) {
        float s = (tid < 8) ? red[tid] : 0.f;
#pragma unroll
        for (int o = 4; o > 0; o >>= 1) s += __shfl_xor_sync(0xffffffffu, s, o);
        if (tid == 0) red[0] = s;
    }
    __syncthreads();
    float r = red[0];
    __syncthreads();
    return r;
}
__device__ __forceinline__ float blk_max(float v, float* red, int tid) {
#pragma unroll
    for (int o = 16; o > 0; o >>= 1) v = fmaxf(v, __shfl_xor_sync(0xffffffffu, v, o));
    if ((tid & 31) == 0) red[tid >> 5] = v;
    __syncthreads();
    if (tid < 32) {
        float s = (tid < 8) ? red[tid] : -1e30f;
#pragma unroll
        for (int o = 4; o > 0; o >>= 1) s = fmaxf(s, __shfl_xor_sync(0xffffffffu, s, o));
        if (tid == 0) red[0] = s;
    }
    __syncthreads();
    float r = red[0];
    __syncthreads();
    return r;
}

// ================= misc kernels (vectorized) =================
__global__ void embed_k(const int* __restrict__ ids, const float* __restrict__ emb,
                        float* __restrict__ out,
                        __nv_bfloat16* __restrict__ oh, __nv_bfloat16* __restrict__ ol) {
    long long t = blockIdx.x;
    int tid = threadIdx.x;
    float4 v = ((const float4*)(emb + (size_t)ids[t]*HN))[tid];
    ((float4*)(out + t*HN))[tid] = v;
    unsigned h0, l0, h1, l1;
    split2w(v.x, v.y, h0, l0); split2w(v.z, v.w, h1, l1);
    ((uint2*)(oh + t*HN))[tid] = make_uint2(h0, h1);
    ((uint2*)(ol + t*HN))[tid] = make_uint2(l0, l1);
}
__global__ void softmax_k(const float* __restrict__ p,
                          __nv_bfloat16* __restrict__ oh, __nv_bfloat16* __restrict__ ol) {
    long long row = blockIdx.x;
    int tid = threadIdx.x;
    __shared__ float red[8];
    float4 v = ((const float4*)(p + row*SS))[tid];
    float mx = blk_max(fmaxf(fmaxf(v.x, v.y), fmaxf(v.z, v.w)), red, tid);
    v.x = expf(v.x - mx); v.y = expf(v.y - mx); v.z = expf(v.z - mx); v.w = expf(v.w - mx);
    float inv = 1.f / blk_sum(v.x + v.y + v.z + v.w, red, tid);
    v.x *= inv; v.y *= inv; v.z *= inv; v.w *= inv;
    unsigned h0, l0, h1, l1;
    split2w(v.x, v.y, h0, l0); split2w(v.z, v.w, h1, l1);
    ((uint2*)(oh + row*SS))[tid] = make_uint2(h0, h1);
    ((uint2*)(ol + row*SS))[tid] = make_uint2(l0, l1);
}
__global__ void ln_k(const float* __restrict__ resid, const float* __restrict__ delta,
                     const float* __restrict__ g, const float* __restrict__ b,
                     float* __restrict__ out,
                     __nv_bfloat16* __restrict__ oh, __nv_bfloat16* __restrict__ ol) {
    long long t = blockIdx.x;
    int tid = threadIdx.x;
    __shared__ float red[8];
    float4 r = ((const float4*)(resid + t*HN))[tid];
    float4 d = ((const float4*)(delta + t*HN))[tid];
    float4 v = make_float4(r.x + d.x, r.y + d.y, r.z + d.z, r.w + d.w);
    float m = blk_sum(v.x + v.y + v.z + v.w, red, tid) * (1.0f/HN);
    float4 c = make_float4(v.x - m, v.y - m, v.z - m, v.w - m);
    float var = blk_sum(c.x*c.x + c.y*c.y + c.z*c.z + c.w*c.w, red, tid) * (1.0f/HN);
    float inv = rsqrtf(var + 1e-5f);
    float4 gg = ((const float4*)g)[tid];
    float4 bb = ((const float4*)b)[tid];
    float4 o = make_float4(c.x*inv*gg.x + bb.x, c.y*inv*gg.y + bb.y,
                           c.z*inv*gg.z + bb.z, c.w*inv*gg.w + bb.w);
    ((float4*)(out + t*HN))[tid] = o;
    unsigned h0, l0, h1, l1;
    split2w(o.x, o.y, h0, l0); split2w(o.z, o.w, h1, l1);
    ((uint2*)(oh + t*HN))[tid] = make_uint2(h0, h1);
    ((uint2*)(ol + t*HN))[tid] = make_uint2(l0, l1);
}
__global__ void gate_k(const float* __restrict__ x, const float* __restrict__ gw,
                       const float* __restrict__ gb, int* __restrict__ cnt,
                       int* __restrict__ toks) {
    int t = blockIdx.x;
    int tid = threadIdx.x;
    __shared__ float xs[HN];
    __shared__ float red[256];
    for (int i = tid; i < HN; i += 256) xs[i] = x[(long long)t*HN+i];
    __syncthreads();
    int e = tid & 7, g = tid >> 3;
    float p = 0.f;
    for (int j = g; j < HN; j += 32) p += xs[j]*gw[j*NE+e];
    red[tid] = p; __syncthreads();
    if (tid < 8) {
        float s = 0.f;
        for (int j = 0; j < 32; j++) s += red[j*8 + tid];
        red[tid] = s + gb[tid];
    }
    __syncthreads();
    if (tid == 0) {
        float l[NE];
        for (int i = 0; i < NE; i++) l[i] = red[i];
        int i1 = 0;
        for (int i = 1; i < NE; i++) if (l[i] > l[i1]) i1 = i;
        int i2 = (i1 == 0) ? 1 : 0;
        for (int i = 0; i < NE; i++) if (i != i1 && l[i] > l[i2]) i2 = i;
        int p1 = atomicAdd(&cnt[i1], 1); toks[i1*TK+p1] = t;
        int p2 = atomicAdd(&cnt[i2], 1); toks[i2*TK+p2] = t;
    }
}
__global__ void copysplit_k(float* __restrict__ dst, __nv_bfloat16* __restrict__ oh,
                            __nv_bfloat16* __restrict__ ol, const float* __restrict__ src,
                            long long n4) {
    long long i = (long long)blockIdx.x*blockDim.x + threadIdx.x;
    if (i >= n4) return;
    float4 v = ((const float4*)src)[i];
    ((float4*)dst)[i] = v;
    unsigned h0, l0, h1, l1;
    split2w(v.x, v.y, h0, l0); split2w(v.z, v.w, h1, l1);
    ((uint2*)oh)[i] = make_uint2(h0, h1);
    ((uint2*)ol)[i] = make_uint2(l0, l1);
}
__global__ void xtohalf_k(const float* __restrict__ src, __half* __restrict__ dst,
                          long long n4) {
    long long i = (long long)blockIdx.x*blockDim.x + threadIdx.x;
    if (i >= n4) return;
    float4 v = ((const float4*)src)[i];
    __half2 a = __floats2half2_rn(v.x, v.y);
    __half2 b = __floats2half2_rn(v.z, v.w);
    ((uint2*)dst)[i] = make_uint2(*(unsigned*)&a, *(unsigned*)&b);
}

// ================= launch =================
extern "C" void kernel_launch(void* const* d_in, const int* in_sizes, int n_in,
                              void* d_out, int out_size)
{
    const int*   ids   = (const int*)d_in[0];
    const float* emb   = (const float*)d_in[1];
    const float* qkvw  = (const float*)d_in[2];
    const float* qkvb  = (const float*)d_in[3];
    const float* outw  = (const float*)d_in[4];
    const float* outb  = (const float*)d_in[5];
    const float* ln1g  = (const float*)d_in[6];
    const float* ln1b  = (const float*)d_in[7];
    const float* ffw1  = (const float*)d_in[8];
    const float* ffb1  = (const float*)d_in[9];
    const float* ffw2  = (const float*)d_in[10];
    const float* ffb2  = (const float*)d_in[11];
    const float* ln2g  = (const float*)d_in[12];
    const float* ln2b  = (const float*)d_in[13];
    const float* gw    = (const float*)d_in[14];
    const float* gb    = (const float*)d_in[15];
    const float* ew1   = (const float*)d_in[16];
    const float* eb1   = (const float*)d_in[17];
    const float* ew2   = (const float*)d_in[18];
    const float* eb2   = (const float*)d_in[19];
    const float* lmw   = (const float*)d_in[20];
    const float* lmb   = (const float*)d_in[21];
    float* out = (float*)d_out;

    float *x, *t1, *big, *sc; int *cnt, *tok;
    __nv_bfloat16 *wh, *wl, *vth, *vtl, *xh, *xl, *bh, *bl, *ph, *pl, *ehh, *ehl, *t1h, *t1l;
    __half *lmh, *lml, *xf;
    cudaGetSymbolAddress((void**)&x,   g_x);
    cudaGetSymbolAddress((void**)&t1,  g_t1);
    cudaGetSymbolAddress((void**)&big, g_big);
    cudaGetSymbolAddress((void**)&sc,  g_sc);
    cudaGetSymbolAddress((void**)&cnt, g_cnt);
    cudaGetSymbolAddress((void**)&tok, g_tok);
    cudaGetSymbolAddress((void**)&wh,  g_wh);
    cudaGetSymbolAddress((void**)&wl,  g_wl);
    cudaGetSymbolAddress((void**)&vth, g_vth);
    cudaGetSymbolAddress((void**)&vtl, g_vtl);
    cudaGetSymbolAddress((void**)&xh,  g_xh);
    cudaGetSymbolAddress((void**)&xl,  g_xl);
    cudaGetSymbolAddress((void**)&bh,  g_bh);
    cudaGetSymbolAddress((void**)&bl,  g_bl);
    cudaGetSymbolAddress((void**)&ph,  g_ph);
    cudaGetSymbolAddress((void**)&pl,  g_pl);
    cudaGetSymbolAddress((void**)&ehh, g_ehh);
    cudaGetSymbolAddress((void**)&ehl, g_ehl);
    cudaGetSymbolAddress((void**)&t1h, g_t1h);
    cudaGetSymbolAddress((void**)&t1l, g_t1l);
    cudaGetSymbolAddress((void**)&lmh, g_lmh);
    cudaGetSymbolAddress((void**)&lml, g_lml);
    cudaGetSymbolAddress((void**)&xf,  g_xf);

    cudaFuncSetAttribute(tc_k<0,false,false,true, true, false,3>, cudaFuncAttributeMaxDynamicSharedMemorySize, SMEMB);
    cudaFuncSetAttribute(tc_k<0,false,false,false,true, false,3>, cudaFuncAttributeMaxDynamicSharedMemorySize, SMEMB);
    cudaFuncSetAttribute(tc_k<0,false,false,true, false,false,3>, cudaFuncAttributeMaxDynamicSharedMemorySize, SMEMB);
    cudaFuncSetAttribute(tc_k<1,false,false,true, false,false,3>, cudaFuncAttributeMaxDynamicSharedMemorySize, SMEMB);
    cudaFuncSetAttribute(tc_k<2,true, false,true, false,false,3>, cudaFuncAttributeMaxDynamicSharedMemorySize, SMEMB);
    cudaFuncSetAttribute(tc_k<0,false,true, false,false,false,3>, cudaFuncAttributeMaxDynamicSharedMemorySize, SMEMB);
    cudaFuncSetAttribute(tc_k<0,false,false,false,true, true, 1>, cudaFuncAttributeMaxDynamicSharedMemorySize, SMEMB);

    const long long Z0 = 0;

    // ---- weight pre-split ----
    split_k<<<(unsigned)(((long long)NL*3*HN*HN/4 + 255)/256), 256>>>(qkvw, wh + OFF_QKV, wl + OFF_QKV, (long long)NL*3*HN*HN/4);
    split_k<<<(unsigned)(((long long)NL*HN*HN/4 + 255)/256), 256>>>(outw, wh + OFF_OUT, wl + OFF_OUT, (long long)NL*HN*HN/4);
    transsplit_k<false><<<dim3(FFD/64, HN/64, NL), 256>>>(ffw1, FFD, wh + OFF_FF1, wl + OFF_FF1,
        HN, FFD, (long long)HN*FFD, Z0, (long long)HN*FFD, Z0, 1);
    transsplit_k<false><<<dim3(HN/64, FFD/64, NL), 256>>>(ffw2, HN, wh + OFF_FF2, wl + OFF_FF2,
        FFD, HN, (long long)FFD*HN, Z0, (long long)FFD*HN, Z0, 1);
    transsplit_k<false><<<dim3(EHD/64, HN/64, NL*NE), 256>>>(ew1, EHD, wh + OFF_E1, wl + OFF_E1,
        HN, EHD, (long long)HN*EHD, Z0, (long long)HN*EHD, Z0, 1);
    transsplit_k<false><<<dim3(HN/64, EHD/64, NL*NE), 256>>>(ew2, HN, wh + OFF_E2, wl + OFF_E2,
        EHD, HN, (long long)EHD*HN, Z0, (long long)EHD*HN, Z0, 1);
    transsplit_k<true><<<dim3(VS/64, HN/64, 1), 256>>>(lmw, VS, lmh, lml,
        HN, VS, Z0, Z0, Z0, Z0, 1);

    embed_k<<<TK, 256>>>(ids, emb, x, xh, xl);

    for (int l = 0; l < NL; l++) {
        // qkv = x @ Wqkv^T + b  -> big fp32 + bh/bl
        tc_k<0,false,false,true,true,false,3><<<dim3(3*HN/BN, TK/BM, 1), 512, SMEMB>>>(
            xh, xl, wh + OFF_QKV + (long long)l*3*HN*HN, wl + OFF_QKV + (long long)l*3*HN*HN,
            qkvb + (long long)l*3*HN, big, bh, bl, TK, 3*HN, HN, HN, HN, 3*HN,
            Z0,Z0,Z0,Z0,Z0,Z0,Z0, 0, 1.f, nullptr, nullptr);

        // V^T split per (b,h)
        transsplit_k<false><<<dim3(HDD/64, SS/64, BB*NHD), 256>>>(
            big + 2*HN, 3*HN, vth, vtl, SS, HDD,
            (long long)SS*3*HN, (long long)HDD,
            (long long)NHD*HDD*SS, (long long)HDD*SS, NHD);

        // scores = Q @ K^T / 16 -> sc fp32
        tc_k<0,false,false,false,true,false,3><<<dim3(SS/BN, SS/BM, BB*NHD), 512, SMEMB>>>(
            bh, bl, bh + HN, bl + HN, nullptr, sc, nullptr, nullptr,
            SS, SS, HDD, 3*HN, 3*HN, SS,
            (long long)SS*3*HN, (long long)HDD,
            (long long)SS*3*HN, (long long)HDD,
            (long long)NHD*SS*SS, (long long)SS*SS, Z0, NHD,
            0.0625f, nullptr, nullptr);

        softmax_k<<<BB*NHD*SS, 256>>>(sc, ph, pl);

        // ao = probs @ V -> t1h/t1l
        tc_k<0,false,false,true,false,false,3><<<dim3(HDD/BN, SS/BM, BB*NHD), 512, SMEMB>>>(
            ph, pl, vth, vtl, nullptr, nullptr, t1h, t1l,
            SS, HDD, SS, SS, SS, HN,
            (long long)NHD*SS*SS, (long long)SS*SS,
            (long long)NHD*HDD*SS, (long long)HDD*SS,
            (long long)SS*HN, (long long)HDD, Z0, NHD,
            1.f, nullptr, nullptr);

        // proj = ao @ Wout^T + b -> big fp32
        tc_k<0,false,false,false,true,false,3><<<dim3(HN/BN, TK/BM, 1), 512, SMEMB>>>(
            t1h, t1l, wh + OFF_OUT + (long long)l*HN*HN, wl + OFF_OUT + (long long)l*HN*HN,
            outb + (long long)l*HN, big, nullptr, nullptr, TK, HN, HN, HN, HN, HN,
            Z0,Z0,Z0,Z0,Z0,Z0,Z0, 0, 1.f, nullptr, nullptr);

        ln_k<<<TK,256>>>(x, big, ln1g + (long long)l*HN, ln1b + (long long)l*HN, x, xh, xl);

        // ffn
        tc_k<1,false,false,true,false,false,3><<<dim3(FFD/BN, TK/BM, 1), 512, SMEMB>>>(
            xh, xl, wh + OFF_FF1 + (long long)l*HN*FFD, wl + OFF_FF1 + (long long)l*HN*FFD,
            ffb1 + (long long)l*FFD, nullptr, bh, bl, TK, FFD, HN, HN, HN, FFD,
            Z0,Z0,Z0,Z0,Z0,Z0,Z0, 0, 1.f, nullptr, nullptr);
        tc_k<0,false,false,false,true,false,3><<<dim3(HN/BN, TK/BM, 1), 512, SMEMB>>>(
            bh, bl, wh + OFF_FF2 + (long long)l*FFD*HN, wl + OFF_FF2 + (long long)l*FFD*HN,
            ffb2 + (long long)l*HN, t1, nullptr, nullptr, TK, HN, FFD, FFD, FFD, HN,
            Z0,Z0,Z0,Z0,Z0,Z0,Z0, 0, 1.f, nullptr, nullptr);

        ln_k<<<TK,256>>>(x, t1, ln2g + (long long)l*HN, ln2b + (long long)l*HN, x, xh, xl);

        // MoE
        cudaMemsetAsync(cnt, 0, NE*sizeof(int));
        gate_k<<<TK,256>>>(x, gw + (long long)l*HN*NE, gb + (long long)l*NE, cnt, tok);
        cudaMemsetAsync(t1, 0, (size_t)TK*HN*sizeof(float));

        // up: ehh/ehl[e] = relu(x[gather] @ W1_e + b1_e)
        tc_k<2,true,false,true,false,false,3><<<dim3(EHD/BN, TK/BM, NE), 512, SMEMB>>>(
            xh, xl, wh + OFF_E1 + (long long)l*NE*HN*EHD, wl + OFF_E1 + (long long)l*NE*HN*EHD,
            eb1 + (long long)l*NE*EHD, nullptr, ehh, ehl, TK, EHD, HN, HN, HN, EHD,
            Z0, Z0, (long long)EHD*HN, Z0, (long long)TK*EHD, Z0, (long long)EHD, 1,
            1.f, tok, cnt);
        // down: t1[token] += eh[e] @ W2_e + b2_e  (atomic scatter)
        tc_k<0,false,true,false,false,false,3><<<dim3(HN/BN, TK/BM, NE), 512, SMEMB>>>(
            ehh, ehl, wh + OFF_E2 + (long long)l*NE*EHD*HN, wl + OFF_E2 + (long long)l*NE*EHD*HN,
            eb2 + (long long)l*NE*HN, t1, nullptr, nullptr, TK, HN, EHD, EHD, EHD, HN,
            (long long)TK*EHD, Z0, (long long)HN*EHD, Z0, Z0, Z0, (long long)HN, 1,
            1.f, tok, cnt);

        copysplit_k<<<(TK*HN/4)/256, 256>>>(x, xh, xl, t1, (long long)TK*HN/4);
    }

    // lm head: pure fp16 1-term (A = fp16(x); B = fp16(W)), M-inner rasterization
    xtohalf_k<<<(TK*HN/4)/256, 256>>>(x, xf, (long long)TK*HN/4);
    tc_k<0,false,false,false,true,true,1><<<dim3(TK/BM, VS/BN, 1), 512, SMEMB>>>(
        (const __nv_bfloat16*)xf, (const __nv_bfloat16*)xf,
        (const __nv_bfloat16*)lmh, (const __nv_bfloat16*)lml,
        lmb, out, nullptr, nullptr,
        TK, VS, HN, HN, HN, VS,
        Z0,Z0,Z0,Z0,Z0,Z0,Z0, 0, 1.f, nullptr, nullptr);
}

// round 15
// speedup vs baseline: 3.9616x; 1.0338x over previous
#include <cuda_runtime.h>
#include <cuda_bf16.h>
#include <cuda_fp16.h>
#include <math.h>

// ---------------- problem constants ----------------
#define TK   4096
#define HN   1024
#define NHD  4
#define HDD  256
#define BB   4
#define SS   1024
#define FFD  4096
#define NE   8
#define EHD  2048
#define VS   32000
#define NL   2

// ---------------- split-weight offsets (elements) ----------------
#define OFF_QKV 0LL
#define OFF_OUT  (OFF_QKV + (long long)NL*3*HN*HN)
#define OFF_FF1  (OFF_OUT + (long long)NL*HN*HN)
#define OFF_FF2  (OFF_FF1 + (long long)NL*HN*FFD)
#define OFF_E1   (OFF_FF2 + (long long)NL*FFD*HN)
#define OFF_E2   (OFF_E1  + (long long)NL*NE*HN*EHD)
#define TOTW     (OFF_E2  + (long long)NL*NE*EHD*HN)

// ---------------- scratch ----------------
__device__ float g_x  [(size_t)TK*HN];
__device__ float g_t1 [(size_t)TK*HN];
__device__ float g_big[(size_t)TK*FFD];
__device__ float g_sc [(size_t)BB*NHD*SS*SS];
__device__ int   g_cnt[NE];
__device__ int   g_tok[NE*TK];
__device__ __nv_bfloat16 g_wh[TOTW];
__device__ __nv_bfloat16 g_wl[TOTW];
__device__ __nv_bfloat16 g_vth[(size_t)BB*NHD*HDD*SS];
__device__ __nv_bfloat16 g_vtl[(size_t)BB*NHD*HDD*SS];
// split activations
__device__ __nv_bfloat16 g_xh [(size_t)TK*HN];
__device__ __nv_bfloat16 g_xl [(size_t)TK*HN];
__device__ __nv_bfloat16 g_bh [(size_t)TK*FFD];
__device__ __nv_bfloat16 g_bl [(size_t)TK*FFD];
__device__ __nv_bfloat16 g_ph [(size_t)BB*NHD*SS*SS];
__device__ __nv_bfloat16 g_pl [(size_t)BB*NHD*SS*SS];
__device__ __nv_bfloat16 g_ehh[(size_t)NE*TK*EHD];
__device__ __nv_bfloat16 g_ehl[(size_t)NE*TK*EHD];
__device__ __nv_bfloat16 g_t1h[(size_t)TK*HN];
__device__ __nv_bfloat16 g_t1l[(size_t)TK*HN];
// fp16 paths
__device__ __half g_lmh[(size_t)HN*VS];
__device__ __half g_lml[(size_t)HN*VS];
__device__ __half g_xf [(size_t)TK*HN];
__device__ __half g_e1h[(size_t)NE*HN*EHD];   // layer-2 expert W1 fp16 hi/lo
__device__ __half g_e1l[(size_t)NE*HN*EHD];
__device__ __half g_e2h[(size_t)NE*EHD*HN];   // layer-2 expert W2 fp16 hi/lo
__device__ __half g_e2l[(size_t)NE*EHD*HN];
__device__ __half g_ehf[(size_t)NE*TK*EHD];   // layer-2 hidden fp16

// ================= helpers =================
__device__ __forceinline__ unsigned smem_u32(const void* p){
    unsigned a;
    asm("{ .reg .u64 t; cvta.to.shared.u64 t, %1; cvt.u32.u64 %0, t; }" : "=r"(a) : "l"(p));
    return a;
}
__device__ __forceinline__ void split1(float v, __nv_bfloat16& h, __nv_bfloat16& l) {
    h = __float2bfloat16(v);
    l = __float2bfloat16(v - __bfloat162float(h));
}
__device__ __forceinline__ void split2w(float v0, float v1, unsigned& hw, unsigned& lw) {
    __nv_bfloat16 h0, l0, h1, l1;
    split1(v0, h0, l0); split1(v1, h1, l1);
    hw = (unsigned)__bfloat16_as_ushort(h0) | ((unsigned)__bfloat16_as_ushort(h1) << 16);
    lw = (unsigned)__bfloat16_as_ushort(l0) | ((unsigned)__bfloat16_as_ushort(l1) << 16);
}
__device__ __forceinline__ void split2wh(float v0, float v1, unsigned& hw, unsigned& lw) {
    __half h0 = __float2half(v0), h1 = __float2half(v1);
    __half l0 = __float2half(v0 - __half2float(h0));
    __half l1 = __float2half(v1 - __half2float(h1));
    hw = (unsigned)__half_as_ushort(h0) | ((unsigned)__half_as_ushort(h1) << 16);
    lw = (unsigned)__half_as_ushort(l0) | ((unsigned)__half_as_ushort(l1) << 16);
}

#define LDSM_X4(r0, r1, r2, r3, a) \
    asm volatile("ldmatrix.sync.aligned.m8n8.x4.shared.b16 {%0,%1,%2,%3}, [%4];" \
                 : "=r"(r0), "=r"(r1), "=r"(r2), "=r"(r3) : "r"(a))
#define MMA16816(d, a, b) \
    asm volatile("mma.sync.aligned.m16n8k16.row.col.f32.bf16.bf16.f32 " \
                 "{%0,%1,%2,%3}, {%4,%5,%6,%7}, {%8,%9}, {%0,%1,%2,%3};" \
                 : "+f"((d)[0]), "+f"((d)[1]), "+f"((d)[2]), "+f"((d)[3]) \
                 : "r"((a)[0]), "r"((a)[1]), "r"((a)[2]), "r"((a)[3]), \
                   "r"((b)[0]), "r"((b)[1]))
#define MMA16816H(d, a, b) \
    asm volatile("mma.sync.aligned.m16n8k16.row.col.f32.f16.f16.f32 " \
                 "{%0,%1,%2,%3}, {%4,%5,%6,%7}, {%8,%9}, {%0,%1,%2,%3};" \
                 : "+f"((d)[0]), "+f"((d)[1]), "+f"((d)[2]), "+f"((d)[3]) \
                 : "r"((a)[0]), "r"((a)[1]), "r"((a)[2]), "r"((a)[3]), \
                   "r"((b)[0]), "r"((b)[1]))
#define CP_ASYNC16(sa, gp) \
    asm volatile("cp.async.cg.shared.global [%0], [%1], 16;" :: "r"(sa), "l"(gp) : "memory")
#define CP_COMMIT() asm volatile("cp.async.commit_group;" ::: "memory")
#define CP_WAIT1()  asm volatile("cp.async.wait_group 1;" ::: "memory")
#define CP_WAIT0()  asm volatile("cp.async.wait_group 0;" ::: "memory")

// ================= bf16x3 / fp16x2 / fp16x1 MMA GEMM (cp.async 3-stage) ======
#define BM 128
#define BN 256
#define KC 32
#define ROWB 80
#define RG_AL 10240
#define RG_BH 20480
#define RG_BL 40960
#define STGB  61440
#define NSTG  3
#define SMEMB (NSTG*STGB)

template<int ACT, bool GATHER, bool SCATTER, bool OSPLIT, bool OF32, bool SWAP, int TERMS, bool OHALF>
__global__ void __launch_bounds__(512, 1)
tc_k(const __nv_bfloat16* __restrict__ Ah, const __nv_bfloat16* __restrict__ Al,
     const __nv_bfloat16* __restrict__ Bh, const __nv_bfloat16* __restrict__ Bl,
     const float* __restrict__ bias,
     float* __restrict__ C, __nv_bfloat16* __restrict__ Ch, __nv_bfloat16* __restrict__ Cl,
     int M, int N, int Kd, int lda, int ldb, int ldc,
     long long sAb, long long sAh_, long long sBb, long long sBh_,
     long long sCb, long long sCh_, long long sBias, int nh, float alpha,
     const int* __restrict__ ridx, const int* __restrict__ cptr)
{
    if (nh > 0) {
        int z = blockIdx.z, zb = z / nh, zh = z % nh;
        long long ao = zb*sAb + zh*sAh_;
        Ah += ao; Al += ao;
        long long bo = zb*sBb + zh*sBh_;
        Bh += bo; Bl += bo;
        long long co = zb*sCb + zh*sCh_;
        if (OF32 || SCATTER) C += co;
        if (OSPLIT || OHALF) { Ch += co; Cl += co; }
        if (bias) bias += zb*sBias;
        if (GATHER || SCATTER) ridx += (long long)zb*TK;
        if (cptr) cptr += zb;
    }
    if (cptr) M = *cptr;
    int m0 = SWAP ? blockIdx.x*BM : blockIdx.y*BM;
    int n0 = SWAP ? blockIdx.y*BN : blockIdx.x*BN;
    if (m0 >= M) return;

    extern __shared__ char sm[];
    unsigned sb = smem_u32(sm);
    int tid = threadIdx.x, lane = tid & 31, wid = tid >> 5;
    int wm = wid & 1, wn = wid >> 1;       // 2 x 8 warp grid; warp tile 64x32

    float acc[4][4][4];
#pragma unroll
    for (int i = 0; i < 4; i++)
#pragma unroll
        for (int j = 0; j < 4; j++)
#pragma unroll
            for (int e = 0; e < 4; e++) acc[i][j][e] = 0.f;

    int lr = tid >> 2, lc = tid & 3;
    long long arow;
    { int gm = m0 + lr; if (gm >= M) gm = M - 1;
      arow = GATHER ? (long long)ridx[gm] : (long long)gm; }
    const __nv_bfloat16* pAh  = Ah + arow*lda + lc*8;
    const __nv_bfloat16* pAl  = Al + arow*lda + lc*8;
    const __nv_bfloat16* pBh0 = Bh + (long long)(n0 + lr)*ldb + lc*8;
    const __nv_bfloat16* pBl0 = Bl + (long long)(n0 + lr)*ldb + lc*8;
    const __nv_bfloat16* pBh1 = pBh0 + (long long)128*ldb;
    const __nv_bfloat16* pBl1 = pBl0 + (long long)128*ldb;
    unsigned offR = (unsigned)lr*ROWB + (unsigned)lc*16;

    int NC = Kd / KC;

    auto issue = [&](int s) {
        unsigned base = sb + (unsigned)(s % NSTG)*STGB;
        int k0 = s*KC;
        CP_ASYNC16(base + offR,                 pAh  + k0);
        if (TERMS == 3)
            CP_ASYNC16(base + RG_AL + offR,     pAl  + k0);
        CP_ASYNC16(base + RG_BH + offR,         pBh0 + k0);
        CP_ASYNC16(base + RG_BH + 10240 + offR, pBh1 + k0);
        if (TERMS >= 2) {
            CP_ASYNC16(base + RG_BL + offR,         pBl0 + k0);
            CP_ASYNC16(base + RG_BL + 10240 + offR, pBl1 + k0);
        }
        CP_COMMIT();
    };

    issue(0);
    if (NC > 1) issue(1);

    unsigned aoff = (unsigned)(lane & 15)*ROWB + (unsigned)(lane >> 4)*16;
    unsigned boff = (unsigned)(lane & 7)*ROWB + (unsigned)((lane >> 3) & 1)*16
                  + (unsigned)(lane >> 4)*(8*ROWB);

    for (int i = 0; i < NC; i++) {
        if (i + 1 < NC) { CP_WAIT1(); } else { CP_WAIT0(); }
        __syncthreads();
        if (i + 2 < NC) issue(i + 2);

        unsigned st = sb + (unsigned)(i % NSTG)*STGB;
        unsigned abase = st + (unsigned)(wm*64)*ROWB;
        unsigned bbase = st + RG_BH + (unsigned)(wn*32)*ROWB;
#pragma unroll
        for (int ks = 0; ks < 2; ks++) {
            unsigned ah[4][4], al[4][4], bh[4][2], bl[4][2];
#pragma unroll
            for (int mt = 0; mt < 4; mt++) {
                unsigned ad = abase + (unsigned)(mt*16)*ROWB + aoff + ks*32;
                LDSM_X4(ah[mt][0], ah[mt][1], ah[mt][2], ah[mt][3], ad);
                if (TERMS == 3)
                    LDSM_X4(al[mt][0], al[mt][1], al[mt][2], al[mt][3], ad + RG_AL);
            }
#pragma unroll
            for (int nt = 0; nt < 4; nt += 2) {
                unsigned bd = bbase + (unsigned)(nt*8)*ROWB + boff + ks*32;
                LDSM_X4(bh[nt][0], bh[nt][1], bh[nt+1][0], bh[nt+1][1], bd);
                if (TERMS >= 2)
                    LDSM_X4(bl[nt][0], bl[nt][1], bl[nt+1][0], bl[nt+1][1], bd + (RG_BL - RG_BH));
            }
#pragma unroll
            for (int mt = 0; mt < 4; mt++)
#pragma unroll
                for (int nt = 0; nt < 4; nt++) {
                    if (TERMS == 3) {
                        MMA16816(acc[mt][nt], ah[mt], bh[nt]);
                        MMA16816(acc[mt][nt], ah[mt], bl[nt]);
                        MMA16816(acc[mt][nt], al[mt], bh[nt]);
                    } else if (TERMS == 2) {
                        MMA16816H(acc[mt][nt], ah[mt], bh[nt]);
                        MMA16816H(acc[mt][nt], ah[mt], bl[nt]);
                    } else {
                        MMA16816H(acc[mt][nt], ah[mt], bh[nt]);
                    }
                }
        }
    }

    // ---- epilogue ----
#pragma unroll
    for (int mt = 0; mt < 4; mt++) {
#pragma unroll
        for (int half = 0; half < 2; half++) {
            int gm = m0 + wm*64 + mt*16 + (lane >> 2) + half*8;
            if (gm >= M) continue;
            long long crow = SCATTER ? (long long)ridx[gm]*ldc : (long long)gm*ldc;
#pragma unroll
            for (int nt = 0; nt < 4; nt++) {
                int gn = n0 + wn*32 + nt*8 + (lane & 3)*2;
                float v0 = acc[mt][nt][half*2 + 0] * alpha;
                float v1 = acc[mt][nt][half*2 + 1] * alpha;
                if (bias) { v0 += bias[gn]; v1 += bias[gn+1]; }
                if (ACT == 1) {
                    v0 = 0.5f*v0*(1.0f + erff(v0*0.7071067811865475f));
                    v1 = 0.5f*v1*(1.0f + erff(v1*0.7071067811865475f));
                } else if (ACT == 2) {
                    v0 = v0 > 0.f ? v0 : 0.f;
                    v1 = v1 > 0.f ? v1 : 0.f;
                }
                if (SCATTER) {
                    atomicAdd(C + crow + gn,     v0);
                    atomicAdd(C + crow + gn + 1, v1);
                } else {
                    if (OF32) *(float2*)(C + crow + gn) = make_float2(v0, v1);
                    if (OSPLIT) {
                        unsigned hw, lw; split2w(v0, v1, hw, lw);
                        *(unsigned*)(Ch + crow + gn) = hw;
                        *(unsigned*)(Cl + crow + gn) = lw;
                    }
                    if (OHALF) {
                        __half2 hv = __floats2half2_rn(v0, v1);
                        *(unsigned*)((__half*)Ch + crow + gn) = *(unsigned*)&hv;
                    }
                }
            }
        }
    }
}

// ================= weight prep (bandwidth-optimized) =================
__global__ void split_k(const float* __restrict__ W, __nv_bfloat16* __restrict__ hi,
                        __nv_bfloat16* __restrict__ lo, long long n4) {
    long long i = (long long)blockIdx.x*256 + threadIdx.x;
    if (i >= n4) return;
    float4 v = ((const float4*)W)[i];
    unsigned h0, l0, h1, l1;
    split2w(v.x, v.y, h0, l0); split2w(v.z, v.w, h1, l1);
    ((uint2*)hi)[i] = make_uint2(h0, h1);
    ((uint2*)lo)[i] = make_uint2(l0, l1);
}
// out[N,K] = split(W[K,N]), 64x64 tiles; HALFOUT selects fp16 vs bf16 split.
template<bool HALFOUT>
__global__ void transsplit_k(const float* __restrict__ W, int ldw,
                             void* __restrict__ hip, void* __restrict__ lop,
                             int Kd, int Nd, long long sWb, long long sWh,
                             long long sOb, long long sOh, int nhz) {
    int z = blockIdx.z, zb = z / nhz, zh = z % nhz;
    W += zb*sWb + zh*sWh;
    __nv_bfloat16* hi = (__nv_bfloat16*)hip + zb*sOb + zh*sOh;
    __nv_bfloat16* lo = (__nv_bfloat16*)lop + zb*sOb + zh*sOh;
    __shared__ float ts[64][65];
    int n0 = blockIdx.x*64, k0 = blockIdx.y*64;
    int tid = threadIdx.x;                     // 256
    {
        int rr = tid >> 4, c4 = (tid & 15)*4;
#pragma unroll
        for (int it = 0; it < 4; it++) {
            int r = rr + it*16;
            float4 v = *(const float4*)(W + (long long)(k0 + r)*ldw + n0 + c4);
            ts[r][c4+0] = v.x; ts[r][c4+1] = v.y; ts[r][c4+2] = v.z; ts[r][c4+3] = v.w;
        }
    }
    __syncthreads();
    int nb = tid >> 4, kq = (tid & 15)*4;
#pragma unroll
    for (int it = 0; it < 4; it++) {
        int nn = nb + it*16;
        float a = ts[kq+0][nn], b = ts[kq+1][nn];
        float c = ts[kq+2][nn], d = ts[kq+3][nn];
        unsigned h0, l0, h1, l1;
        if (HALFOUT) { split2wh(a, b, h0, l0); split2wh(c, d, h1, l1); }
        else         { split2w (a, b, h0, l0); split2w (c, d, h1, l1); }
        long long o = (long long)(n0 + nn)*Kd + k0 + kq;
        *(uint2*)(hi + o) = make_uint2(h0, h1);
        *(uint2*)(lo + o) = make_uint2(l0, l1);
    }
}

// ================= block reduce helpers (smem broadcast) =================
__device__ __forceinline__ float blk_sum(float v, float* red, int tid) {
#pragma unroll
    for (int o = 16; o > 0; o >>= 1) v += __shfl_xor_sync(0xffffffffu, v, o);
    if ((tid & 31) == 0) red[tid >> 5] = v;
    __syncthreads();
    if (tid < 32) {
        float s = (tid < 8) ? red[tid] : 0.f;
#pragma unroll
        for (int o = 4; o > 0; o >>= 1) s += __shfl_xor_sync(0xffffffffu, s, o);
        if (tid == 0) red[0] = s;
    }
    __syncthreads();
    float r = red[0];
    __syncthreads();
    return r;
}
__device__ __forceinline__ float blk_max(float v, float* red, int tid) {
#pragma unroll
    for (int o = 16; o > 0; o >>= 1) v = fmaxf(v, __shfl_xor_sync(0xffffffffu, v, o));
    if ((tid & 31) == 0) red[tid >> 5] = v;
    __syncthreads();
    if (tid < 32) {
        float s = (tid < 8) ? red[tid] : -1e30f;
#pragma unroll
        for (int o = 4; o > 0; o >>= 1) s = fmaxf(s, __shfl_xor_sync(0xffffffffu, s, o));
        if (tid == 0) red[0] = s;
    }
    __syncthreads();
    float r = red[0];
    __syncthreads();
    return r;
}

// ================= misc kernels (vectorized) =================
__global__ void embed_k(const int* __restrict__ ids, const float* __restrict__ emb,
                        float* __restrict__ out,
                        __nv_bfloat16* __restrict__ oh, __nv_bfloat16* __restrict__ ol) {
    long long t = blockIdx.x;
    int tid = threadIdx.x;
    float4 v = ((const float4*)(emb + (size_t)ids[t]*HN))[tid];
    ((float4*)(out + t*HN))[tid] = v;
    unsigned h0, l0, h1, l1;
    split2w(v.x, v.y, h0, l0); split2w(v.z, v.w, h1, l1);
    ((uint2*)(oh + t*HN))[tid] = make_uint2(h0, h1);
    ((uint2*)(ol + t*HN))[tid] = make_uint2(l0, l1);
}
__global__ void softmax_k(const float* __restrict__ p,
                          __nv_bfloat16* __restrict__ oh, __nv_bfloat16* __restrict__ ol) {
    long long row = blockIdx.x;
    int tid = threadIdx.x;
    __shared__ float red[8];
    float4 v = ((const float4*)(p + row*SS))[tid];
    float mx = blk_max(fmaxf(fmaxf(v.x, v.y), fmaxf(v.z, v.w)), red, tid);
    v.x = expf(v.x - mx); v.y = expf(v.y - mx); v.z = expf(v.z - mx); v.w = expf(v.w - mx);
    float inv = 1.f / blk_sum(v.x + v.y + v.z + v.w, red, tid);
    v.x *= inv; v.y *= inv; v.z *= inv; v.w *= inv;
    unsigned h0, l0, h1, l1;
    split2w(v.x, v.y, h0, l0); split2w(v.z, v.w, h1, l1);
    ((uint2*)(oh + row*SS))[tid] = make_uint2(h0, h1);
    ((uint2*)(ol + row*SS))[tid] = make_uint2(l0, l1);
}
__global__ void ln_k(const float* __restrict__ resid, const float* __restrict__ delta,
                     const float* __restrict__ g, const float* __restrict__ b,
                     float* __restrict__ out,
                     __nv_bfloat16* __restrict__ oh, __nv_bfloat16* __restrict__ ol) {
    long long t = blockIdx.x;
    int tid = threadIdx.x;
    __shared__ float red[8];
    float4 r = ((const float4*)(resid + t*HN))[tid];
    float4 d = ((const float4*)(delta + t*HN))[tid];
    float4 v = make_float4(r.x + d.x, r.y + d.y, r.z + d.z, r.w + d.w);
    float m = blk_sum(v.x + v.y + v.z + v.w, red, tid) * (1.0f/HN);
    float4 c = make_float4(v.x - m, v.y - m, v.z - m, v.w - m);
    float var = blk_sum(c.x*c.x + c.y*c.y + c.z*c.z + c.w*c.w, red, tid) * (1.0f/HN);
    float inv = rsqrtf(var + 1e-5f);
    float4 gg = ((const float4*)g)[tid];
    float4 bb = ((const float4*)b)[tid];
    float4 o = make_float4(c.x*inv*gg.x + bb.x, c.y*inv*gg.y + bb.y,
                           c.z*inv*gg.z + bb.z, c.w*inv*gg.w + bb.w);
    ((float4*)(out + t*HN))[tid] = o;
    unsigned h0, l0, h1, l1;
    split2w(o.x, o.y, h0, l0); split2w(o.z, o.w, h1, l1);
    ((uint2*)(oh + t*HN))[tid] = make_uint2(h0, h1);
    ((uint2*)(ol + t*HN))[tid] = make_uint2(l0, l1);
}
__global__ void gate_k(const float* __restrict__ x, const float* __restrict__ gw,
                       const float* __restrict__ gb, int* __restrict__ cnt,
                       int* __restrict__ toks) {
    int t = blockIdx.x;
    int tid = threadIdx.x;
    __shared__ float xs[HN];
    __shared__ float red[256];
    for (int i = tid; i < HN; i += 256) xs[i] = x[(long long)t*HN+i];
    __syncthreads();
    int e = tid & 7, g = tid >> 3;
    float p = 0.f;
    for (int j = g; j < HN; j += 32) p += xs[j]*gw[j*NE+e];
    red[tid] = p; __syncthreads();
    if (tid < 8) {
        float s = 0.f;
        for (int j = 0; j < 32; j++) s += red[j*8 + tid];
        red[tid] = s + gb[tid];
    }
    __syncthreads();
    if (tid == 0) {
        float l[NE];
        for (int i = 0; i < NE; i++) l[i] = red[i];
        int i1 = 0;
        for (int i = 1; i < NE; i++) if (l[i] > l[i1]) i1 = i;
        int i2 = (i1 == 0) ? 1 : 0;
        for (int i = 0; i < NE; i++) if (i != i1 && l[i] > l[i2]) i2 = i;
        int p1 = atomicAdd(&cnt[i1], 1); toks[i1*TK+p1] = t;
        int p2 = atomicAdd(&cnt[i2], 1); toks[i2*TK+p2] = t;
    }
}
__global__ void copysplit_k(float* __restrict__ dst, __nv_bfloat16* __restrict__ oh,
                            __nv_bfloat16* __restrict__ ol, const float* __restrict__ src,
                            long long n4) {
    long long i = (long long)blockIdx.x*blockDim.x + threadIdx.x;
    if (i >= n4) return;
    float4 v = ((const float4*)src)[i];
    ((float4*)dst)[i] = v;
    unsigned h0, l0, h1, l1;
    split2w(v.x, v.y, h0, l0); split2w(v.z, v.w, h1, l1);
    ((uint2*)oh)[i] = make_uint2(h0, h1);
    ((uint2*)ol)[i] = make_uint2(l0, l1);
}
__global__ void xtohalf_k(const float* __restrict__ src, __half* __restrict__ dst,
                          long long n4) {
    long long i = (long long)blockIdx.x*blockDim.x + threadIdx.x;
    if (i >= n4) return;
    float4 v = ((const float4*)src)[i];
    __half2 a = __floats2half2_rn(v.x, v.y);
    __half2 b = __floats2half2_rn(v.z, v.w);
    ((uint2*)dst)[i] = make_uint2(*(unsigned*)&a, *(unsigned*)&b);
}

// ================= launch =================
extern "C" void kernel_launch(void* const* d_in, const int* in_sizes, int n_in,
                              void* d_out, int out_size)
{
    const int*   ids   = (const int*)d_in[0];
    const float* emb   = (const float*)d_in[1];
    const float* qkvw  = (const float*)d_in[2];
    const float* qkvb  = (const float*)d_in[3];
    const float* outw  = (const float*)d_in[4];
    const float* outb  = (const float*)d_in[5];
    const float* ln1g  = (const float*)d_in[6];
    const float* ln1b  = (const float*)d_in[7];
    const float* ffw1  = (const float*)d_in[8];
    const float* ffb1  = (const float*)d_in[9];
    const float* ffw2  = (const float*)d_in[10];
    const float* ffb2  = (const float*)d_in[11];
    const float* ln2g  = (const float*)d_in[12];
    const float* ln2b  = (const float*)d_in[13];
    const float* gw    = (const float*)d_in[14];
    const float* gb    = (const float*)d_in[15];
    const float* ew1   = (const float*)d_in[16];
    const float* eb1   = (const float*)d_in[17];
    const float* ew2   = (const float*)d_in[18];
    const float* eb2   = (const float*)d_in[19];
    const float* lmw   = (const float*)d_in[20];
    const float* lmb   = (const float*)d_in[21];
    float* out = (float*)d_out;

    float *x, *t1, *big, *sc; int *cnt, *tok;
    __nv_bfloat16 *wh, *wl, *vth, *vtl, *xh, *xl, *bh, *bl, *ph, *pl, *ehh, *ehl, *t1h, *t1l;
    __half *lmh, *lml, *xf, *e1h, *e1l, *e2h, *e2l, *ehf;
    cudaGetSymbolAddress((void**)&x,   g_x);
    cudaGetSymbolAddress((void**)&t1,  g_t1);
    cudaGetSymbolAddress((void**)&big, g_big);
    cudaGetSymbolAddress((void**)&sc,  g_sc);
    cudaGetSymbolAddress((void**)&cnt, g_cnt);
    cudaGetSymbolAddress((void**)&tok, g_tok);
    cudaGetSymbolAddress((void**)&wh,  g_wh);
    cudaGetSymbolAddress((void**)&wl,  g_wl);
    cudaGetSymbolAddress((void**)&vth, g_vth);
    cudaGetSymbolAddress((void**)&vtl, g_vtl);
    cudaGetSymbolAddress((void**)&xh,  g_xh);
    cudaGetSymbolAddress((void**)&xl,  g_xl);
    cudaGetSymbolAddress((void**)&bh,  g_bh);
    cudaGetSymbolAddress((void**)&bl,  g_bl);
    cudaGetSymbolAddress((void**)&ph,  g_ph);
    cudaGetSymbolAddress((void**)&pl,  g_pl);
    cudaGetSymbolAddress((void**)&ehh, g_ehh);
    cudaGetSymbolAddress((void**)&ehl, g_ehl);
    cudaGetSymbolAddress((void**)&t1h, g_t1h);
    cudaGetSymbolAddress((void**)&t1l, g_t1l);
    cudaGetSymbolAddress((void**)&lmh, g_lmh);
    cudaGetSymbolAddress((void**)&lml, g_lml);
    cudaGetSymbolAddress((void**)&xf,  g_xf);
    cudaGetSymbolAddress((void**)&e1h, g_e1h);
    cudaGetSymbolAddress((void**)&e1l, g_e1l);
    cudaGetSymbolAddress((void**)&e2h, g_e2h);
    cudaGetSymbolAddress((void**)&e2l, g_e2l);
    cudaGetSymbolAddress((void**)&ehf, g_ehf);

    cudaFuncSetAttribute(tc_k<0,false,false,true, true, false,3,false>, cudaFuncAttributeMaxDynamicSharedMemorySize, SMEMB);
    cudaFuncSetAttribute(tc_k<0,false,false,false,true, false,3,false>, cudaFuncAttributeMaxDynamicSharedMemorySize, SMEMB);
    cudaFuncSetAttribute(tc_k<0,false,false,true, false,false,3,false>, cudaFuncAttributeMaxDynamicSharedMemorySize, SMEMB);
    cudaFuncSetAttribute(tc_k<1,false,false,true, false,false,3,false>, cudaFuncAttributeMaxDynamicSharedMemorySize, SMEMB);
    cudaFuncSetAttribute(tc_k<2,true, false,true, false,false,3,false>, cudaFuncAttributeMaxDynamicSharedMemorySize, SMEMB);
    cudaFuncSetAttribute(tc_k<0,false,true, false,false,false,3,false>, cudaFuncAttributeMaxDynamicSharedMemorySize, SMEMB);
    cudaFuncSetAttribute(tc_k<0,false,false,false,true, true, 1,false>, cudaFuncAttributeMaxDynamicSharedMemorySize, SMEMB);
    cudaFuncSetAttribute(tc_k<2,true, false,false,false,false,2,true >, cudaFuncAttributeMaxDynamicSharedMemorySize, SMEMB);
    cudaFuncSetAttribute(tc_k<0,false,true, false,false,false,2,false>, cudaFuncAttributeMaxDynamicSharedMemorySize, SMEMB);

    const long long Z0 = 0;

    // ---- weight pre-split ----
    split_k<<<(unsigned)(((long long)NL*3*HN*HN/4 + 255)/256), 256>>>(qkvw, wh + OFF_QKV, wl + OFF_QKV, (long long)NL*3*HN*HN/4);
    split_k<<<(unsigned)(((long long)NL*HN*HN/4 + 255)/256), 256>>>(outw, wh + OFF_OUT, wl + OFF_OUT, (long long)NL*HN*HN/4);
    transsplit_k<false><<<dim3(FFD/64, HN/64, NL), 256>>>(ffw1, FFD, wh + OFF_FF1, wl + OFF_FF1,
        HN, FFD, (long long)HN*FFD, Z0, (long long)HN*FFD, Z0, 1);
    transsplit_k<false><<<dim3(HN/64, FFD/64, NL), 256>>>(ffw2, HN, wh + OFF_FF2, wl + OFF_FF2,
        FFD, HN, (long long)FFD*HN, Z0, (long long)FFD*HN, Z0, 1);
    // layer-1 expert weights: bf16 hi/lo
    transsplit_k<false><<<dim3(EHD/64, HN/64, NE), 256>>>(ew1, EHD, wh + OFF_E1, wl + OFF_E1,
        HN, EHD, (long long)HN*EHD, Z0, (long long)HN*EHD, Z0, 1);
    transsplit_k<false><<<dim3(HN/64, EHD/64, NE), 256>>>(ew2, HN, wh + OFF_E2, wl + OFF_E2,
        EHD, HN, (long long)EHD*HN, Z0, (long long)EHD*HN, Z0, 1);
    // layer-2 expert weights: fp16 hi/lo
    transsplit_k<true><<<dim3(EHD/64, HN/64, NE), 256>>>(ew1 + (long long)NE*HN*EHD, EHD, e1h, e1l,
        HN, EHD, (long long)HN*EHD, Z0, (long long)HN*EHD, Z0, 1);
    transsplit_k<true><<<dim3(HN/64, EHD/64, NE), 256>>>(ew2 + (long long)NE*EHD*HN, HN, e2h, e2l,
        EHD, HN, (long long)EHD*HN, Z0, (long long)EHD*HN, Z0, 1);
    transsplit_k<true><<<dim3(VS/64, HN/64, 1), 256>>>(lmw, VS, lmh, lml,
        HN, VS, Z0, Z0, Z0, Z0, 1);

    embed_k<<<TK, 256>>>(ids, emb, x, xh, xl);

    for (int l = 0; l < NL; l++) {
        // qkv = x @ Wqkv^T + b  -> big fp32 + bh/bl
        tc_k<0,false,false,true,true,false,3,false><<<dim3(3*HN/BN, TK/BM, 1), 512, SMEMB>>>(
            xh, xl, wh + OFF_QKV + (long long)l*3*HN*HN, wl + OFF_QKV + (long long)l*3*HN*HN,
            qkvb + (long long)l*3*HN, big, bh, bl, TK, 3*HN, HN, HN, HN, 3*HN,
            Z0,Z0,Z0,Z0,Z0,Z0,Z0, 0, 1.f, nullptr, nullptr);

        // V^T split per (b,h)
        transsplit_k<false><<<dim3(HDD/64, SS/64, BB*NHD), 256>>>(
            big + 2*HN, 3*HN, vth, vtl, SS, HDD,
            (long long)SS*3*HN, (long long)HDD,
            (long long)NHD*HDD*SS, (long long)HDD*SS, NHD);

        // scores = Q @ K^T / 16 -> sc fp32
        tc_k<0,false,false,false,true,false,3,false><<<dim3(SS/BN, SS/BM, BB*NHD), 512, SMEMB>>>(
            bh, bl, bh + HN, bl + HN, nullptr, sc, nullptr, nullptr,
            SS, SS, HDD, 3*HN, 3*HN, SS,
            (long long)SS*3*HN, (long long)HDD,
            (long long)SS*3*HN, (long long)HDD,
            (long long)NHD*SS*SS, (long long)SS*SS, Z0, NHD,
            0.0625f, nullptr, nullptr);

        softmax_k<<<BB*NHD*SS, 256>>>(sc, ph, pl);

        // ao = probs @ V -> t1h/t1l
        tc_k<0,false,false,true,false,false,3,false><<<dim3(HDD/BN, SS/BM, BB*NHD), 512, SMEMB>>>(
            ph, pl, vth, vtl, nullptr, nullptr, t1h, t1l,
            SS, HDD, SS, SS, SS, HN,
            (long long)NHD*SS*SS, (long long)SS*SS,
            (long long)NHD*HDD*SS, (long long)HDD*SS,
            (long long)SS*HN, (long long)HDD, Z0, NHD,
            1.f, nullptr, nullptr);

        // proj = ao @ Wout^T + b -> big fp32
        tc_k<0,false,false,false,true,false,3,false><<<dim3(HN/BN, TK/BM, 1), 512, SMEMB>>>(
            t1h, t1l, wh + OFF_OUT + (long long)l*HN*HN, wl + OFF_OUT + (long long)l*HN*HN,
            outb + (long long)l*HN, big, nullptr, nullptr, TK, HN, HN, HN, HN, HN,
            Z0,Z0,Z0,Z0,Z0,Z0,Z0, 0, 1.f, nullptr, nullptr);

        ln_k<<<TK,256>>>(x, big, ln1g + (long long)l*HN, ln1b + (long long)l*HN, x, xh, xl);

        // ffn
        tc_k<1,false,false,true,false,false,3,false><<<dim3(FFD/BN, TK/BM, 1), 512, SMEMB>>>(
            xh, xl, wh + OFF_FF1 + (long long)l*HN*FFD, wl + OFF_FF1 + (long long)l*HN*FFD,
            ffb1 + (long long)l*FFD, nullptr, bh, bl, TK, FFD, HN, HN, HN, FFD,
            Z0,Z0,Z0,Z0,Z0,Z0,Z0, 0, 1.f, nullptr, nullptr);
        tc_k<0,false,false,false,true,false,3,false><<<dim3(HN/BN, TK/BM, 1), 512, SMEMB>>>(
            bh, bl, wh + OFF_FF2 + (long long)l*FFD*HN, wl + OFF_FF2 + (long long)l*FFD*HN,
            ffb2 + (long long)l*HN, t1, nullptr, nullptr, TK, HN, FFD, FFD, FFD, HN,
            Z0,Z0,Z0,Z0,Z0,Z0,Z0, 0, 1.f, nullptr, nullptr);

        ln_k<<<TK,256>>>(x, t1, ln2g + (long long)l*HN, ln2b + (long long)l*HN, x, xh, xl);

        // MoE routing
        cudaMemsetAsync(cnt, 0, NE*sizeof(int));
        gate_k<<<TK,256>>>(x, gw + (long long)l*HN*NE, gb + (long long)l*NE, cnt, tok);
        cudaMemsetAsync(t1, 0, (size_t)TK*HN*sizeof(float));

        if (l == 0) {
            // layer-1 MoE: bf16x3 (feeds layer-2 gates -> full precision)
            tc_k<2,true,false,true,false,false,3,false><<<dim3(EHD/BN, TK/BM, NE), 512, SMEMB>>>(
                xh, xl, wh + OFF_E1, wl + OFF_E1,
                eb1, nullptr, ehh, ehl, TK, EHD, HN, HN, HN, EHD,
                Z0, Z0, (long long)EHD*HN, Z0, (long long)TK*EHD, Z0, (long long)EHD, 1,
                1.f, tok, cnt);
            tc_k<0,false,true,false,false,false,3,false><<<dim3(HN/BN, TK/BM, NE), 512, SMEMB>>>(
                ehh, ehl, wh + OFF_E2, wl + OFF_E2,
                eb2, t1, nullptr, nullptr, TK, HN, EHD, EHD, EHD, HN,
                (long long)TK*EHD, Z0, (long long)HN*EHD, Z0, Z0, Z0, (long long)HN, 1,
                1.f, tok, cnt);
        } else {
            // layer-2 MoE: fp16x2 (gate-free: output feeds only the LM head)
            xtohalf_k<<<(TK*HN/4)/256, 256>>>(x, xf, (long long)TK*HN/4);
            tc_k<2,true,false,false,false,false,2,true><<<dim3(EHD/BN, TK/BM, NE), 512, SMEMB>>>(
                (const __nv_bfloat16*)xf, (const __nv_bfloat16*)xf,
                (const __nv_bfloat16*)e1h, (const __nv_bfloat16*)e1l,
                eb1 + (long long)NE*EHD, nullptr, (__nv_bfloat16*)ehf, nullptr,
                TK, EHD, HN, HN, HN, EHD,
                Z0, Z0, (long long)HN*EHD, Z0, (long long)TK*EHD, Z0, (long long)EHD, 1,
                1.f, tok, cnt);
            tc_k<0,false,true,false,false,false,2,false><<<dim3(HN/BN, TK/BM, NE), 512, SMEMB>>>(
                (const __nv_bfloat16*)ehf, (const __nv_bfloat16*)ehf,
                (const __nv_bfloat16*)e2h, (const __nv_bfloat16*)e2l,
                eb2 + (long long)NE*HN, t1, nullptr, nullptr, TK, HN, EHD, EHD, EHD, HN,
                (long long)TK*EHD, Z0, (long long)HN*EHD, Z0, Z0, Z0, (long long)HN, 1,
                1.f, tok, cnt);
        }

        copysplit_k<<<(TK*HN/4)/256, 256>>>(x, xh, xl, t1, (long long)TK*HN/4);
    }

    // lm head: pure fp16 1-term, M-inner rasterization
    xtohalf_k<<<(TK*HN/4)/256, 256>>>(x, xf, (long long)TK*HN/4);
    tc_k<0,false,false,false,true,true,1,false><<<dim3(TK/BM, VS/BN, 1), 512, SMEMB>>>(
        (const __nv_bfloat16*)xf, (const __nv_bfloat16*)xf,
        (const __nv_bfloat16*)lmh, (const __nv_bfloat16*)lml,
        lmb, out, nullptr, nullptr,
        TK, VS, HN, HN, HN, VS,
        Z0,Z0,Z0,Z0,Z0,Z0,Z0, 0, 1.f, nullptr, nullptr);
}

// round 16
// speedup vs baseline: 4.1784x; 1.0547x over previous
#include <cuda_runtime.h>
#include <cuda_bf16.h>
#include <cuda_fp16.h>
#include <math.h>

// ---------------- problem constants ----------------
#define TK   4096
#define HN   1024
#define NHD  4
#define HDD  256
#define BB   4
#define SS   1024
#define FFD  4096
#define NE   8
#define EHD  2048
#define VS   32000
#define NL   2

// ---------------- split-weight offsets (elements) ----------------
#define OFF_QKV 0LL
#define OFF_OUT  (OFF_QKV + (long long)NL*3*HN*HN)
#define OFF_FF1  (OFF_OUT + (long long)NL*HN*HN)
#define OFF_FF2  (OFF_FF1 + (long long)NL*HN*FFD)
#define OFF_E1   (OFF_FF2 + (long long)NL*FFD*HN)
#define OFF_E2   (OFF_E1  + (long long)NL*NE*HN*EHD)
#define TOTW     (OFF_E2  + (long long)NL*NE*EHD*HN)

// ---------------- scratch ----------------
__device__ float g_x  [(size_t)TK*HN];
__device__ float g_t1 [(size_t)TK*HN];
__device__ float g_big[(size_t)TK*FFD];
__device__ float g_sc [(size_t)BB*NHD*SS*SS];
__device__ int   g_cnt[NE];
__device__ int   g_tok[NE*TK];
__device__ __nv_bfloat16 g_wh[TOTW];
__device__ __nv_bfloat16 g_wl[TOTW];
__device__ __nv_bfloat16 g_vth[(size_t)BB*NHD*HDD*SS];
__device__ __nv_bfloat16 g_vtl[(size_t)BB*NHD*HDD*SS];
// split activations
__device__ __nv_bfloat16 g_xh [(size_t)TK*HN];
__device__ __nv_bfloat16 g_xl [(size_t)TK*HN];
__device__ __nv_bfloat16 g_bh [(size_t)TK*FFD];
__device__ __nv_bfloat16 g_bl [(size_t)TK*FFD];
__device__ __nv_bfloat16 g_ph [(size_t)BB*NHD*SS*SS];
__device__ __nv_bfloat16 g_pl [(size_t)BB*NHD*SS*SS];
__device__ __nv_bfloat16 g_ehh[(size_t)NE*TK*EHD];
__device__ __nv_bfloat16 g_ehl[(size_t)NE*TK*EHD];
__device__ __nv_bfloat16 g_t1h[(size_t)TK*HN];
__device__ __nv_bfloat16 g_t1l[(size_t)TK*HN];
// fp16 paths
__device__ __half g_lmh[(size_t)HN*VS];
__device__ __half g_lml[(size_t)HN*VS];
__device__ __half g_xf [(size_t)TK*HN];
__device__ __half g_e1h[(size_t)NE*HN*EHD];
__device__ __half g_e1l[(size_t)NE*HN*EHD];
__device__ __half g_e2h[(size_t)NE*EHD*HN];
__device__ __half g_e2l[(size_t)NE*EHD*HN];
__device__ __half g_ehf[(size_t)NE*TK*EHD];

// ================= helpers =================
__device__ __forceinline__ unsigned smem_u32(const void* p){
    unsigned a;
    asm("{ .reg .u64 t; cvta.to.shared.u64 t, %1; cvt.u32.u64 %0, t; }" : "=r"(a) : "l"(p));
    return a;
}
__device__ __forceinline__ void split1(float v, __nv_bfloat16& h, __nv_bfloat16& l) {
    h = __float2bfloat16(v);
    l = __float2bfloat16(v - __bfloat162float(h));
}
__device__ __forceinline__ void split2w(float v0, float v1, unsigned& hw, unsigned& lw) {
    __nv_bfloat16 h0, l0, h1, l1;
    split1(v0, h0, l0); split1(v1, h1, l1);
    hw = (unsigned)__bfloat16_as_ushort(h0) | ((unsigned)__bfloat16_as_ushort(h1) << 16);
    lw = (unsigned)__bfloat16_as_ushort(l0) | ((unsigned)__bfloat16_as_ushort(l1) << 16);
}
__device__ __forceinline__ void split2wh(float v0, float v1, unsigned& hw, unsigned& lw) {
    __half h0 = __float2half(v0), h1 = __float2half(v1);
    __half l0 = __float2half(v0 - __half2float(h0));
    __half l1 = __float2half(v1 - __half2float(h1));
    hw = (unsigned)__half_as_ushort(h0) | ((unsigned)__half_as_ushort(h1) << 16);
    lw = (unsigned)__half_as_ushort(l0) | ((unsigned)__half_as_ushort(l1) << 16);
}

#define LDSM_X4(r0, r1, r2, r3, a) \
    asm volatile("ldmatrix.sync.aligned.m8n8.x4.shared.b16 {%0,%1,%2,%3}, [%4];" \
                 : "=r"(r0), "=r"(r1), "=r"(r2), "=r"(r3) : "r"(a))
#define MMA16816(d, a, b) \
    asm volatile("mma.sync.aligned.m16n8k16.row.col.f32.bf16.bf16.f32 " \
                 "{%0,%1,%2,%3}, {%4,%5,%6,%7}, {%8,%9}, {%0,%1,%2,%3};" \
                 : "+f"((d)[0]), "+f"((d)[1]), "+f"((d)[2]), "+f"((d)[3]) \
                 : "r"((a)[0]), "r"((a)[1]), "r"((a)[2]), "r"((a)[3]), \
                   "r"((b)[0]), "r"((b)[1]))
#define MMA16816H(d, a, b) \
    asm volatile("mma.sync.aligned.m16n8k16.row.col.f32.f16.f16.f32 " \
                 "{%0,%1,%2,%3}, {%4,%5,%6,%7}, {%8,%9}, {%0,%1,%2,%3};" \
                 : "+f"((d)[0]), "+f"((d)[1]), "+f"((d)[2]), "+f"((d)[3]) \
                 : "r"((a)[0]), "r"((a)[1]), "r"((a)[2]), "r"((a)[3]), \
                   "r"((b)[0]), "r"((b)[1]))
#define CP_ASYNC16(sa, gp) \
    asm volatile("cp.async.cg.shared.global [%0], [%1], 16;" :: "r"(sa), "l"(gp) : "memory")
#define CP_COMMIT() asm volatile("cp.async.commit_group;" ::: "memory")
#define CP_WAIT1()  asm volatile("cp.async.wait_group 1;" ::: "memory")
#define CP_WAIT0()  asm volatile("cp.async.wait_group 0;" ::: "memory")

// ===== 128x128 / 256-thread / 2-stage / 2-CTA-per-SM MMA GEMM =====
#define BM 128
#define BN 128
#define KC 32
#define ROWB 80
#define RG_AL 10240
#define RG_BH 20480
#define RG_BL 30720
#define STGB  40960
#define NSTG  2
#define SMEMB (NSTG*STGB)

template<int ACT, bool GATHER, bool SCATTER, bool OSPLIT, bool OF32, bool SWAP, int TERMS, bool OHALF>
__global__ void __launch_bounds__(256, 2)
tc_k(const __nv_bfloat16* __restrict__ Ah, const __nv_bfloat16* __restrict__ Al,
     const __nv_bfloat16* __restrict__ Bh, const __nv_bfloat16* __restrict__ Bl,
     const float* __restrict__ bias,
     float* __restrict__ C, __nv_bfloat16* __restrict__ Ch, __nv_bfloat16* __restrict__ Cl,
     int M, int N, int Kd, int lda, int ldb, int ldc,
     long long sAb, long long sAh_, long long sBb, long long sBh_,
     long long sCb, long long sCh_, long long sBias, int nh, float alpha,
     const int* __restrict__ ridx, const int* __restrict__ cptr)
{
    if (nh > 0) {
        int z = blockIdx.z, zb = z / nh, zh = z % nh;
        long long ao = zb*sAb + zh*sAh_;
        Ah += ao; Al += ao;
        long long bo = zb*sBb + zh*sBh_;
        Bh += bo; Bl += bo;
        long long co = zb*sCb + zh*sCh_;
        if (OF32 || SCATTER) C += co;
        if (OSPLIT || OHALF) { Ch += co; Cl += co; }
        if (bias) bias += zb*sBias;
        if (GATHER || SCATTER) ridx += (long long)zb*TK;
        if (cptr) cptr += zb;
    }
    if (cptr) M = *cptr;
    int m0 = SWAP ? blockIdx.x*BM : blockIdx.y*BM;
    int n0 = SWAP ? blockIdx.y*BN : blockIdx.x*BN;
    if (m0 >= M) return;

    extern __shared__ char sm[];
    unsigned sb = smem_u32(sm);
    int tid = threadIdx.x, lane = tid & 31, wid = tid >> 5;
    int wm = wid & 1, wn = wid >> 1;       // 2 x 4 warp grid; warp tile 64x32

    float acc[4][4][4];
#pragma unroll
    for (int i = 0; i < 4; i++)
#pragma unroll
        for (int j = 0; j < 4; j++)
#pragma unroll
            for (int e = 0; e < 4; e++) acc[i][j][e] = 0.f;

    // ---- load mapping: 256 threads; row = tid>>2 (0..63) + {0,64}, 16B chunk = tid&3 ----
    int lr = tid >> 2, lc = tid & 3;
    long long arow, arow2;
    {
        int gm  = m0 + lr;      if (gm  >= M) gm  = M - 1;
        int gm2 = m0 + 64 + lr; if (gm2 >= M) gm2 = M - 1;
        arow  = GATHER ? (long long)ridx[gm]  : (long long)gm;
        arow2 = GATHER ? (long long)ridx[gm2] : (long long)gm2;
    }
    const __nv_bfloat16* pAh  = Ah + arow *lda + lc*8;
    const __nv_bfloat16* pAh2 = Ah + arow2*lda + lc*8;
    const __nv_bfloat16* pAl  = Al + arow *lda + lc*8;
    const __nv_bfloat16* pAl2 = Al + arow2*lda + lc*8;
    const __nv_bfloat16* pBh0 = Bh + (long long)(n0 + lr)*ldb + lc*8;
    const __nv_bfloat16* pBh1 = Bh + (long long)(n0 + 64 + lr)*ldb + lc*8;
    const __nv_bfloat16* pBl0 = Bl + (long long)(n0 + lr)*ldb + lc*8;
    const __nv_bfloat16* pBl1 = Bl + (long long)(n0 + 64 + lr)*ldb + lc*8;
    unsigned offR  = (unsigned)lr*ROWB + (unsigned)lc*16;
    unsigned offR2 = offR + 64u*ROWB;

    int NC = Kd / KC;

    auto issue = [&](int s) {
        unsigned base = sb + (unsigned)(s & 1)*STGB;
        int k0 = s*KC;
        CP_ASYNC16(base + offR,  pAh  + k0);
        CP_ASYNC16(base + offR2, pAh2 + k0);
        if (TERMS == 3) {
            CP_ASYNC16(base + RG_AL + offR,  pAl  + k0);
            CP_ASYNC16(base + RG_AL + offR2, pAl2 + k0);
        }
        CP_ASYNC16(base + RG_BH + offR,  pBh0 + k0);
        CP_ASYNC16(base + RG_BH + offR2, pBh1 + k0);
        if (TERMS >= 2) {
            CP_ASYNC16(base + RG_BL + offR,  pBl0 + k0);
            CP_ASYNC16(base + RG_BL + offR2, pBl1 + k0);
        }
        CP_COMMIT();
    };

    issue(0);

    unsigned aoff = (unsigned)(lane & 15)*ROWB + (unsigned)(lane >> 4)*16;
    unsigned boff = (unsigned)(lane & 7)*ROWB + (unsigned)((lane >> 3) & 1)*16
                  + (unsigned)(lane >> 4)*(8*ROWB);

    for (int i = 0; i < NC; i++) {
        __syncthreads();                              // buffer (i+1)&1 fully consumed
        if (i + 1 < NC) { issue(i + 1); CP_WAIT1(); } else { CP_WAIT0(); }
        __syncthreads();                              // chunk i visible to all warps

        unsigned st = sb + (unsigned)(i & 1)*STGB;
        unsigned abase = st + (unsigned)(wm*64)*ROWB;
        unsigned bbase = st + RG_BH + (unsigned)(wn*32)*ROWB;
#pragma unroll
        for (int ks = 0; ks < 2; ks++) {
            unsigned bh[4][2], bl[4][2];
#pragma unroll
            for (int p = 0; p < 2; p++) {
                unsigned bd = bbase + (unsigned)(p*16)*ROWB + boff + ks*32;
                LDSM_X4(bh[2*p][0], bh[2*p][1], bh[2*p+1][0], bh[2*p+1][1], bd);
                if (TERMS >= 2)
                    LDSM_X4(bl[2*p][0], bl[2*p][1], bl[2*p+1][0], bl[2*p+1][1],
                            bd + (RG_BL - RG_BH));
            }
#pragma unroll
            for (int mt = 0; mt < 4; mt++) {
                unsigned ah[4], al[4];
                unsigned ad = abase + (unsigned)(mt*16)*ROWB + aoff + ks*32;
                LDSM_X4(ah[0], ah[1], ah[2], ah[3], ad);
                if (TERMS == 3)
                    LDSM_X4(al[0], al[1], al[2], al[3], ad + RG_AL);
#pragma unroll
                for (int nt = 0; nt < 4; nt++) {
                    if (TERMS == 3) {
                        MMA16816(acc[mt][nt], ah, bh[nt]);
                        MMA16816(acc[mt][nt], ah, bl[nt]);
                        MMA16816(acc[mt][nt], al, bh[nt]);
                    } else if (TERMS == 2) {
                        MMA16816H(acc[mt][nt], ah, bh[nt]);
                        MMA16816H(acc[mt][nt], ah, bl[nt]);
                    } else {
                        MMA16816H(acc[mt][nt], ah, bh[nt]);
                    }
                }
            }
        }
    }

    // ---- epilogue ----
#pragma unroll
    for (int mt = 0; mt < 4; mt++) {
#pragma unroll
        for (int half = 0; half < 2; half++) {
            int gm = m0 + wm*64 + mt*16 + (lane >> 2) + half*8;
            if (gm >= M) continue;
            long long crow = SCATTER ? (long long)ridx[gm]*ldc : (long long)gm*ldc;
#pragma unroll
            for (int nt = 0; nt < 4; nt++) {
                int gn = n0 + wn*32 + nt*8 + (lane & 3)*2;
                float v0 = acc[mt][nt][half*2 + 0] * alpha;
                float v1 = acc[mt][nt][half*2 + 1] * alpha;
                if (bias) { v0 += bias[gn]; v1 += bias[gn+1]; }
                if (ACT == 1) {
                    v0 = 0.5f*v0*(1.0f + erff(v0*0.7071067811865475f));
                    v1 = 0.5f*v1*(1.0f + erff(v1*0.7071067811865475f));
                } else if (ACT == 2) {
                    v0 = v0 > 0.f ? v0 : 0.f;
                    v1 = v1 > 0.f ? v1 : 0.f;
                }
                if (SCATTER) {
                    atomicAdd(C + crow + gn,     v0);
                    atomicAdd(C + crow + gn + 1, v1);
                } else {
                    if (OF32) *(float2*)(C + crow + gn) = make_float2(v0, v1);
                    if (OSPLIT) {
                        unsigned hw, lw; split2w(v0, v1, hw, lw);
                        *(unsigned*)(Ch + crow + gn) = hw;
                        *(unsigned*)(Cl + crow + gn) = lw;
                    }
                    if (OHALF) {
                        __half2 hv = __floats2half2_rn(v0, v1);
                        *(unsigned*)((__half*)Ch + crow + gn) = *(unsigned*)&hv;
                    }
                }
            }
        }
    }
}

// ================= weight prep (bandwidth-optimized) =================
__global__ void split_k(const float* __restrict__ W, __nv_bfloat16* __restrict__ hi,
                        __nv_bfloat16* __restrict__ lo, long long n4) {
    long long i = (long long)blockIdx.x*256 + threadIdx.x;
    if (i >= n4) return;
    float4 v = ((const float4*)W)[i];
    unsigned h0, l0, h1, l1;
    split2w(v.x, v.y, h0, l0); split2w(v.z, v.w, h1, l1);
    ((uint2*)hi)[i] = make_uint2(h0, h1);
    ((uint2*)lo)[i] = make_uint2(l0, l1);
}
template<bool HALFOUT>
__global__ void transsplit_k(const float* __restrict__ W, int ldw,
                             void* __restrict__ hip, void* __restrict__ lop,
                             int Kd, int Nd, long long sWb, long long sWh,
                             long long sOb, long long sOh, int nhz) {
    int z = blockIdx.z, zb = z / nhz, zh = z % nhz;
    W += zb*sWb + zh*sWh;
    __nv_bfloat16* hi = (__nv_bfloat16*)hip + zb*sOb + zh*sOh;
    __nv_bfloat16* lo = (__nv_bfloat16*)lop + zb*sOb + zh*sOh;
    __shared__ float ts[64][65];
    int n0 = blockIdx.x*64, k0 = blockIdx.y*64;
    int tid = threadIdx.x;
    {
        int rr = tid >> 4, c4 = (tid & 15)*4;
#pragma unroll
        for (int it = 0; it < 4; it++) {
            int r = rr + it*16;
            float4 v = *(const float4*)(W + (long long)(k0 + r)*ldw + n0 + c4);
            ts[r][c4+0] = v.x; ts[r][c4+1] = v.y; ts[r][c4+2] = v.z; ts[r][c4+3] = v.w;
        }
    }
    __syncthreads();
    int nb = tid >> 4, kq = (tid & 15)*4;
#pragma unroll
    for (int it = 0; it < 4; it++) {
        int nn = nb + it*16;
        float a = ts[kq+0][nn], b = ts[kq+1][nn];
        float c = ts[kq+2][nn], d = ts[kq+3][nn];
        unsigned h0, l0, h1, l1;
        if (HALFOUT) { split2wh(a, b, h0, l0); split2wh(c, d, h1, l1); }
        else         { split2w (a, b, h0, l0); split2w (c, d, h1, l1); }
        long long o = (long long)(n0 + nn)*Kd + k0 + kq;
        *(uint2*)(hi + o) = make_uint2(h0, h1);
        *(uint2*)(lo + o) = make_uint2(l0, l1);
    }
}

// ================= block reduce helpers (smem broadcast) =================
__device__ __forceinline__ float blk_sum(float v, float* red, int tid) {
#pragma unroll
    for (int o = 16; o > 0; o >>= 1) v += __shfl_xor_sync(0xffffffffu, v, o);
    if ((tid & 31) == 0) red[tid >> 5] = v;
    __syncthreads();
    if (tid < 32) {
        float s = (tid < 8) ? red[tid] : 0.f;
#pragma unroll
        for (int o = 4; o > 0; o >>= 1) s += __shfl_xor_sync(0xffffffffu, s, o);
        if (tid == 0) red[0] = s;
    }
    __syncthreads();
    float r = red[0];
    __syncthreads();
    return r;
}
__device__ __forceinline__ float blk_max(float v, float* red, int tid) {
#pragma unroll
    for (int o = 16; o > 0; o >>= 1) v = fmaxf(v, __shfl_xor_sync(0xffffffffu, v, o));
    if ((tid & 31) == 0) red[tid >> 5] = v;
    __syncthreads();
    if (tid < 32) {
        float s = (tid < 8) ? red[tid] : -1e30f;
#pragma unroll
        for (int o = 4; o > 0; o >>= 1) s = fmaxf(s, __shfl_xor_sync(0xffffffffu, s, o));
        if (tid == 0) red[0] = s;
    }
    __syncthreads();
    float r = red[0];
    __syncthreads();
    return r;
}

// ================= misc kernels (vectorized) =================
__global__ void embed_k(const int* __restrict__ ids, const float* __restrict__ emb,
                        float* __restrict__ out,
                        __nv_bfloat16* __restrict__ oh, __nv_bfloat16* __restrict__ ol) {
    long long t = blockIdx.x;
    int tid = threadIdx.x;
    float4 v = ((const float4*)(emb + (size_t)ids[t]*HN))[tid];
    ((float4*)(out + t*HN))[tid] = v;
    unsigned h0, l0, h1, l1;
    split2w(v.x, v.y, h0, l0); split2w(v.z, v.w, h1, l1);
    ((uint2*)(oh + t*HN))[tid] = make_uint2(h0, h1);
    ((uint2*)(ol + t*HN))[tid] = make_uint2(l0, l1);
}
__global__ void softmax_k(const float* __restrict__ p,
                          __nv_bfloat16* __restrict__ oh, __nv_bfloat16* __restrict__ ol) {
    long long row = blockIdx.x;
    int tid = threadIdx.x;
    __shared__ float red[8];
    float4 v = ((const float4*)(p + row*SS))[tid];
    float mx = blk_max(fmaxf(fmaxf(v.x, v.y), fmaxf(v.z, v.w)), red, tid);
    v.x = expf(v.x - mx); v.y = expf(v.y - mx); v.z = expf(v.z - mx); v.w = expf(v.w - mx);
    float inv = 1.f / blk_sum(v.x + v.y + v.z + v.w, red, tid);
    v.x *= inv; v.y *= inv; v.z *= inv; v.w *= inv;
    unsigned h0, l0, h1, l1;
    split2w(v.x, v.y, h0, l0); split2w(v.z, v.w, h1, l1);
    ((uint2*)(oh + row*SS))[tid] = make_uint2(h0, h1);
    ((uint2*)(ol + row*SS))[tid] = make_uint2(l0, l1);
}
__global__ void ln_k(const float* __restrict__ resid, const float* __restrict__ delta,
                     const float* __restrict__ g, const float* __restrict__ b,
                     float* __restrict__ out,
                     __nv_bfloat16* __restrict__ oh, __nv_bfloat16* __restrict__ ol) {
    long long t = blockIdx.x;
    int tid = threadIdx.x;
    __shared__ float red[8];
    float4 r = ((const float4*)(resid + t*HN))[tid];
    float4 d = ((const float4*)(delta + t*HN))[tid];
    float4 v = make_float4(r.x + d.x, r.y + d.y, r.z + d.z, r.w + d.w);
    float m = blk_sum(v.x + v.y + v.z + v.w, red, tid) * (1.0f/HN);
    float4 c = make_float4(v.x - m, v.y - m, v.z - m, v.w - m);
    float var = blk_sum(c.x*c.x + c.y*c.y + c.z*c.z + c.w*c.w, red, tid) * (1.0f/HN);
    float inv = rsqrtf(var + 1e-5f);
    float4 gg = ((const float4*)g)[tid];
    float4 bb = ((const float4*)b)[tid];
    float4 o = make_float4(c.x*inv*gg.x + bb.x, c.y*inv*gg.y + bb.y,
                           c.z*inv*gg.z + bb.z, c.w*inv*gg.w + bb.w);
    ((float4*)(out + t*HN))[tid] = o;
    unsigned h0, l0, h1, l1;
    split2w(o.x, o.y, h0, l0); split2w(o.z, o.w, h1, l1);
    ((uint2*)(oh + t*HN))[tid] = make_uint2(h0, h1);
    ((uint2*)(ol + t*HN))[tid] = make_uint2(l0, l1);
}
__global__ void gate_k(const float* __restrict__ x, const float* __restrict__ gw,
                       const float* __restrict__ gb, int* __restrict__ cnt,
                       int* __restrict__ toks) {
    int t = blockIdx.x;
    int tid = threadIdx.x;
    __shared__ float xs[HN];
    __shared__ float red[256];
    for (int i = tid; i < HN; i += 256) xs[i] = x[(long long)t*HN+i];
    __syncthreads();
    int e = tid & 7, g = tid >> 3;
    float p = 0.f;
    for (int j = g; j < HN; j += 32) p += xs[j]*gw[j*NE+e];
    red[tid] = p; __syncthreads();
    if (tid < 8) {
        float s = 0.f;
        for (int j = 0; j < 32; j++) s += red[j*8 + tid];
        red[tid] = s + gb[tid];
    }
    __syncthreads();
    if (tid == 0) {
        float l[NE];
        for (int i = 0; i < NE; i++) l[i] = red[i];
        int i1 = 0;
        for (int i = 1; i < NE; i++) if (l[i] > l[i1]) i1 = i;
        int i2 = (i1 == 0) ? 1 : 0;
        for (int i = 0; i < NE; i++) if (i != i1 && l[i] > l[i2]) i2 = i;
        int p1 = atomicAdd(&cnt[i1], 1); toks[i1*TK+p1] = t;
        int p2 = atomicAdd(&cnt[i2], 1); toks[i2*TK+p2] = t;
    }
}
__global__ void copysplit_k(float* __restrict__ dst, __nv_bfloat16* __restrict__ oh,
                            __nv_bfloat16* __restrict__ ol, const float* __restrict__ src,
                            long long n4) {
    long long i = (long long)blockIdx.x*blockDim.x + threadIdx.x;
    if (i >= n4) return;
    float4 v = ((const float4*)src)[i];
    ((float4*)dst)[i] = v;
    unsigned h0, l0, h1, l1;
    split2w(v.x, v.y, h0, l0); split2w(v.z, v.w, h1, l1);
    ((uint2*)oh)[i] = make_uint2(h0, h1);
    ((uint2*)ol)[i] = make_uint2(l0, l1);
}
__global__ void copyhalf_k(float* __restrict__ dst, __half* __restrict__ dsth,
                           const float* __restrict__ src, long long n4) {
    long long i = (long long)blockIdx.x*blockDim.x + threadIdx.x;
    if (i >= n4) return;
    float4 v = ((const float4*)src)[i];
    ((float4*)dst)[i] = v;
    __half2 a = __floats2half2_rn(v.x, v.y);
    __half2 b = __floats2half2_rn(v.z, v.w);
    ((uint2*)dsth)[i] = make_uint2(*(unsigned*)&a, *(unsigned*)&b);
}
__global__ void xtohalf_k(const float* __restrict__ src, __half* __restrict__ dst,
                          long long n4) {
    long long i = (long long)blockIdx.x*blockDim.x + threadIdx.x;
    if (i >= n4) return;
    float4 v = ((const float4*)src)[i];
    __half2 a = __floats2half2_rn(v.x, v.y);
    __half2 b = __floats2half2_rn(v.z, v.w);
    ((uint2*)dst)[i] = make_uint2(*(unsigned*)&a, *(unsigned*)&b);
}

// ================= launch =================
extern "C" void kernel_launch(void* const* d_in, const int* in_sizes, int n_in,
                              void* d_out, int out_size)
{
    const int*   ids   = (const int*)d_in[0];
    const float* emb   = (const float*)d_in[1];
    const float* qkvw  = (const float*)d_in[2];
    const float* qkvb  = (const float*)d_in[3];
    const float* outw  = (const float*)d_in[4];
    const float* outb  = (const float*)d_in[5];
    const float* ln1g  = (const float*)d_in[6];
    const float* ln1b  = (const float*)d_in[7];
    const float* ffw1  = (const float*)d_in[8];
    const float* ffb1  = (const float*)d_in[9];
    const float* ffw2  = (const float*)d_in[10];
    const float* ffb2  = (const float*)d_in[11];
    const float* ln2g  = (const float*)d_in[12];
    const float* ln2b  = (const float*)d_in[13];
    const float* gw    = (const float*)d_in[14];
    const float* gb    = (const float*)d_in[15];
    const float* ew1   = (const float*)d_in[16];
    const float* eb1   = (const float*)d_in[17];
    const float* ew2   = (const float*)d_in[18];
    const float* eb2   = (const float*)d_in[19];
    const float* lmw   = (const float*)d_in[20];
    const float* lmb   = (const float*)d_in[21];
    float* out = (float*)d_out;

    float *x, *t1, *big, *sc; int *cnt, *tok;
    __nv_bfloat16 *wh, *wl, *vth, *vtl, *xh, *xl, *bh, *bl, *ph, *pl, *ehh, *ehl, *t1h, *t1l;
    __half *lmh, *lml, *xf, *e1h, *e1l, *e2h, *e2l, *ehf;
    cudaGetSymbolAddress((void**)&x,   g_x);
    cudaGetSymbolAddress((void**)&t1,  g_t1);
    cudaGetSymbolAddress((void**)&big, g_big);
    cudaGetSymbolAddress((void**)&sc,  g_sc);
    cudaGetSymbolAddress((void**)&cnt, g_cnt);
    cudaGetSymbolAddress((void**)&tok, g_tok);
    cudaGetSymbolAddress((void**)&wh,  g_wh);
    cudaGetSymbolAddress((void**)&wl,  g_wl);
    cudaGetSymbolAddress((void**)&vth, g_vth);
    cudaGetSymbolAddress((void**)&vtl, g_vtl);
    cudaGetSymbolAddress((void**)&xh,  g_xh);
    cudaGetSymbolAddress((void**)&xl,  g_xl);
    cudaGetSymbolAddress((void**)&bh,  g_bh);
    cudaGetSymbolAddress((void**)&bl,  g_bl);
    cudaGetSymbolAddress((void**)&ph,  g_ph);
    cudaGetSymbolAddress((void**)&pl,  g_pl);
    cudaGetSymbolAddress((void**)&ehh, g_ehh);
    cudaGetSymbolAddress((void**)&ehl, g_ehl);
    cudaGetSymbolAddress((void**)&t1h, g_t1h);
    cudaGetSymbolAddress((void**)&t1l, g_t1l);
    cudaGetSymbolAddress((void**)&lmh, g_lmh);
    cudaGetSymbolAddress((void**)&lml, g_lml);
    cudaGetSymbolAddress((void**)&xf,  g_xf);
    cudaGetSymbolAddress((void**)&e1h, g_e1h);
    cudaGetSymbolAddress((void**)&e1l, g_e1l);
    cudaGetSymbolAddress((void**)&e2h, g_e2h);
    cudaGetSymbolAddress((void**)&e2l, g_e2l);
    cudaGetSymbolAddress((void**)&ehf, g_ehf);

    cudaFuncSetAttribute(tc_k<0,false,false,true, true, false,3,false>, cudaFuncAttributeMaxDynamicSharedMemorySize, SMEMB);
    cudaFuncSetAttribute(tc_k<0,false,false,false,true, false,3,false>, cudaFuncAttributeMaxDynamicSharedMemorySize, SMEMB);
    cudaFuncSetAttribute(tc_k<0,false,false,true, false,false,3,false>, cudaFuncAttributeMaxDynamicSharedMemorySize, SMEMB);
    cudaFuncSetAttribute(tc_k<1,false,false,true, false,false,3,false>, cudaFuncAttributeMaxDynamicSharedMemorySize, SMEMB);
    cudaFuncSetAttribute(tc_k<2,true, false,true, false,false,3,false>, cudaFuncAttributeMaxDynamicSharedMemorySize, SMEMB);
    cudaFuncSetAttribute(tc_k<0,false,true, false,false,false,3,false>, cudaFuncAttributeMaxDynamicSharedMemorySize, SMEMB);
    cudaFuncSetAttribute(tc_k<0,false,false,false,true, true, 1,false>, cudaFuncAttributeMaxDynamicSharedMemorySize, SMEMB);
    cudaFuncSetAttribute(tc_k<2,true, false,false,false,false,2,true >, cudaFuncAttributeMaxDynamicSharedMemorySize, SMEMB);
    cudaFuncSetAttribute(tc_k<0,false,true, false,false,false,2,false>, cudaFuncAttributeMaxDynamicSharedMemorySize, SMEMB);

    const long long Z0 = 0;

    // ---- weight pre-split ----
    split_k<<<(unsigned)(((long long)NL*3*HN*HN/4 + 255)/256), 256>>>(qkvw, wh + OFF_QKV, wl + OFF_QKV, (long long)NL*3*HN*HN/4);
    split_k<<<(unsigned)(((long long)NL*HN*HN/4 + 255)/256), 256>>>(outw, wh + OFF_OUT, wl + OFF_OUT, (long long)NL*HN*HN/4);
    transsplit_k<false><<<dim3(FFD/64, HN/64, NL), 256>>>(ffw1, FFD, wh + OFF_FF1, wl + OFF_FF1,
        HN, FFD, (long long)HN*FFD, Z0, (long long)HN*FFD, Z0, 1);
    transsplit_k<false><<<dim3(HN/64, FFD/64, NL), 256>>>(ffw2, HN, wh + OFF_FF2, wl + OFF_FF2,
        FFD, HN, (long long)FFD*HN, Z0, (long long)FFD*HN, Z0, 1);
    transsplit_k<false><<<dim3(EHD/64, HN/64, NE), 256>>>(ew1, EHD, wh + OFF_E1, wl + OFF_E1,
        HN, EHD, (long long)HN*EHD, Z0, (long long)HN*EHD, Z0, 1);
    transsplit_k<false><<<dim3(HN/64, EHD/64, NE), 256>>>(ew2, HN, wh + OFF_E2, wl + OFF_E2,
        EHD, HN, (long long)EHD*HN, Z0, (long long)EHD*HN, Z0, 1);
    transsplit_k<true><<<dim3(EHD/64, HN/64, NE), 256>>>(ew1 + (long long)NE*HN*EHD, EHD, e1h, e1l,
        HN, EHD, (long long)HN*EHD, Z0, (long long)HN*EHD, Z0, 1);
    transsplit_k<true><<<dim3(HN/64, EHD/64, NE), 256>>>(ew2 + (long long)NE*EHD*HN, HN, e2h, e2l,
        EHD, HN, (long long)EHD*HN, Z0, (long long)EHD*HN, Z0, 1);
    transsplit_k<true><<<dim3(VS/64, HN/64, 1), 256>>>(lmw, VS, lmh, lml,
        HN, VS, Z0, Z0, Z0, Z0, 1);

    embed_k<<<TK, 256>>>(ids, emb, x, xh, xl);

    for (int l = 0; l < NL; l++) {
        // qkv = x @ Wqkv^T + b  -> big fp32 + bh/bl
        tc_k<0,false,false,true,true,false,3,false><<<dim3(3*HN/BN, TK/BM, 1), 256, SMEMB>>>(
            xh, xl, wh + OFF_QKV + (long long)l*3*HN*HN, wl + OFF_QKV + (long long)l*3*HN*HN,
            qkvb + (long long)l*3*HN, big, bh, bl, TK, 3*HN, HN, HN, HN, 3*HN,
            Z0,Z0,Z0,Z0,Z0,Z0,Z0, 0, 1.f, nullptr, nullptr);

        // V^T split per (b,h)
        transsplit_k<false><<<dim3(HDD/64, SS/64, BB*NHD), 256>>>(
            big + 2*HN, 3*HN, vth, vtl, SS, HDD,
            (long long)SS*3*HN, (long long)HDD,
            (long long)NHD*HDD*SS, (long long)HDD*SS, NHD);

        // scores = Q @ K^T / 16 -> sc fp32
        tc_k<0,false,false,false,true,false,3,false><<<dim3(SS/BN, SS/BM, BB*NHD), 256, SMEMB>>>(
            bh, bl, bh + HN, bl + HN, nullptr, sc, nullptr, nullptr,
            SS, SS, HDD, 3*HN, 3*HN, SS,
            (long long)SS*3*HN, (long long)HDD,
            (long long)SS*3*HN, (long long)HDD,
            (long long)NHD*SS*SS, (long long)SS*SS, Z0, NHD,
            0.0625f, nullptr, nullptr);

        softmax_k<<<BB*NHD*SS, 256>>>(sc, ph, pl);

        // ao = probs @ V -> t1h/t1l
        tc_k<0,false,false,true,false,false,3,false><<<dim3(HDD/BN, SS/BM, BB*NHD), 256, SMEMB>>>(
            ph, pl, vth, vtl, nullptr, nullptr, t1h, t1l,
            SS, HDD, SS, SS, SS, HN,
            (long long)NHD*SS*SS, (long long)SS*SS,
            (long long)NHD*HDD*SS, (long long)HDD*SS,
            (long long)SS*HN, (long long)HDD, Z0, NHD,
            1.f, nullptr, nullptr);

        // proj = ao @ Wout^T + b -> big fp32
        tc_k<0,false,false,false,true,false,3,false><<<dim3(HN/BN, TK/BM, 1), 256, SMEMB>>>(
            t1h, t1l, wh + OFF_OUT + (long long)l*HN*HN, wl + OFF_OUT + (long long)l*HN*HN,
            outb + (long long)l*HN, big, nullptr, nullptr, TK, HN, HN, HN, HN, HN,
            Z0,Z0,Z0,Z0,Z0,Z0,Z0, 0, 1.f, nullptr, nullptr);

        ln_k<<<TK,256>>>(x, big, ln1g + (long long)l*HN, ln1b + (long long)l*HN, x, xh, xl);

        // ffn
        tc_k<1,false,false,true,false,false,3,false><<<dim3(FFD/BN, TK/BM, 1), 256, SMEMB>>>(
            xh, xl, wh + OFF_FF1 + (long long)l*HN*FFD, wl + OFF_FF1 + (long long)l*HN*FFD,
            ffb1 + (long long)l*FFD, nullptr, bh, bl, TK, FFD, HN, HN, HN, FFD,
            Z0,Z0,Z0,Z0,Z0,Z0,Z0, 0, 1.f, nullptr, nullptr);
        tc_k<0,false,false,false,true,false,3,false><<<dim3(HN/BN, TK/BM, 1), 256, SMEMB>>>(
            bh, bl, wh + OFF_FF2 + (long long)l*FFD*HN, wl + OFF_FF2 + (long long)l*FFD*HN,
            ffb2 + (long long)l*HN, t1, nullptr, nullptr, TK, HN, FFD, FFD, FFD, HN,
            Z0,Z0,Z0,Z0,Z0,Z0,Z0, 0, 1.f, nullptr, nullptr);

        ln_k<<<TK,256>>>(x, t1, ln2g + (long long)l*HN, ln2b + (long long)l*HN, x, xh, xl);

        // MoE routing
        cudaMemsetAsync(cnt, 0, NE*sizeof(int));
        gate_k<<<TK,256>>>(x, gw + (long long)l*HN*NE, gb + (long long)l*NE, cnt, tok);
        cudaMemsetAsync(t1, 0, (size_t)TK*HN*sizeof(float));

        if (l == 0) {
            // layer-1 MoE: bf16x3 (feeds layer-2 gates)
            tc_k<2,true,false,true,false,false,3,false><<<dim3(EHD/BN, TK/BM, NE), 256, SMEMB>>>(
                xh, xl, wh + OFF_E1, wl + OFF_E1,
                eb1, nullptr, ehh, ehl, TK, EHD, HN, HN, HN, EHD,
                Z0, Z0, (long long)EHD*HN, Z0, (long long)TK*EHD, Z0, (long long)EHD, 1,
                1.f, tok, cnt);
            tc_k<0,false,true,false,false,false,3,false><<<dim3(HN/BN, TK/BM, NE), 256, SMEMB>>>(
                ehh, ehl, wh + OFF_E2, wl + OFF_E2,
                eb2, t1, nullptr, nullptr, TK, HN, EHD, EHD, EHD, HN,
                (long long)TK*EHD, Z0, (long long)HN*EHD, Z0, Z0, Z0, (long long)HN, 1,
                1.f, tok, cnt);
            copysplit_k<<<(TK*HN/4)/256, 256>>>(x, xh, xl, t1, (long long)TK*HN/4);
        } else {
            // layer-2 MoE: fp16x2 (output feeds only the LM head)
            xtohalf_k<<<(TK*HN/4)/256, 256>>>(x, xf, (long long)TK*HN/4);
            tc_k<2,true,false,false,false,false,2,true><<<dim3(EHD/BN, TK/BM, NE), 256, SMEMB>>>(
                (const __nv_bfloat16*)xf, (const __nv_bfloat16*)xf,
                (const __nv_bfloat16*)e1h, (const __nv_bfloat16*)e1l,
                eb1 + (long long)NE*EHD, nullptr, (__nv_bfloat16*)ehf, nullptr,
                TK, EHD, HN, HN, HN, EHD,
                Z0, Z0, (long long)HN*EHD, Z0, (long long)TK*EHD, Z0, (long long)EHD, 1,
                1.f, tok, cnt);
            tc_k<0,false,true,false,false,false,2,false><<<dim3(HN/BN, TK/BM, NE), 256, SMEMB>>>(
                (const __nv_bfloat16*)ehf, (const __nv_bfloat16*)ehf,
                (const __nv_bfloat16*)e2h, (const __nv_bfloat16*)e2l,
                eb2 + (long long)NE*HN, t1, nullptr, nullptr, TK, HN, EHD, EHD, EHD, HN,
                (long long)TK*EHD, Z0, (long long)HN*EHD, Z0, Z0, Z0, (long long)HN, 1,
                1.f, tok, cnt);
            // final activation: x + fp16 copy for LM head (xh/xl no longer needed)
            copyhalf_k<<<(TK*HN/4)/256, 256>>>(x, xf, t1, (long long)TK*HN/4);
        }
    }

    // lm head: pure fp16 1-term, M-inner rasterization
    tc_k<0,false,false,false,true,true,1,false><<<dim3(TK/BM, VS/BN, 1), 256, SMEMB>>>(
        (const __nv_bfloat16*)xf, (const __nv_bfloat16*)xf,
        (const __nv_bfloat16*)lmh, (const __nv_bfloat16*)lml,
        lmb, out, nullptr, nullptr,
        TK, VS, HN, HN, HN, VS,
        Z0,Z0,Z0,Z0,Z0,Z0,Z0, 0, 1.f, nullptr, nullptr);
}